// round 1
// baseline (speedup 1.0000x reference)
#include <cuda_runtime.h>
#include <math.h>

#define S_LEN 2048
#define HID   4096
#define NH    32
#define DQK   192
#define DV    128

// ---------------- scratch (device globals; no allocations allowed) ----------
__device__ float g_cq [2048*1536];
__device__ float g_qc [2048*4096];
__device__ float g_qr [2048*2048];
__device__ float g_ckv[2048*512];
__device__ float g_kc [2048*4096];
__device__ float g_kr [2048*64];
__device__ float g_v  [2048*4096];
__device__ float g_q  [2048*32*192];
__device__ float g_k  [2048*32*192];
__device__ float g_ao [2048*4096];

// ---------------- generic C[M,N] = A[M,K] @ W[N,K]^T + bias[N] --------------
// M%64==0, N%64==0, K%16==0 guaranteed by problem shapes.
__global__ void gemm_bias_kernel(const float* __restrict__ A,
                                 const float* __restrict__ W,
                                 const float* __restrict__ bias,
                                 float* __restrict__ C,
                                 int M, int N, int K) {
    __shared__ float As[16][64];
    __shared__ float Ws[16][64];
    const int tid  = threadIdx.x;
    const int row0 = blockIdx.y * 64;
    const int col0 = blockIdx.x * 64;
    const int ty = tid >> 4, tx = tid & 15;
    const int lr = tid >> 2;          // 0..63
    const int lk = (tid & 3) * 4;     // 0,4,8,12

    float acc[4][4];
#pragma unroll
    for (int i = 0; i < 4; i++)
#pragma unroll
        for (int j = 0; j < 4; j++) acc[i][j] = 0.f;

    for (int kk = 0; kk < K; kk += 16) {
        float4 av = *(const float4*)&A[(size_t)(row0 + lr) * K + kk + lk];
        float4 wv = *(const float4*)&W[(size_t)(col0 + lr) * K + kk + lk];
        As[lk + 0][lr] = av.x; As[lk + 1][lr] = av.y;
        As[lk + 2][lr] = av.z; As[lk + 3][lr] = av.w;
        Ws[lk + 0][lr] = wv.x; Ws[lk + 1][lr] = wv.y;
        Ws[lk + 2][lr] = wv.z; Ws[lk + 3][lr] = wv.w;
        __syncthreads();
#pragma unroll
        for (int k = 0; k < 16; k++) {
            float4 a = *(const float4*)&As[k][ty * 4];
            float4 b = *(const float4*)&Ws[k][tx * 4];
            float ar[4] = {a.x, a.y, a.z, a.w};
            float br[4] = {b.x, b.y, b.z, b.w};
#pragma unroll
            for (int i = 0; i < 4; i++)
#pragma unroll
                for (int j = 0; j < 4; j++) acc[i][j] += ar[i] * br[j];
        }
        __syncthreads();
    }
#pragma unroll
    for (int i = 0; i < 4; i++) {
        const int r = row0 + ty * 4 + i;
#pragma unroll
        for (int j = 0; j < 4; j++) {
            const int c = col0 + tx * 4 + j;
            C[(size_t)r * N + c] = acc[i][j] + bias[c];
        }
    }
}

// ---------------- rotate-half RoPE, in place, x: [S, D] ---------------------
__global__ void rope_kernel(float* __restrict__ x, int S, int D) {
    const int half = D / 2;
    const int idx = blockIdx.x * blockDim.x + threadIdx.x;
    if (idx >= S * half) return;
    const int s = idx / half, j = idx % half;
    // match jnp f32 formula closely via double intermediates
    double inv = exp(-((double)(2 * j) / (double)D) * log(10000.0));
    double ang = (double)s * inv;
    float c = (float)cos(ang), sn = (float)sin(ang);
    float x1 = x[(size_t)s * D + j];
    float x2 = x[(size_t)s * D + half + j];
    x[(size_t)s * D + j]        = x1 * c - x2 * sn;
    x[(size_t)s * D + half + j] = x2 * c + x1 * sn;
}

// ---------------- concat(content, rope) + RMSnorm over 192 ------------------
// one warp per (s, h) row
__global__ void fuse_q_kernel(const float* __restrict__ qc,
                              const float* __restrict__ qr,
                              float* __restrict__ qn) {
    const int gw   = (blockIdx.x * blockDim.x + threadIdx.x) >> 5;
    const int lane = threadIdx.x & 31;
    const int s = gw >> 5, h = gw & 31;
    float vals[6]; float ss = 0.f;
#pragma unroll
    for (int t = 0; t < 6; t++) {
        int d = lane + 32 * t;
        float x = (d < 128) ? qc[(size_t)s * HID + h * 128 + d]
                            : qr[(size_t)s * 2048 + h * 64 + (d - 128)];
        vals[t] = x; ss += x * x;
    }
#pragma unroll
    for (int o = 16; o; o >>= 1) ss += __shfl_xor_sync(0xffffffffu, ss, o);
    float r = rsqrtf(ss * (1.f / 192.f) + 1.1920929e-7f);
#pragma unroll
    for (int t = 0; t < 6; t++)
        qn[((size_t)s * NH + h) * DQK + lane + 32 * t] = vals[t] * r;
}

__global__ void fuse_k_kernel(const float* __restrict__ kc,
                              const float* __restrict__ kr,
                              float* __restrict__ kn) {
    const int gw   = (blockIdx.x * blockDim.x + threadIdx.x) >> 5;
    const int lane = threadIdx.x & 31;
    const int s = gw >> 5, h = gw & 31;
    float vals[6]; float ss = 0.f;
#pragma unroll
    for (int t = 0; t < 6; t++) {
        int d = lane + 32 * t;
        float x = (d < 128) ? kc[(size_t)s * HID + h * 128 + d]
                            : kr[(size_t)s * 64 + (d - 128)];  // broadcast over heads
        vals[t] = x; ss += x * x;
    }
#pragma unroll
    for (int o = 16; o; o >>= 1) ss += __shfl_xor_sync(0xffffffffu, ss, o);
    float r = rsqrtf(ss * (1.f / 192.f) + 1.1920929e-7f);
#pragma unroll
    for (int t = 0; t < 6; t++)
        kn[((size_t)s * NH + h) * DQK + lane + 32 * t] = vals[t] * r;
}

// ---------------- flash attention (fp32), 64 q-rows x 1 head per CTA --------
// q,k: [S, NH, 192]; v: [S, 4096] slice h*128; out: [S, 4096]
__global__ void attn_kernel(const float* __restrict__ q,
                            const float* __restrict__ k,
                            const float* __restrict__ v,
                            const float* __restrict__ mask,
                            float* __restrict__ out) {
    extern __shared__ float sm[];
    float* Qs = sm;              // [64][193]
    float* Ks = Qs + 64 * 193;   // [64][193]
    float* Vs = Ks + 64 * 193;   // [64][129]
    float* Ps = Vs + 64 * 129;   // [64][65]

    const int h  = blockIdx.y;
    const int q0 = blockIdx.x * 64;
    const int tid = threadIdx.x;
    const int ty = tid >> 4, tx = tid & 15;
    const float scale = 1.0f / sqrtf(192.0f);

    for (int i = tid; i < 64 * 192; i += 256) {
        int r = i / 192, d = i % 192;
        Qs[r * 193 + d] = q[((size_t)(q0 + r) * NH + h) * DQK + d];
    }

    float m_i[4], l_i[4], acc[4][8];
#pragma unroll
    for (int i = 0; i < 4; i++) {
        m_i[i] = -1e30f; l_i[i] = 0.f;
#pragma unroll
        for (int j = 0; j < 8; j++) acc[i][j] = 0.f;
    }
    __syncthreads();

    for (int k0 = 0; k0 < S_LEN; k0 += 64) {
        for (int i = tid; i < 64 * 192; i += 256) {
            int r = i / 192, d = i % 192;
            Ks[r * 193 + d] = k[((size_t)(k0 + r) * NH + h) * DQK + d];
        }
        for (int i = tid; i < 64 * 128; i += 256) {
            int r = i >> 7, d = i & 127;
            Vs[r * 129 + d] = v[(size_t)(k0 + r) * HID + h * DV + d];
        }
        __syncthreads();

        float s[4][4];
#pragma unroll
        for (int i = 0; i < 4; i++)
#pragma unroll
            for (int j = 0; j < 4; j++) s[i][j] = 0.f;

        for (int d = 0; d < 192; d++) {
            float ar[4], br[4];
#pragma unroll
            for (int i = 0; i < 4; i++) ar[i] = Qs[(ty * 4 + i) * 193 + d];
#pragma unroll
            for (int j = 0; j < 4; j++) br[j] = Ks[(tx * 4 + j) * 193 + d];
#pragma unroll
            for (int i = 0; i < 4; i++)
#pragma unroll
                for (int j = 0; j < 4; j++) s[i][j] += ar[i] * br[j];
        }

#pragma unroll
        for (int i = 0; i < 4; i++) {
#pragma unroll
            for (int j = 0; j < 4; j++)
                s[i][j] = s[i][j] * scale +
                          mask[(size_t)(q0 + ty * 4 + i) * S_LEN + k0 + tx * 4 + j];
            float mx = fmaxf(fmaxf(s[i][0], s[i][1]), fmaxf(s[i][2], s[i][3]));
#pragma unroll
            for (int o = 8; o; o >>= 1) mx = fmaxf(mx, __shfl_xor_sync(0xffffffffu, mx, o));
            float mnew = fmaxf(m_i[i], mx);
            float ps = 0.f;
#pragma unroll
            for (int j = 0; j < 4; j++) { s[i][j] = __expf(s[i][j] - mnew); ps += s[i][j]; }
#pragma unroll
            for (int o = 8; o; o >>= 1) ps += __shfl_xor_sync(0xffffffffu, ps, o);
            float alpha = __expf(m_i[i] - mnew);
            l_i[i] = alpha * l_i[i] + ps;
            m_i[i] = mnew;
#pragma unroll
            for (int j = 0; j < 8; j++) acc[i][j] *= alpha;
#pragma unroll
            for (int j = 0; j < 4; j++) Ps[(ty * 4 + i) * 65 + tx * 4 + j] = s[i][j];
        }
        __syncthreads();

        for (int c = 0; c < 64; c++) {
            float pv[4];
#pragma unroll
            for (int i = 0; i < 4; i++) pv[i] = Ps[(ty * 4 + i) * 65 + c];
#pragma unroll
            for (int j = 0; j < 8; j++) {
                float vv = Vs[c * 129 + tx * 8 + j];
#pragma unroll
                for (int i = 0; i < 4; i++) acc[i][j] += pv[i] * vv;
            }
        }
        __syncthreads();
    }

#pragma unroll
    for (int i = 0; i < 4; i++) {
        float inv = 1.f / l_i[i];
#pragma unroll
        for (int j = 0; j < 8; j++)
            out[(size_t)(q0 + ty * 4 + i) * HID + h * DV + tx * 8 + j] = acc[i][j] * inv;
    }
}

// ---------------- launcher ---------------------------------------------------
extern "C" void kernel_launch(void* const* d_in, const int* in_sizes, int n_in,
                              void* d_out, int out_size) {
    const float* hidden  = (const float*)d_in[0];
    const float* mask    = (const float*)d_in[1];
    const float* Wq_lr   = (const float*)d_in[2];
    const float* bq_lr   = (const float*)d_in[3];
    const float* Wq_rope = (const float*)d_in[4];
    const float* bq_rope = (const float*)d_in[5];
    const float* Wq_c    = (const float*)d_in[6];
    const float* bq_c    = (const float*)d_in[7];
    const float* Wkv     = (const float*)d_in[8];
    const float* bkv     = (const float*)d_in[9];
    const float* Wk_rope = (const float*)d_in[10];
    const float* bk_rope = (const float*)d_in[11];
    const float* Wk_c    = (const float*)d_in[12];
    const float* bk_c    = (const float*)d_in[13];
    const float* Wv      = (const float*)d_in[14];
    const float* bv      = (const float*)d_in[15];
    const float* Wo      = (const float*)d_in[16];
    const float* bo      = (const float*)d_in[17];
    float* out = (float*)d_out;

    float *cq, *qc, *qr, *ckv, *kc, *kr, *vv, *qn, *kn, *ao;
    cudaGetSymbolAddress((void**)&cq,  g_cq);
    cudaGetSymbolAddress((void**)&qc,  g_qc);
    cudaGetSymbolAddress((void**)&qr,  g_qr);
    cudaGetSymbolAddress((void**)&ckv, g_ckv);
    cudaGetSymbolAddress((void**)&kc,  g_kc);
    cudaGetSymbolAddress((void**)&kr,  g_kr);
    cudaGetSymbolAddress((void**)&vv,  g_v);
    cudaGetSymbolAddress((void**)&qn,  g_q);
    cudaGetSymbolAddress((void**)&kn,  g_k);
    cudaGetSymbolAddress((void**)&ao,  g_ao);

    const int M = 2048;
    dim3 thr(256);

    // c_q = hidden @ Wq_lr^T
    gemm_bias_kernel<<<dim3(1536 / 64, M / 64), thr>>>(hidden, Wq_lr, bq_lr, cq, M, 1536, 4096);
    // q_content = c_q @ Wq_c^T
    gemm_bias_kernel<<<dim3(4096 / 64, M / 64), thr>>>(cq, Wq_c, bq_c, qc, M, 4096, 1536);
    // q_rope(pre-rope) = c_q @ Wq_rope^T
    gemm_bias_kernel<<<dim3(2048 / 64, M / 64), thr>>>(cq, Wq_rope, bq_rope, qr, M, 2048, 1536);
    // c_kv = hidden @ Wkv^T
    gemm_bias_kernel<<<dim3(512 / 64, M / 64), thr>>>(hidden, Wkv, bkv, ckv, M, 512, 4096);
    // k_content = c_kv @ Wk_c^T
    gemm_bias_kernel<<<dim3(4096 / 64, M / 64), thr>>>(ckv, Wk_c, bk_c, kc, M, 4096, 512);
    // k_rope(pre-rope) = hidden @ Wk_rope^T
    gemm_bias_kernel<<<dim3(64 / 64, M / 64), thr>>>(hidden, Wk_rope, bk_rope, kr, M, 64, 4096);
    // v = c_kv @ Wv^T
    gemm_bias_kernel<<<dim3(4096 / 64, M / 64), thr>>>(ckv, Wv, bv, vv, M, 4096, 512);

    // RoPE (q over full D=2048 before head split; k over D=64)
    rope_kernel<<<(2048 * 1024 + 255) / 256, 256>>>(qr, 2048, 2048);
    rope_kernel<<<(2048 * 32 + 255) / 256, 256>>>(kr, 2048, 64);

    // concat + RMSnorm
    fuse_q_kernel<<<8192, 256>>>(qc, qr, qn);
    fuse_k_kernel<<<8192, 256>>>(kc, kr, kn);

    // attention
    size_t smem = (size_t)(64 * 193 * 2 + 64 * 129 + 64 * 65) * sizeof(float);
    cudaFuncSetAttribute(attn_kernel, cudaFuncAttributeMaxDynamicSharedMemorySize, (int)smem);
    attn_kernel<<<dim3(S_LEN / 64, NH), 256, smem>>>(qn, kn, vv, mask, ao);

    // output projection
    gemm_bias_kernel<<<dim3(4096 / 64, M / 64), thr>>>(ao, Wo, bo, out, M, 4096, 4096);
}

// round 3
// speedup vs baseline: 1.3281x; 1.3281x over previous
#include <cuda_runtime.h>
#include <cuda_bf16.h>
#include <math.h>
#include <stdint.h>

#define S_LEN 2048
#define HID   4096
#define NH    32
#define DQK   192
#define DV    128

// ---------------------------------------------------------------------------
// scratch (device globals; no allocations allowed)
// ---------------------------------------------------------------------------
__device__ float g_cq [2048*1536];
__device__ float g_qc [2048*4096];
__device__ float g_qr [2048*2048];
__device__ float g_ckv[2048*512];
__device__ float g_kc [2048*4096];
__device__ float g_kr [2048*64];
__device__ float g_v  [2048*4096];
__device__ float g_q  [2048*32*192];
__device__ float g_k  [2048*32*192];
__device__ float g_ao [2048*4096];

// bf16 hi/lo splits
__device__ __align__(16) __nv_bfloat16 g_h_hi [2048*4096], g_h_lo [2048*4096];
__device__ __align__(16) __nv_bfloat16 g_cq_hi[2048*1536], g_cq_lo[2048*1536];
__device__ __align__(16) __nv_bfloat16 g_ckv_hi[2048*512], g_ckv_lo[2048*512];
__device__ __align__(16) __nv_bfloat16 g_ao_hi[2048*4096], g_ao_lo[2048*4096];
__device__ __align__(16) __nv_bfloat16 g_Wqlr_hi[1536*4096], g_Wqlr_lo[1536*4096];
__device__ __align__(16) __nv_bfloat16 g_Wqc_hi [4096*1536], g_Wqc_lo [4096*1536];
__device__ __align__(16) __nv_bfloat16 g_Wqr_hi [2048*1536], g_Wqr_lo [2048*1536];
__device__ __align__(16) __nv_bfloat16 g_Wkv_hi [512*4096],  g_Wkv_lo [512*4096];
__device__ __align__(16) __nv_bfloat16 g_Wkc_hi [4096*512],  g_Wkc_lo [4096*512];
__device__ __align__(16) __nv_bfloat16 g_Wv_hi  [4096*512],  g_Wv_lo  [4096*512];
__device__ __align__(16) __nv_bfloat16 g_Wo_hi  [4096*4096], g_Wo_lo  [4096*4096];

// ---------------------------------------------------------------------------
// small PTX helpers (all non-arch-'a' instructions)
// ---------------------------------------------------------------------------
__device__ __forceinline__ uint32_t smem_u32(const void* p) {
    uint32_t a;
    asm("{ .reg .u64 t; cvta.to.shared.u64 t, %1; cvt.u32.u64 %0, t; }" : "=r"(a) : "l"(p));
    return a;
}
#define CP_ASYNC16(dst_u32, src_ptr) \
    asm volatile("cp.async.cg.shared.global [%0], [%1], 16;" \
                 :: "r"(dst_u32), "l"(__cvta_generic_to_global(src_ptr)) : "memory")
#define CP_COMMIT() asm volatile("cp.async.commit_group;" ::: "memory")
#define CP_WAIT(n)  asm volatile("cp.async.wait_group %0;" :: "n"(n) : "memory")

__device__ __forceinline__ void ldmx4(uint32_t& r0, uint32_t& r1, uint32_t& r2, uint32_t& r3,
                                      uint32_t addr) {
    asm volatile("ldmatrix.sync.aligned.m8n8.x4.shared.b16 {%0,%1,%2,%3}, [%4];"
                 : "=r"(r0), "=r"(r1), "=r"(r2), "=r"(r3) : "r"(addr));
}
__device__ __forceinline__ void mma_bf16(float* d, const uint32_t* a, const uint32_t* b) {
    asm volatile("mma.sync.aligned.m16n8k16.row.col.f32.bf16.bf16.f32 "
                 "{%0,%1,%2,%3}, {%4,%5,%6,%7}, {%8,%9}, {%0,%1,%2,%3};"
                 : "+f"(d[0]), "+f"(d[1]), "+f"(d[2]), "+f"(d[3])
                 : "r"(a[0]), "r"(a[1]), "r"(a[2]), "r"(a[3]), "r"(b[0]), "r"(b[1]));
}

// ---------------------------------------------------------------------------
// fp32 -> bf16 (hi, lo) split
// ---------------------------------------------------------------------------
__global__ void split_bf16_kernel(const float* __restrict__ x,
                                  __nv_bfloat16* __restrict__ hi,
                                  __nv_bfloat16* __restrict__ lo, int n4) {
    int i = blockIdx.x * blockDim.x + threadIdx.x;
    if (i >= n4) return;
    float4 v = ((const float4*)x)[i];
    __nv_bfloat16 h0 = __float2bfloat16(v.x), h1 = __float2bfloat16(v.y);
    __nv_bfloat16 h2 = __float2bfloat16(v.z), h3 = __float2bfloat16(v.w);
    __nv_bfloat16 l0 = __float2bfloat16(v.x - __bfloat162float(h0));
    __nv_bfloat16 l1 = __float2bfloat16(v.y - __bfloat162float(h1));
    __nv_bfloat16 l2 = __float2bfloat16(v.z - __bfloat162float(h2));
    __nv_bfloat16 l3 = __float2bfloat16(v.w - __bfloat162float(h3));
    ((__nv_bfloat162*)hi)[i*2 + 0] = __nv_bfloat162(h0, h1);
    ((__nv_bfloat162*)hi)[i*2 + 1] = __nv_bfloat162(h2, h3);
    ((__nv_bfloat162*)lo)[i*2 + 0] = __nv_bfloat162(l0, l1);
    ((__nv_bfloat162*)lo)[i*2 + 1] = __nv_bfloat162(l2, l3);
}

// ---------------------------------------------------------------------------
// warp-MMA bf16 GEMM with fp32 emulation (3 passes hi*hi + hi*lo + lo*hi)
// C[M,N] = A[M,K] @ W[N,K]^T + bias;  CTA tile 128x128, BK=32, 8 warps (4x2).
// M%128==0, N%128==0, K%32==0.
// ---------------------------------------------------------------------------
#define BM 128
#define BN 128
#define BK 32
#define ROWB 80   // bytes per smem row (40 halfs): conflict-free ldmatrix

__global__ void __launch_bounds__(256)
mma_gemm_kernel(const __nv_bfloat16* __restrict__ Ahi, const __nv_bfloat16* __restrict__ Alo,
                const __nv_bfloat16* __restrict__ Whi, const __nv_bfloat16* __restrict__ Wlo,
                const float* __restrict__ bias, float* __restrict__ C,
                int M, int N, int K) {
    __shared__ __align__(16) char smbuf[2][2 * BM * ROWB];   // [buf][A|W]

    const int tid = threadIdx.x, wid = tid >> 5, lane = tid & 31;
    const int warp_m = wid >> 1;          // 0..3
    const int warp_n = wid & 1;           // 0..1
    const int row0 = blockIdx.y * BM, col0 = blockIdx.x * BN;

    const uint32_t sA[2] = { smem_u32(&smbuf[0][0]), smem_u32(&smbuf[1][0]) };
    const uint32_t sW[2] = { sA[0] + BM * ROWB, sA[1] + BM * ROWB };

    // ldmatrix per-thread row/col offsets
    const int a_row = (lane & 7) + ((lane >> 3) & 1) * 8;   // m within 16
    const int a_kof = (lane >> 4) * 8;                      // k within 16
    const int b_row = (lane & 7) + (lane >> 4) * 8;         // n within 16
    const int b_kof = ((lane >> 3) & 1) * 8;                // k within 16

    const __nv_bfloat16* APs[3] = { Ahi, Ahi, Alo };
    const __nv_bfloat16* WPs[3] = { Whi, Wlo, Whi };

    const int kc = K >> 5;        // chunks per pass
    const int nc = kc * 3;

    float acc[2][8][4];
#pragma unroll
    for (int mt = 0; mt < 2; mt++)
#pragma unroll
        for (int nt = 0; nt < 8; nt++)
#pragma unroll
            for (int e = 0; e < 4; e++) acc[mt][nt][e] = 0.f;

    // --- async tile loader: A tile BM x 32 halfs (64B), W tile BN x 64B ---
    auto load_chunk = [&](int c, int buf) {
        const int p  = c / kc;
        const int kk = (c - p * kc) << 5;
        const __nv_bfloat16* Ap = APs[p];
        const __nv_bfloat16* Wp = WPs[p];
        // 512 chunks of 16B each for A, same for W; 256 threads -> 2+2 each
#pragma unroll
        for (int i = 0; i < 2; i++) {
            int idx = tid + i * 256;
            int r = idx >> 2, cb = idx & 3;
            CP_ASYNC16(sA[buf] + r * ROWB + cb * 16,
                       Ap + (size_t)(row0 + r) * K + kk + cb * 8);
        }
#pragma unroll
        for (int i = 0; i < 2; i++) {
            int idx = tid + i * 256;
            int r = idx >> 2, cb = idx & 3;
            CP_ASYNC16(sW[buf] + r * ROWB + cb * 16,
                       Wp + (size_t)(col0 + r) * K + kk + cb * 8);
        }
        CP_COMMIT();
    };

    load_chunk(0, 0);

    for (int c = 0; c < nc; c++) {
        const int buf = c & 1;
        if (c + 1 < nc) {
            load_chunk(c + 1, buf ^ 1);
            CP_WAIT(1);
        } else {
            CP_WAIT(0);
        }
        __syncthreads();

        // compute on buf: two k16 steps
#pragma unroll
        for (int ks = 0; ks < 2; ks++) {
            const int kb = ks * 16;
            uint32_t af[2][4], bf[4][4];
#pragma unroll
            for (int mt = 0; mt < 2; mt++) {
                uint32_t addr = sA[buf] + (warp_m * 32 + mt * 16 + a_row) * ROWB
                              + (kb + a_kof) * 2;
                ldmx4(af[mt][0], af[mt][1], af[mt][2], af[mt][3], addr);
            }
#pragma unroll
            for (int np = 0; np < 4; np++) {
                uint32_t addr = sW[buf] + (warp_n * 64 + np * 16 + b_row) * ROWB
                              + (kb + b_kof) * 2;
                ldmx4(bf[np][0], bf[np][1], bf[np][2], bf[np][3], addr);
            }
#pragma unroll
            for (int mt = 0; mt < 2; mt++)
#pragma unroll
                for (int nt = 0; nt < 8; nt++) {
                    uint32_t b2[2] = { bf[nt >> 1][(nt & 1) * 2],
                                       bf[nt >> 1][(nt & 1) * 2 + 1] };
                    mma_bf16(acc[mt][nt], af[mt], b2);
                }
        }
        __syncthreads();
    }

    // epilogue: acc -> C (+bias)
    const int rbase = row0 + warp_m * 32 + (lane >> 2);
    const int cbase = col0 + warp_n * 64 + (lane & 3) * 2;
#pragma unroll
    for (int mt = 0; mt < 2; mt++) {
#pragma unroll
        for (int nt = 0; nt < 8; nt++) {
            const int cc = cbase + nt * 8;
            const float b0 = bias[cc], b1 = bias[cc + 1];
            const int r0 = rbase + mt * 16;
            *(float2*)&C[(size_t)r0 * N + cc] =
                make_float2(acc[mt][nt][0] + b0, acc[mt][nt][1] + b1);
            *(float2*)&C[(size_t)(r0 + 8) * N + cc] =
                make_float2(acc[mt][nt][2] + b0, acc[mt][nt][3] + b1);
        }
    }
}

// ---------------------------------------------------------------------------
// SIMT GEMM (tiny k_rope: N=64)
// ---------------------------------------------------------------------------
__global__ void gemm_bias_kernel(const float* __restrict__ A,
                                 const float* __restrict__ W,
                                 const float* __restrict__ bias,
                                 float* __restrict__ C,
                                 int M, int N, int K) {
    __shared__ float As[16][64];
    __shared__ float Ws[16][64];
    const int tid  = threadIdx.x;
    const int row0 = blockIdx.y * 64;
    const int col0 = blockIdx.x * 64;
    const int ty = tid >> 4, tx = tid & 15;
    const int lr = tid >> 2;
    const int lk = (tid & 3) * 4;

    float acc[4][4];
#pragma unroll
    for (int i = 0; i < 4; i++)
#pragma unroll
        for (int j = 0; j < 4; j++) acc[i][j] = 0.f;

    for (int kk = 0; kk < K; kk += 16) {
        float4 av = *(const float4*)&A[(size_t)(row0 + lr) * K + kk + lk];
        float4 wv = *(const float4*)&W[(size_t)(col0 + lr) * K + kk + lk];
        As[lk + 0][lr] = av.x; As[lk + 1][lr] = av.y;
        As[lk + 2][lr] = av.z; As[lk + 3][lr] = av.w;
        Ws[lk + 0][lr] = wv.x; Ws[lk + 1][lr] = wv.y;
        Ws[lk + 2][lr] = wv.z; Ws[lk + 3][lr] = wv.w;
        __syncthreads();
#pragma unroll
        for (int k = 0; k < 16; k++) {
            float4 a = *(const float4*)&As[k][ty * 4];
            float4 b = *(const float4*)&Ws[k][tx * 4];
            float ar[4] = {a.x, a.y, a.z, a.w};
            float br[4] = {b.x, b.y, b.z, b.w};
#pragma unroll
            for (int i = 0; i < 4; i++)
#pragma unroll
                for (int j = 0; j < 4; j++) acc[i][j] += ar[i] * br[j];
        }
        __syncthreads();
    }
#pragma unroll
    for (int i = 0; i < 4; i++) {
        const int r = row0 + ty * 4 + i;
#pragma unroll
        for (int j = 0; j < 4; j++) {
            const int c = col0 + tx * 4 + j;
            C[(size_t)r * N + c] = acc[i][j] + bias[c];
        }
    }
}

// ---------------- rotate-half RoPE, in place, x: [S, D] ---------------------
__global__ void rope_kernel(float* __restrict__ x, int S, int D) {
    const int half = D / 2;
    const int idx = blockIdx.x * blockDim.x + threadIdx.x;
    if (idx >= S * half) return;
    const int s = idx / half, j = idx % half;
    double inv = exp(-((double)(2 * j) / (double)D) * log(10000.0));
    double ang = (double)s * inv;
    float c = (float)cos(ang), sn = (float)sin(ang);
    float x1 = x[(size_t)s * D + j];
    float x2 = x[(size_t)s * D + half + j];
    x[(size_t)s * D + j]        = x1 * c - x2 * sn;
    x[(size_t)s * D + half + j] = x2 * c + x1 * sn;
}

// ---------------- concat(content, rope) + RMSnorm over 192 ------------------
__global__ void fuse_q_kernel(const float* __restrict__ qc,
                              const float* __restrict__ qr,
                              float* __restrict__ qn) {
    const int gw   = (blockIdx.x * blockDim.x + threadIdx.x) >> 5;
    const int lane = threadIdx.x & 31;
    const int s = gw >> 5, h = gw & 31;
    float vals[6]; float ss = 0.f;
#pragma unroll
    for (int t = 0; t < 6; t++) {
        int d = lane + 32 * t;
        float x = (d < 128) ? qc[(size_t)s * HID + h * 128 + d]
                            : qr[(size_t)s * 2048 + h * 64 + (d - 128)];
        vals[t] = x; ss += x * x;
    }
#pragma unroll
    for (int o = 16; o; o >>= 1) ss += __shfl_xor_sync(0xffffffffu, ss, o);
    float r = rsqrtf(ss * (1.f / 192.f) + 1.1920929e-7f);
#pragma unroll
    for (int t = 0; t < 6; t++)
        qn[((size_t)s * NH + h) * DQK + lane + 32 * t] = vals[t] * r;
}

__global__ void fuse_k_kernel(const float* __restrict__ kc,
                              const float* __restrict__ kr,
                              float* __restrict__ kn) {
    const int gw   = (blockIdx.x * blockDim.x + threadIdx.x) >> 5;
    const int lane = threadIdx.x & 31;
    const int s = gw >> 5, h = gw & 31;
    float vals[6]; float ss = 0.f;
#pragma unroll
    for (int t = 0; t < 6; t++) {
        int d = lane + 32 * t;
        float x = (d < 128) ? kc[(size_t)s * HID + h * 128 + d]
                            : kr[(size_t)s * 64 + (d - 128)];
        vals[t] = x; ss += x * x;
    }
#pragma unroll
    for (int o = 16; o; o >>= 1) ss += __shfl_xor_sync(0xffffffffu, ss, o);
    float r = rsqrtf(ss * (1.f / 192.f) + 1.1920929e-7f);
#pragma unroll
    for (int t = 0; t < 6; t++)
        kn[((size_t)s * NH + h) * DQK + lane + 32 * t] = vals[t] * r;
}

// ---------------- flash attention (fp32), 64 q-rows x 1 head per CTA --------
__global__ void attn_kernel(const float* __restrict__ q,
                            const float* __restrict__ k,
                            const float* __restrict__ v,
                            const float* __restrict__ mask,
                            float* __restrict__ out) {
    extern __shared__ float sm[];
    float* Qs = sm;
    float* Ks = Qs + 64 * 193;
    float* Vs = Ks + 64 * 193;
    float* Ps = Vs + 64 * 129;

    const int h  = blockIdx.y;
    const int q0 = blockIdx.x * 64;
    const int tid = threadIdx.x;
    const int ty = tid >> 4, tx = tid & 15;
    const float scale = 1.0f / sqrtf(192.0f);

    for (int i = tid; i < 64 * 192; i += 256) {
        int r = i / 192, d = i % 192;
        Qs[r * 193 + d] = q[((size_t)(q0 + r) * NH + h) * DQK + d];
    }

    float m_i[4], l_i[4], acc[4][8];
#pragma unroll
    for (int i = 0; i < 4; i++) {
        m_i[i] = -1e30f; l_i[i] = 0.f;
#pragma unroll
        for (int j = 0; j < 8; j++) acc[i][j] = 0.f;
    }
    __syncthreads();

    for (int k0 = 0; k0 < S_LEN; k0 += 64) {
        for (int i = tid; i < 64 * 192; i += 256) {
            int r = i / 192, d = i % 192;
            Ks[r * 193 + d] = k[((size_t)(k0 + r) * NH + h) * DQK + d];
        }
        for (int i = tid; i < 64 * 128; i += 256) {
            int r = i >> 7, d = i & 127;
            Vs[r * 129 + d] = v[(size_t)(k0 + r) * HID + h * DV + d];
        }
        __syncthreads();

        float s[4][4];
#pragma unroll
        for (int i = 0; i < 4; i++)
#pragma unroll
            for (int j = 0; j < 4; j++) s[i][j] = 0.f;

        for (int d = 0; d < 192; d++) {
            float ar[4], br[4];
#pragma unroll
            for (int i = 0; i < 4; i++) ar[i] = Qs[(ty * 4 + i) * 193 + d];
#pragma unroll
            for (int j = 0; j < 4; j++) br[j] = Ks[(tx * 4 + j) * 193 + d];
#pragma unroll
            for (int i = 0; i < 4; i++)
#pragma unroll
                for (int j = 0; j < 4; j++) s[i][j] += ar[i] * br[j];
        }

#pragma unroll
        for (int i = 0; i < 4; i++) {
#pragma unroll
            for (int j = 0; j < 4; j++)
                s[i][j] = s[i][j] * scale +
                          mask[(size_t)(q0 + ty * 4 + i) * S_LEN + k0 + tx * 4 + j];
            float mx = fmaxf(fmaxf(s[i][0], s[i][1]), fmaxf(s[i][2], s[i][3]));
#pragma unroll
            for (int o = 8; o; o >>= 1) mx = fmaxf(mx, __shfl_xor_sync(0xffffffffu, mx, o));
            float mnew = fmaxf(m_i[i], mx);
            float ps = 0.f;
#pragma unroll
            for (int j = 0; j < 4; j++) { s[i][j] = __expf(s[i][j] - mnew); ps += s[i][j]; }
#pragma unroll
            for (int o = 8; o; o >>= 1) ps += __shfl_xor_sync(0xffffffffu, ps, o);
            float alpha = __expf(m_i[i] - mnew);
            l_i[i] = alpha * l_i[i] + ps;
            m_i[i] = mnew;
#pragma unroll
            for (int j = 0; j < 8; j++) acc[i][j] *= alpha;
#pragma unroll
            for (int j = 0; j < 4; j++) Ps[(ty * 4 + i) * 65 + tx * 4 + j] = s[i][j];
        }
        __syncthreads();

        for (int c = 0; c < 64; c++) {
            float pv[4];
#pragma unroll
            for (int i = 0; i < 4; i++) pv[i] = Ps[(ty * 4 + i) * 65 + c];
#pragma unroll
            for (int j = 0; j < 8; j++) {
                float vv = Vs[c * 129 + tx * 8 + j];
#pragma unroll
                for (int i = 0; i < 4; i++) acc[i][j] += pv[i] * vv;
            }
        }
        __syncthreads();
    }

#pragma unroll
    for (int i = 0; i < 4; i++) {
        float inv = 1.f / l_i[i];
#pragma unroll
        for (int j = 0; j < 8; j++)
            out[(size_t)(q0 + ty * 4 + i) * HID + h * DV + tx * 8 + j] = acc[i][j] * inv;
    }
}

// ---------------------------------------------------------------------------
// launcher
// ---------------------------------------------------------------------------
static void split(const float* x, __nv_bfloat16* hi, __nv_bfloat16* lo, int n) {
    int n4 = n / 4;
    split_bf16_kernel<<<(n4 + 255) / 256, 256>>>(x, hi, lo, n4);
}

extern "C" void kernel_launch(void* const* d_in, const int* in_sizes, int n_in,
                              void* d_out, int out_size) {
    const float* hidden  = (const float*)d_in[0];
    const float* mask    = (const float*)d_in[1];
    const float* Wq_lr   = (const float*)d_in[2];
    const float* bq_lr   = (const float*)d_in[3];
    const float* Wq_rope = (const float*)d_in[4];
    const float* bq_rope = (const float*)d_in[5];
    const float* Wq_c    = (const float*)d_in[6];
    const float* bq_c    = (const float*)d_in[7];
    const float* Wkv     = (const float*)d_in[8];
    const float* bkv     = (const float*)d_in[9];
    const float* Wk_rope = (const float*)d_in[10];
    const float* bk_rope = (const float*)d_in[11];
    const float* Wk_c    = (const float*)d_in[12];
    const float* bk_c    = (const float*)d_in[13];
    const float* Wv      = (const float*)d_in[14];
    const float* bv      = (const float*)d_in[15];
    const float* Wo      = (const float*)d_in[16];
    const float* bo      = (const float*)d_in[17];
    float* out = (float*)d_out;

    float *cq, *qc, *qr, *ckv, *kc, *kr, *vv, *qn, *kn, *ao;
    cudaGetSymbolAddress((void**)&cq,  g_cq);
    cudaGetSymbolAddress((void**)&qc,  g_qc);
    cudaGetSymbolAddress((void**)&qr,  g_qr);
    cudaGetSymbolAddress((void**)&ckv, g_ckv);
    cudaGetSymbolAddress((void**)&kc,  g_kc);
    cudaGetSymbolAddress((void**)&kr,  g_kr);
    cudaGetSymbolAddress((void**)&vv,  g_v);
    cudaGetSymbolAddress((void**)&qn,  g_q);
    cudaGetSymbolAddress((void**)&kn,  g_k);
    cudaGetSymbolAddress((void**)&ao,  g_ao);

    __nv_bfloat16 *h_hi, *h_lo, *cq_hi, *cq_lo, *ckv_hi, *ckv_lo, *ao_hi, *ao_lo;
    __nv_bfloat16 *Wqlr_hi, *Wqlr_lo, *Wqc_hi, *Wqc_lo, *Wqr_hi, *Wqr_lo;
    __nv_bfloat16 *Wkv_hi, *Wkv_lo, *Wkc_hi, *Wkc_lo, *Wv_hi, *Wv_lo, *Wo_hi, *Wo_lo;
    cudaGetSymbolAddress((void**)&h_hi,   g_h_hi);   cudaGetSymbolAddress((void**)&h_lo,   g_h_lo);
    cudaGetSymbolAddress((void**)&cq_hi,  g_cq_hi);  cudaGetSymbolAddress((void**)&cq_lo,  g_cq_lo);
    cudaGetSymbolAddress((void**)&ckv_hi, g_ckv_hi); cudaGetSymbolAddress((void**)&ckv_lo, g_ckv_lo);
    cudaGetSymbolAddress((void**)&ao_hi,  g_ao_hi);  cudaGetSymbolAddress((void**)&ao_lo,  g_ao_lo);
    cudaGetSymbolAddress((void**)&Wqlr_hi, g_Wqlr_hi); cudaGetSymbolAddress((void**)&Wqlr_lo, g_Wqlr_lo);
    cudaGetSymbolAddress((void**)&Wqc_hi,  g_Wqc_hi);  cudaGetSymbolAddress((void**)&Wqc_lo,  g_Wqc_lo);
    cudaGetSymbolAddress((void**)&Wqr_hi,  g_Wqr_hi);  cudaGetSymbolAddress((void**)&Wqr_lo,  g_Wqr_lo);
    cudaGetSymbolAddress((void**)&Wkv_hi,  g_Wkv_hi);  cudaGetSymbolAddress((void**)&Wkv_lo,  g_Wkv_lo);
    cudaGetSymbolAddress((void**)&Wkc_hi,  g_Wkc_hi);  cudaGetSymbolAddress((void**)&Wkc_lo,  g_Wkc_lo);
    cudaGetSymbolAddress((void**)&Wv_hi,   g_Wv_hi);   cudaGetSymbolAddress((void**)&Wv_lo,   g_Wv_lo);
    cudaGetSymbolAddress((void**)&Wo_hi,   g_Wo_hi);   cudaGetSymbolAddress((void**)&Wo_lo,   g_Wo_lo);

    const int M = 2048;

    // splits of inputs/weights
    split(hidden,  h_hi,    h_lo,    2048 * 4096);
    split(Wq_lr,   Wqlr_hi, Wqlr_lo, 1536 * 4096);
    split(Wq_c,    Wqc_hi,  Wqc_lo,  4096 * 1536);
    split(Wq_rope, Wqr_hi,  Wqr_lo,  2048 * 1536);
    split(Wkv,     Wkv_hi,  Wkv_lo,  512 * 4096);
    split(Wk_c,    Wkc_hi,  Wkc_lo,  4096 * 512);
    split(Wv,      Wv_hi,   Wv_lo,   4096 * 512);
    split(Wo,      Wo_hi,   Wo_lo,   4096 * 4096);

    // c_q = hidden @ Wq_lr^T   [2048,1536] K=4096
    mma_gemm_kernel<<<dim3(1536 / BN, M / BM), 256>>>(
        h_hi, h_lo, Wqlr_hi, Wqlr_lo, bq_lr, cq, M, 1536, 4096);
    split(cq, cq_hi, cq_lo, 2048 * 1536);

    // q_content = c_q @ Wq_c^T  [2048,4096] K=1536
    mma_gemm_kernel<<<dim3(4096 / BN, M / BM), 256>>>(
        cq_hi, cq_lo, Wqc_hi, Wqc_lo, bq_c, qc, M, 4096, 1536);
    // q_rope = c_q @ Wq_rope^T  [2048,2048] K=1536
    mma_gemm_kernel<<<dim3(2048 / BN, M / BM), 256>>>(
        cq_hi, cq_lo, Wqr_hi, Wqr_lo, bq_rope, qr, M, 2048, 1536);

    // c_kv = hidden @ Wkv^T  [2048,512] K=4096
    mma_gemm_kernel<<<dim3(512 / BN, M / BM), 256>>>(
        h_hi, h_lo, Wkv_hi, Wkv_lo, bkv, ckv, M, 512, 4096);
    split(ckv, ckv_hi, ckv_lo, 2048 * 512);

    // k_content = c_kv @ Wk_c^T  [2048,4096] K=512
    mma_gemm_kernel<<<dim3(4096 / BN, M / BM), 256>>>(
        ckv_hi, ckv_lo, Wkc_hi, Wkc_lo, bk_c, kc, M, 4096, 512);
    // v = c_kv @ Wv^T  [2048,4096] K=512
    mma_gemm_kernel<<<dim3(4096 / BN, M / BM), 256>>>(
        ckv_hi, ckv_lo, Wv_hi, Wv_lo, bv, vv, M, 4096, 512);

    // k_rope = hidden @ Wk_rope^T  [2048,64] K=4096 (tiny -> SIMT)
    gemm_bias_kernel<<<dim3(1, M / 64), 256>>>(hidden, Wk_rope, bk_rope, kr, M, 64, 4096);

    // RoPE
    rope_kernel<<<(2048 * 1024 + 255) / 256, 256>>>(qr, 2048, 2048);
    rope_kernel<<<(2048 * 32 + 255) / 256, 256>>>(kr, 2048, 64);

    // concat + RMSnorm
    fuse_q_kernel<<<8192, 256>>>(qc, qr, qn);
    fuse_k_kernel<<<8192, 256>>>(kc, kr, kn);

    // attention
    size_t smem = (size_t)(64 * 193 * 2 + 64 * 129 + 64 * 65) * sizeof(float);
    cudaFuncSetAttribute(attn_kernel, cudaFuncAttributeMaxDynamicSharedMemorySize, (int)smem);
    attn_kernel<<<dim3(S_LEN / 64, NH), 256, smem>>>(qn, kn, vv, mask, ao);

    // output projection: out = ao @ Wo^T  [2048,4096] K=4096
    split(ao, ao_hi, ao_lo, 2048 * 4096);
    mma_gemm_kernel<<<dim3(4096 / BN, M / BM), 256>>>(
        ao_hi, ao_lo, Wo_hi, Wo_lo, bo, out, M, 4096, 4096);
}

// round 4
// speedup vs baseline: 3.3966x; 2.5574x over previous
#include <cuda_runtime.h>
#include <cuda_bf16.h>
#include <math.h>
#include <stdint.h>

#define S_LEN 2048
#define HID   4096
#define NH    32
#define DQK   192
#define DV    128

// ---------------------------------------------------------------------------
// scratch (device globals; no allocations allowed)
// ---------------------------------------------------------------------------
__device__ float g_cq [2048*1536];
__device__ float g_qc [2048*4096];
__device__ float g_qr [2048*2048];
__device__ float g_ckv[2048*512];
__device__ float g_kc [2048*4096];
__device__ float g_kr [2048*64];
__device__ float g_v  [2048*4096];
__device__ float g_ao [2048*4096];

// bf16 hi/lo splits
__device__ __align__(16) __nv_bfloat16 g_h_hi [2048*4096], g_h_lo [2048*4096];
__device__ __align__(16) __nv_bfloat16 g_cq_hi[2048*1536], g_cq_lo[2048*1536];
__device__ __align__(16) __nv_bfloat16 g_ckv_hi[2048*512], g_ckv_lo[2048*512];
__device__ __align__(16) __nv_bfloat16 g_ao_hi[2048*4096], g_ao_lo[2048*4096];
__device__ __align__(16) __nv_bfloat16 g_Wqlr_hi[1536*4096], g_Wqlr_lo[1536*4096];
__device__ __align__(16) __nv_bfloat16 g_Wqc_hi [4096*1536], g_Wqc_lo [4096*1536];
__device__ __align__(16) __nv_bfloat16 g_Wqr_hi [2048*1536], g_Wqr_lo [2048*1536];
__device__ __align__(16) __nv_bfloat16 g_Wkv_hi [512*4096],  g_Wkv_lo [512*4096];
__device__ __align__(16) __nv_bfloat16 g_Wkc_hi [4096*512],  g_Wkc_lo [4096*512];
__device__ __align__(16) __nv_bfloat16 g_Wv_hi  [4096*512],  g_Wv_lo  [4096*512];
__device__ __align__(16) __nv_bfloat16 g_Wo_hi  [4096*4096], g_Wo_lo  [4096*4096];

// attention operands in bf16 hi/lo
__device__ __align__(16) __nv_bfloat16 g_qhi[2048*32*192], g_qlo[2048*32*192];
__device__ __align__(16) __nv_bfloat16 g_khi[2048*32*192], g_klo[2048*32*192];
__device__ __align__(16) __nv_bfloat16 g_vhi[2048*4096],   g_vlo[2048*4096];

// ---------------------------------------------------------------------------
// small PTX helpers
// ---------------------------------------------------------------------------
__device__ __forceinline__ uint32_t smem_u32(const void* p) {
    uint32_t a;
    asm("{ .reg .u64 t; cvta.to.shared.u64 t, %1; cvt.u32.u64 %0, t; }" : "=r"(a) : "l"(p));
    return a;
}
#define CP_ASYNC16(dst_u32, src_ptr) \
    asm volatile("cp.async.cg.shared.global [%0], [%1], 16;" \
                 :: "r"(dst_u32), "l"(__cvta_generic_to_global(src_ptr)) : "memory")
#define CP_COMMIT() asm volatile("cp.async.commit_group;" ::: "memory")
#define CP_WAIT(n)  asm volatile("cp.async.wait_group %0;" :: "n"(n) : "memory")

__device__ __forceinline__ void ldmx4(uint32_t& r0, uint32_t& r1, uint32_t& r2, uint32_t& r3,
                                      uint32_t addr) {
    asm volatile("ldmatrix.sync.aligned.m8n8.x4.shared.b16 {%0,%1,%2,%3}, [%4];"
                 : "=r"(r0), "=r"(r1), "=r"(r2), "=r"(r3) : "r"(addr));
}
__device__ __forceinline__ void ldmx4t(uint32_t& r0, uint32_t& r1, uint32_t& r2, uint32_t& r3,
                                       uint32_t addr) {
    asm volatile("ldmatrix.sync.aligned.m8n8.x4.trans.shared.b16 {%0,%1,%2,%3}, [%4];"
                 : "=r"(r0), "=r"(r1), "=r"(r2), "=r"(r3) : "r"(addr));
}
__device__ __forceinline__ void mma_bf16(float* d, const uint32_t* a, const uint32_t* b) {
    asm volatile("mma.sync.aligned.m16n8k16.row.col.f32.bf16.bf16.f32 "
                 "{%0,%1,%2,%3}, {%4,%5,%6,%7}, {%8,%9}, {%0,%1,%2,%3};"
                 : "+f"(d[0]), "+f"(d[1]), "+f"(d[2]), "+f"(d[3])
                 : "r"(a[0]), "r"(a[1]), "r"(a[2]), "r"(a[3]), "r"(b[0]), "r"(b[1]));
}

// ---------------------------------------------------------------------------
// fp32 -> bf16 (hi, lo) split
// ---------------------------------------------------------------------------
__global__ void split_bf16_kernel(const float* __restrict__ x,
                                  __nv_bfloat16* __restrict__ hi,
                                  __nv_bfloat16* __restrict__ lo, int n4) {
    int i = blockIdx.x * blockDim.x + threadIdx.x;
    if (i >= n4) return;
    float4 v = ((const float4*)x)[i];
    __nv_bfloat16 h0 = __float2bfloat16(v.x), h1 = __float2bfloat16(v.y);
    __nv_bfloat16 h2 = __float2bfloat16(v.z), h3 = __float2bfloat16(v.w);
    __nv_bfloat16 l0 = __float2bfloat16(v.x - __bfloat162float(h0));
    __nv_bfloat16 l1 = __float2bfloat16(v.y - __bfloat162float(h1));
    __nv_bfloat16 l2 = __float2bfloat16(v.z - __bfloat162float(h2));
    __nv_bfloat16 l3 = __float2bfloat16(v.w - __bfloat162float(h3));
    ((__nv_bfloat162*)hi)[i*2 + 0] = __nv_bfloat162(h0, h1);
    ((__nv_bfloat162*)hi)[i*2 + 1] = __nv_bfloat162(h2, h3);
    ((__nv_bfloat162*)lo)[i*2 + 0] = __nv_bfloat162(l0, l1);
    ((__nv_bfloat162*)lo)[i*2 + 1] = __nv_bfloat162(l2, l3);
}

// ---------------------------------------------------------------------------
// warp-MMA bf16 GEMM with fp32 emulation (3 passes)  [unchanged, passing]
// ---------------------------------------------------------------------------
#define BM 128
#define BN 128
#define ROWB 80

__global__ void __launch_bounds__(256)
mma_gemm_kernel(const __nv_bfloat16* __restrict__ Ahi, const __nv_bfloat16* __restrict__ Alo,
                const __nv_bfloat16* __restrict__ Whi, const __nv_bfloat16* __restrict__ Wlo,
                const float* __restrict__ bias, float* __restrict__ C,
                int M, int N, int K) {
    __shared__ __align__(16) char smbuf[2][2 * BM * ROWB];

    const int tid = threadIdx.x, wid = tid >> 5, lane = tid & 31;
    const int warp_m = wid >> 1;
    const int warp_n = wid & 1;
    const int row0 = blockIdx.y * BM, col0 = blockIdx.x * BN;

    const uint32_t sA[2] = { smem_u32(&smbuf[0][0]), smem_u32(&smbuf[1][0]) };
    const uint32_t sW[2] = { sA[0] + BM * ROWB, sA[1] + BM * ROWB };

    const int a_row = (lane & 7) + ((lane >> 3) & 1) * 8;
    const int a_kof = (lane >> 4) * 8;
    const int b_row = (lane & 7) + (lane >> 4) * 8;
    const int b_kof = ((lane >> 3) & 1) * 8;

    const __nv_bfloat16* APs[3] = { Ahi, Ahi, Alo };
    const __nv_bfloat16* WPs[3] = { Whi, Wlo, Whi };

    const int kc = K >> 5;
    const int nc = kc * 3;

    float acc[2][8][4];
#pragma unroll
    for (int mt = 0; mt < 2; mt++)
#pragma unroll
        for (int nt = 0; nt < 8; nt++)
#pragma unroll
            for (int e = 0; e < 4; e++) acc[mt][nt][e] = 0.f;

    auto load_chunk = [&](int c, int buf) {
        const int p  = c / kc;
        const int kk = (c - p * kc) << 5;
        const __nv_bfloat16* Ap = APs[p];
        const __nv_bfloat16* Wp = WPs[p];
#pragma unroll
        for (int i = 0; i < 2; i++) {
            int idx = tid + i * 256;
            int r = idx >> 2, cb = idx & 3;
            CP_ASYNC16(sA[buf] + r * ROWB + cb * 16,
                       Ap + (size_t)(row0 + r) * K + kk + cb * 8);
        }
#pragma unroll
        for (int i = 0; i < 2; i++) {
            int idx = tid + i * 256;
            int r = idx >> 2, cb = idx & 3;
            CP_ASYNC16(sW[buf] + r * ROWB + cb * 16,
                       Wp + (size_t)(col0 + r) * K + kk + cb * 8);
        }
        CP_COMMIT();
    };

    load_chunk(0, 0);

    for (int c = 0; c < nc; c++) {
        const int buf = c & 1;
        if (c + 1 < nc) {
            load_chunk(c + 1, buf ^ 1);
            CP_WAIT(1);
        } else {
            CP_WAIT(0);
        }
        __syncthreads();

#pragma unroll
        for (int ks = 0; ks < 2; ks++) {
            const int kb = ks * 16;
            uint32_t af[2][4], bf[4][4];
#pragma unroll
            for (int mt = 0; mt < 2; mt++) {
                uint32_t addr = sA[buf] + (warp_m * 32 + mt * 16 + a_row) * ROWB
                              + (kb + a_kof) * 2;
                ldmx4(af[mt][0], af[mt][1], af[mt][2], af[mt][3], addr);
            }
#pragma unroll
            for (int np = 0; np < 4; np++) {
                uint32_t addr = sW[buf] + (warp_n * 64 + np * 16 + b_row) * ROWB
                              + (kb + b_kof) * 2;
                ldmx4(bf[np][0], bf[np][1], bf[np][2], bf[np][3], addr);
            }
#pragma unroll
            for (int mt = 0; mt < 2; mt++)
#pragma unroll
                for (int nt = 0; nt < 8; nt++) {
                    uint32_t b2[2] = { bf[nt >> 1][(nt & 1) * 2],
                                       bf[nt >> 1][(nt & 1) * 2 + 1] };
                    mma_bf16(acc[mt][nt], af[mt], b2);
                }
        }
        __syncthreads();
    }

    const int rbase = row0 + warp_m * 32 + (lane >> 2);
    const int cbase = col0 + warp_n * 64 + (lane & 3) * 2;
#pragma unroll
    for (int mt = 0; mt < 2; mt++) {
#pragma unroll
        for (int nt = 0; nt < 8; nt++) {
            const int cc = cbase + nt * 8;
            const float b0 = bias[cc], b1 = bias[cc + 1];
            const int r0 = rbase + mt * 16;
            *(float2*)&C[(size_t)r0 * N + cc] =
                make_float2(acc[mt][nt][0] + b0, acc[mt][nt][1] + b1);
            *(float2*)&C[(size_t)(r0 + 8) * N + cc] =
                make_float2(acc[mt][nt][2] + b0, acc[mt][nt][3] + b1);
        }
    }
}

// ---------------------------------------------------------------------------
// SIMT GEMM (tiny k_rope: N=64)
// ---------------------------------------------------------------------------
__global__ void gemm_bias_kernel(const float* __restrict__ A,
                                 const float* __restrict__ W,
                                 const float* __restrict__ bias,
                                 float* __restrict__ C,
                                 int M, int N, int K) {
    __shared__ float As[16][64];
    __shared__ float Ws[16][64];
    const int tid  = threadIdx.x;
    const int row0 = blockIdx.y * 64;
    const int col0 = blockIdx.x * 64;
    const int ty = tid >> 4, tx = tid & 15;
    const int lr = tid >> 2;
    const int lk = (tid & 3) * 4;

    float acc[4][4];
#pragma unroll
    for (int i = 0; i < 4; i++)
#pragma unroll
        for (int j = 0; j < 4; j++) acc[i][j] = 0.f;

    for (int kk = 0; kk < K; kk += 16) {
        float4 av = *(const float4*)&A[(size_t)(row0 + lr) * K + kk + lk];
        float4 wv = *(const float4*)&W[(size_t)(col0 + lr) * K + kk + lk];
        As[lk + 0][lr] = av.x; As[lk + 1][lr] = av.y;
        As[lk + 2][lr] = av.z; As[lk + 3][lr] = av.w;
        Ws[lk + 0][lr] = wv.x; Ws[lk + 1][lr] = wv.y;
        Ws[lk + 2][lr] = wv.z; Ws[lk + 3][lr] = wv.w;
        __syncthreads();
#pragma unroll
        for (int k = 0; k < 16; k++) {
            float4 a = *(const float4*)&As[k][ty * 4];
            float4 b = *(const float4*)&Ws[k][tx * 4];
            float ar[4] = {a.x, a.y, a.z, a.w};
            float br[4] = {b.x, b.y, b.z, b.w};
#pragma unroll
            for (int i = 0; i < 4; i++)
#pragma unroll
                for (int j = 0; j < 4; j++) acc[i][j] += ar[i] * br[j];
        }
        __syncthreads();
    }
#pragma unroll
    for (int i = 0; i < 4; i++) {
        const int r = row0 + ty * 4 + i;
#pragma unroll
        for (int j = 0; j < 4; j++) {
            const int c = col0 + tx * 4 + j;
            C[(size_t)r * N + c] = acc[i][j] + bias[c];
        }
    }
}

// ---------------- rotate-half RoPE, in place, x: [S, D] (fp32) --------------
__global__ void rope_kernel(float* __restrict__ x, int S, int D) {
    const int half = D / 2;
    const int idx = blockIdx.x * blockDim.x + threadIdx.x;
    if (idx >= S * half) return;
    const int s = idx / half, j = idx % half;
    float ex  = (float)(2 * j) / (float)D;
    float inv = 1.0f / powf(10000.0f, ex);
    float ang = (float)s * inv;
    float sn, c;
    sincosf(ang, &sn, &c);
    float x1 = x[(size_t)s * D + j];
    float x2 = x[(size_t)s * D + half + j];
    x[(size_t)s * D + j]        = x1 * c - x2 * sn;
    x[(size_t)s * D + half + j] = x2 * c + x1 * sn;
}

// ---------------- concat + RMSnorm over 192 -> bf16 hi/lo --------------------
__global__ void fuse_q_kernel(const float* __restrict__ qc,
                              const float* __restrict__ qr,
                              __nv_bfloat16* __restrict__ qh,
                              __nv_bfloat16* __restrict__ ql) {
    const int gw   = (blockIdx.x * blockDim.x + threadIdx.x) >> 5;
    const int lane = threadIdx.x & 31;
    const int s = gw >> 5, h = gw & 31;
    float vals[6]; float ss = 0.f;
#pragma unroll
    for (int t = 0; t < 6; t++) {
        int d = lane + 32 * t;
        float x = (d < 128) ? qc[(size_t)s * HID + h * 128 + d]
                            : qr[(size_t)s * 2048 + h * 64 + (d - 128)];
        vals[t] = x; ss += x * x;
    }
#pragma unroll
    for (int o = 16; o; o >>= 1) ss += __shfl_xor_sync(0xffffffffu, ss, o);
    float r = rsqrtf(ss * (1.f / 192.f) + 1.1920929e-7f);
#pragma unroll
    for (int t = 0; t < 6; t++) {
        float x = vals[t] * r;
        __nv_bfloat16 hb = __float2bfloat16(x);
        __nv_bfloat16 lb = __float2bfloat16(x - __bfloat162float(hb));
        size_t o_ = ((size_t)s * NH + h) * DQK + lane + 32 * t;
        qh[o_] = hb; ql[o_] = lb;
    }
}

__global__ void fuse_k_kernel(const float* __restrict__ kc,
                              const float* __restrict__ kr,
                              __nv_bfloat16* __restrict__ kh,
                              __nv_bfloat16* __restrict__ kl) {
    const int gw   = (blockIdx.x * blockDim.x + threadIdx.x) >> 5;
    const int lane = threadIdx.x & 31;
    const int s = gw >> 5, h = gw & 31;
    float vals[6]; float ss = 0.f;
#pragma unroll
    for (int t = 0; t < 6; t++) {
        int d = lane + 32 * t;
        float x = (d < 128) ? kc[(size_t)s * HID + h * 128 + d]
                            : kr[(size_t)s * 64 + (d - 128)];
        vals[t] = x; ss += x * x;
    }
#pragma unroll
    for (int o = 16; o; o >>= 1) ss += __shfl_xor_sync(0xffffffffu, ss, o);
    float r = rsqrtf(ss * (1.f / 192.f) + 1.1920929e-7f);
#pragma unroll
    for (int t = 0; t < 6; t++) {
        float x = vals[t] * r;
        __nv_bfloat16 hb = __float2bfloat16(x);
        __nv_bfloat16 lb = __float2bfloat16(x - __bfloat162float(hb));
        size_t o_ = ((size_t)s * NH + h) * DQK + lane + 32 * t;
        kh[o_] = hb; kl[o_] = lb;
    }
}

// ---------------------------------------------------------------------------
// flash attention with mma.sync (bf16 hi/lo emulation)
// CTA: 128 q-rows x 1 head, 8 warps x 16 rows; key chunks of 64.
// ---------------------------------------------------------------------------
// smem byte offsets (half strides: Q/K 200, V 136, P 72)
#define OQH 0
#define OQL (OQH + 128*400)
#define OKH (OQL + 128*400)
#define OKL (OKH + 64*400)
#define OVH (OKL + 64*400)
#define OVL (OVH + 64*272)
#define OPH (OVL + 64*272)
#define OPL (OPH + 128*144)
#define ATT_SMEM (OPL + 128*144)   // 225280 bytes

__global__ void __launch_bounds__(256, 1)
attn_mma_kernel(const __nv_bfloat16* __restrict__ qhi, const __nv_bfloat16* __restrict__ qlo,
                const __nv_bfloat16* __restrict__ khi, const __nv_bfloat16* __restrict__ klo,
                const __nv_bfloat16* __restrict__ vhi, const __nv_bfloat16* __restrict__ vlo,
                const float* __restrict__ mask, float* __restrict__ out) {
    extern __shared__ char smraw[];
    const uint32_t s0 = smem_u32(smraw);
    const int h = blockIdx.y, q0 = blockIdx.x * 128;
    const int tid = threadIdx.x, wid = tid >> 5, lane = tid & 31;

    // Q load: 128 rows x 24 16B-chunks, hi+lo
    for (int i = tid; i < 3072; i += 256) {
        int r = i / 24, cb = i % 24;
        size_t src = ((size_t)(q0 + r) * NH + h) * DQK + cb * 8;
        CP_ASYNC16(s0 + OQH + r * 400 + cb * 16, qhi + src);
        CP_ASYNC16(s0 + OQL + r * 400 + cb * 16, qlo + src);
    }
    CP_COMMIT();

    const float scale = 1.0f / sqrtf(192.0f);
    float m0 = -1e30f, m1 = -1e30f, l0 = 0.f, l1 = 0.f;
    float acc[16][4];
#pragma unroll
    for (int nt = 0; nt < 16; nt++)
#pragma unroll
        for (int e = 0; e < 4; e++) acc[nt][e] = 0.f;

    // ldmatrix lane addressing (GEMM-proven conventions)
    const int a_r  = (lane & 7) + ((lane >> 3) & 1) * 8;  // A rows (also V-trans k rows)
    const int a_k  = (lane >> 4) * 8;                     // A k offset (also V-trans n off)
    const int bk_r = (lane & 7) + (lane >> 4) * 8;        // K B rows (n)
    const int bk_k = ((lane >> 3) & 1) * 8;               // K B k offset
    const int prow  = lane >> 2;
    const int pcol2 = (lane & 3) * 2;

    for (int c = 0; c < 32; c++) {
        const int k0 = c * 64;
        for (int i = tid; i < 1536; i += 256) {
            int r = i / 24, cb = i % 24;
            size_t src = ((size_t)(k0 + r) * NH + h) * DQK + cb * 8;
            CP_ASYNC16(s0 + OKH + r * 400 + cb * 16, khi + src);
            CP_ASYNC16(s0 + OKL + r * 400 + cb * 16, klo + src);
        }
        for (int i = tid; i < 1024; i += 256) {
            int r = i / 16, cb = i % 16;
            size_t src = (size_t)(k0 + r) * HID + h * DV + cb * 8;
            CP_ASYNC16(s0 + OVH + r * 272 + cb * 16, vhi + src);
            CP_ASYNC16(s0 + OVL + r * 272 + cb * 16, vlo + src);
        }
        CP_COMMIT();
        CP_WAIT(0);
        __syncthreads();

        // ---- S = Q K^T (hi*hi + lo*hi + hi*lo) ----
        float sacc[8][4];
#pragma unroll
        for (int nt = 0; nt < 8; nt++)
#pragma unroll
            for (int e = 0; e < 4; e++) sacc[nt][e] = 0.f;

#pragma unroll
        for (int kt = 0; kt < 12; kt++) {
            uint32_t ah[4], al[4];
            ldmx4(ah[0], ah[1], ah[2], ah[3],
                  s0 + OQH + (wid * 16 + a_r) * 400 + (kt * 16 + a_k) * 2);
            ldmx4(al[0], al[1], al[2], al[3],
                  s0 + OQL + (wid * 16 + a_r) * 400 + (kt * 16 + a_k) * 2);
#pragma unroll
            for (int n2 = 0; n2 < 4; n2++) {
                uint32_t bh[4], bl[4];
                ldmx4(bh[0], bh[1], bh[2], bh[3],
                      s0 + OKH + (n2 * 16 + bk_r) * 400 + (kt * 16 + bk_k) * 2);
                ldmx4(bl[0], bl[1], bl[2], bl[3],
                      s0 + OKL + (n2 * 16 + bk_r) * 400 + (kt * 16 + bk_k) * 2);
                uint32_t bh0[2] = { bh[0], bh[1] }, bh1[2] = { bh[2], bh[3] };
                uint32_t bl0[2] = { bl[0], bl[1] }, bl1[2] = { bl[2], bl[3] };
                mma_bf16(sacc[n2 * 2],     ah, bh0);
                mma_bf16(sacc[n2 * 2 + 1], ah, bh1);
                mma_bf16(sacc[n2 * 2],     al, bh0);
                mma_bf16(sacc[n2 * 2 + 1], al, bh1);
                mma_bf16(sacc[n2 * 2],     ah, bl0);
                mma_bf16(sacc[n2 * 2 + 1], ah, bl1);
            }
        }

        // ---- softmax (warp-local rows) ----
        const int rg0 = q0 + wid * 16 + prow;
        float sc[8][4];
        float mx0 = -1e30f, mx1 = -1e30f;
#pragma unroll
        for (int nt = 0; nt < 8; nt++) {
            int col = k0 + nt * 8 + pcol2;
            float2 mk0 = *(const float2*)&mask[(size_t)rg0 * S_LEN + col];
            float2 mk1 = *(const float2*)&mask[(size_t)(rg0 + 8) * S_LEN + col];
            sc[nt][0] = sacc[nt][0] * scale + mk0.x;
            sc[nt][1] = sacc[nt][1] * scale + mk0.y;
            sc[nt][2] = sacc[nt][2] * scale + mk1.x;
            sc[nt][3] = sacc[nt][3] * scale + mk1.y;
            mx0 = fmaxf(mx0, fmaxf(sc[nt][0], sc[nt][1]));
            mx1 = fmaxf(mx1, fmaxf(sc[nt][2], sc[nt][3]));
        }
        mx0 = fmaxf(mx0, __shfl_xor_sync(0xffffffffu, mx0, 1));
        mx0 = fmaxf(mx0, __shfl_xor_sync(0xffffffffu, mx0, 2));
        mx1 = fmaxf(mx1, __shfl_xor_sync(0xffffffffu, mx1, 1));
        mx1 = fmaxf(mx1, __shfl_xor_sync(0xffffffffu, mx1, 2));
        float mn0 = fmaxf(m0, mx0), mn1 = fmaxf(m1, mx1);
        float al0 = __expf(m0 - mn0), al1 = __expf(m1 - mn1);
        m0 = mn0; m1 = mn1;

        float ps0 = 0.f, ps1 = 0.f;
#pragma unroll
        for (int nt = 0; nt < 8; nt++) {
            float p00 = __expf(sc[nt][0] - mn0), p01 = __expf(sc[nt][1] - mn0);
            float p10 = __expf(sc[nt][2] - mn1), p11 = __expf(sc[nt][3] - mn1);
            ps0 += p00 + p01; ps1 += p10 + p11;
            __nv_bfloat16 h00 = __float2bfloat16(p00), h01 = __float2bfloat16(p01);
            __nv_bfloat16 h10 = __float2bfloat16(p10), h11 = __float2bfloat16(p11);
            uint32_t pk0 = (uint32_t)__bfloat16_as_ushort(h00) |
                           ((uint32_t)__bfloat16_as_ushort(h01) << 16);
            uint32_t pk1 = (uint32_t)__bfloat16_as_ushort(h10) |
                           ((uint32_t)__bfloat16_as_ushort(h11) << 16);
            __nv_bfloat16 g00 = __float2bfloat16(p00 - __bfloat162float(h00));
            __nv_bfloat16 g01 = __float2bfloat16(p01 - __bfloat162float(h01));
            __nv_bfloat16 g10 = __float2bfloat16(p10 - __bfloat162float(h10));
            __nv_bfloat16 g11 = __float2bfloat16(p11 - __bfloat162float(h11));
            uint32_t qk0 = (uint32_t)__bfloat16_as_ushort(g00) |
                           ((uint32_t)__bfloat16_as_ushort(g01) << 16);
            uint32_t qk1 = (uint32_t)__bfloat16_as_ushort(g10) |
                           ((uint32_t)__bfloat16_as_ushort(g11) << 16);
            int colb = (nt * 8 + pcol2) * 2;
            *(uint32_t*)(smraw + OPH + (wid * 16 + prow) * 144 + colb)     = pk0;
            *(uint32_t*)(smraw + OPH + (wid * 16 + prow + 8) * 144 + colb) = pk1;
            *(uint32_t*)(smraw + OPL + (wid * 16 + prow) * 144 + colb)     = qk0;
            *(uint32_t*)(smraw + OPL + (wid * 16 + prow + 8) * 144 + colb) = qk1;
        }
        ps0 += __shfl_xor_sync(0xffffffffu, ps0, 1);
        ps0 += __shfl_xor_sync(0xffffffffu, ps0, 2);
        ps1 += __shfl_xor_sync(0xffffffffu, ps1, 1);
        ps1 += __shfl_xor_sync(0xffffffffu, ps1, 2);
        l0 = al0 * l0 + ps0;
        l1 = al1 * l1 + ps1;
#pragma unroll
        for (int nt = 0; nt < 16; nt++) {
            acc[nt][0] *= al0; acc[nt][1] *= al0;
            acc[nt][2] *= al1; acc[nt][3] *= al1;
        }
        __syncwarp();

        // ---- O += P V (Phi*Vhi + Plo*Vhi + Phi*Vlo) ----
#pragma unroll
        for (int kt = 0; kt < 4; kt++) {
            uint32_t ph[4], pl[4];
            ldmx4(ph[0], ph[1], ph[2], ph[3],
                  s0 + OPH + (wid * 16 + a_r) * 144 + (kt * 16 + a_k) * 2);
            ldmx4(pl[0], pl[1], pl[2], pl[3],
                  s0 + OPL + (wid * 16 + a_r) * 144 + (kt * 16 + a_k) * 2);
#pragma unroll
            for (int n2 = 0; n2 < 8; n2++) {
                uint32_t vh[4], vl[4];
                ldmx4t(vh[0], vh[1], vh[2], vh[3],
                       s0 + OVH + (kt * 16 + a_r) * 272 + (n2 * 16 + a_k) * 2);
                ldmx4t(vl[0], vl[1], vl[2], vl[3],
                       s0 + OVL + (kt * 16 + a_r) * 272 + (n2 * 16 + a_k) * 2);
                uint32_t vh0[2] = { vh[0], vh[1] }, vh1[2] = { vh[2], vh[3] };
                uint32_t vl0[2] = { vl[0], vl[1] }, vl1[2] = { vl[2], vl[3] };
                mma_bf16(acc[n2 * 2],     ph, vh0);
                mma_bf16(acc[n2 * 2 + 1], ph, vh1);
                mma_bf16(acc[n2 * 2],     pl, vh0);
                mma_bf16(acc[n2 * 2 + 1], pl, vh1);
                mma_bf16(acc[n2 * 2],     ph, vl0);
                mma_bf16(acc[n2 * 2 + 1], ph, vl1);
            }
        }
        __syncthreads();
    }

    // epilogue
    const float i0 = 1.f / l0, i1 = 1.f / l1;
    const int orow = q0 + wid * 16 + prow;
#pragma unroll
    for (int nt = 0; nt < 16; nt++) {
        int col = h * DV + nt * 8 + pcol2;
        *(float2*)&out[(size_t)orow * HID + col] =
            make_float2(acc[nt][0] * i0, acc[nt][1] * i0);
        *(float2*)&out[(size_t)(orow + 8) * HID + col] =
            make_float2(acc[nt][2] * i1, acc[nt][3] * i1);
    }
}

// ---------------------------------------------------------------------------
// launcher
// ---------------------------------------------------------------------------
static void split(const float* x, __nv_bfloat16* hi, __nv_bfloat16* lo, int n) {
    int n4 = n / 4;
    split_bf16_kernel<<<(n4 + 255) / 256, 256>>>(x, hi, lo, n4);
}

extern "C" void kernel_launch(void* const* d_in, const int* in_sizes, int n_in,
                              void* d_out, int out_size) {
    const float* hidden  = (const float*)d_in[0];
    const float* mask    = (const float*)d_in[1];
    const float* Wq_lr   = (const float*)d_in[2];
    const float* bq_lr   = (const float*)d_in[3];
    const float* Wq_rope = (const float*)d_in[4];
    const float* bq_rope = (const float*)d_in[5];
    const float* Wq_c    = (const float*)d_in[6];
    const float* bq_c    = (const float*)d_in[7];
    const float* Wkv     = (const float*)d_in[8];
    const float* bkv     = (const float*)d_in[9];
    const float* Wk_rope = (const float*)d_in[10];
    const float* bk_rope = (const float*)d_in[11];
    const float* Wk_c    = (const float*)d_in[12];
    const float* bk_c    = (const float*)d_in[13];
    const float* Wv      = (const float*)d_in[14];
    const float* bv      = (const float*)d_in[15];
    const float* Wo      = (const float*)d_in[16];
    const float* bo      = (const float*)d_in[17];
    float* out = (float*)d_out;

    float *cq, *qc, *qr, *ckv, *kc, *kr, *vv, *ao;
    cudaGetSymbolAddress((void**)&cq,  g_cq);
    cudaGetSymbolAddress((void**)&qc,  g_qc);
    cudaGetSymbolAddress((void**)&qr,  g_qr);
    cudaGetSymbolAddress((void**)&ckv, g_ckv);
    cudaGetSymbolAddress((void**)&kc,  g_kc);
    cudaGetSymbolAddress((void**)&kr,  g_kr);
    cudaGetSymbolAddress((void**)&vv,  g_v);
    cudaGetSymbolAddress((void**)&ao,  g_ao);

    __nv_bfloat16 *h_hi, *h_lo, *cq_hi, *cq_lo, *ckv_hi, *ckv_lo, *ao_hi, *ao_lo;
    __nv_bfloat16 *Wqlr_hi, *Wqlr_lo, *Wqc_hi, *Wqc_lo, *Wqr_hi, *Wqr_lo;
    __nv_bfloat16 *Wkv_hi, *Wkv_lo, *Wkc_hi, *Wkc_lo, *Wv_hi, *Wv_lo, *Wo_hi, *Wo_lo;
    __nv_bfloat16 *qhi, *qlo, *khi, *klo, *vhi, *vlo;
    cudaGetSymbolAddress((void**)&h_hi,   g_h_hi);   cudaGetSymbolAddress((void**)&h_lo,   g_h_lo);
    cudaGetSymbolAddress((void**)&cq_hi,  g_cq_hi);  cudaGetSymbolAddress((void**)&cq_lo,  g_cq_lo);
    cudaGetSymbolAddress((void**)&ckv_hi, g_ckv_hi); cudaGetSymbolAddress((void**)&ckv_lo, g_ckv_lo);
    cudaGetSymbolAddress((void**)&ao_hi,  g_ao_hi);  cudaGetSymbolAddress((void**)&ao_lo,  g_ao_lo);
    cudaGetSymbolAddress((void**)&Wqlr_hi, g_Wqlr_hi); cudaGetSymbolAddress((void**)&Wqlr_lo, g_Wqlr_lo);
    cudaGetSymbolAddress((void**)&Wqc_hi,  g_Wqc_hi);  cudaGetSymbolAddress((void**)&Wqc_lo,  g_Wqc_lo);
    cudaGetSymbolAddress((void**)&Wqr_hi,  g_Wqr_hi);  cudaGetSymbolAddress((void**)&Wqr_lo,  g_Wqr_lo);
    cudaGetSymbolAddress((void**)&Wkv_hi,  g_Wkv_hi);  cudaGetSymbolAddress((void**)&Wkv_lo,  g_Wkv_lo);
    cudaGetSymbolAddress((void**)&Wkc_hi,  g_Wkc_hi);  cudaGetSymbolAddress((void**)&Wkc_lo,  g_Wkc_lo);
    cudaGetSymbolAddress((void**)&Wv_hi,   g_Wv_hi);   cudaGetSymbolAddress((void**)&Wv_lo,   g_Wv_lo);
    cudaGetSymbolAddress((void**)&Wo_hi,   g_Wo_hi);   cudaGetSymbolAddress((void**)&Wo_lo,   g_Wo_lo);
    cudaGetSymbolAddress((void**)&qhi, g_qhi); cudaGetSymbolAddress((void**)&qlo, g_qlo);
    cudaGetSymbolAddress((void**)&khi, g_khi); cudaGetSymbolAddress((void**)&klo, g_klo);
    cudaGetSymbolAddress((void**)&vhi, g_vhi); cudaGetSymbolAddress((void**)&vlo, g_vlo);

    const int M = 2048;

    split(hidden,  h_hi,    h_lo,    2048 * 4096);
    split(Wq_lr,   Wqlr_hi, Wqlr_lo, 1536 * 4096);
    split(Wq_c,    Wqc_hi,  Wqc_lo,  4096 * 1536);
    split(Wq_rope, Wqr_hi,  Wqr_lo,  2048 * 1536);
    split(Wkv,     Wkv_hi,  Wkv_lo,  512 * 4096);
    split(Wk_c,    Wkc_hi,  Wkc_lo,  4096 * 512);
    split(Wv,      Wv_hi,   Wv_lo,   4096 * 512);
    split(Wo,      Wo_hi,   Wo_lo,   4096 * 4096);

    mma_gemm_kernel<<<dim3(1536 / BN, M / BM), 256>>>(
        h_hi, h_lo, Wqlr_hi, Wqlr_lo, bq_lr, cq, M, 1536, 4096);
    split(cq, cq_hi, cq_lo, 2048 * 1536);

    mma_gemm_kernel<<<dim3(4096 / BN, M / BM), 256>>>(
        cq_hi, cq_lo, Wqc_hi, Wqc_lo, bq_c, qc, M, 4096, 1536);
    mma_gemm_kernel<<<dim3(2048 / BN, M / BM), 256>>>(
        cq_hi, cq_lo, Wqr_hi, Wqr_lo, bq_rope, qr, M, 2048, 1536);

    mma_gemm_kernel<<<dim3(512 / BN, M / BM), 256>>>(
        h_hi, h_lo, Wkv_hi, Wkv_lo, bkv, ckv, M, 512, 4096);
    split(ckv, ckv_hi, ckv_lo, 2048 * 512);

    mma_gemm_kernel<<<dim3(4096 / BN, M / BM), 256>>>(
        ckv_hi, ckv_lo, Wkc_hi, Wkc_lo, bk_c, kc, M, 4096, 512);
    mma_gemm_kernel<<<dim3(4096 / BN, M / BM), 256>>>(
        ckv_hi, ckv_lo, Wv_hi, Wv_lo, bv, vv, M, 4096, 512);

    gemm_bias_kernel<<<dim3(1, M / 64), 256>>>(hidden, Wk_rope, bk_rope, kr, M, 64, 4096);

    rope_kernel<<<(2048 * 1024 + 255) / 256, 256>>>(qr, 2048, 2048);
    rope_kernel<<<(2048 * 32 + 255) / 256, 256>>>(kr, 2048, 64);

    fuse_q_kernel<<<8192, 256>>>(qc, qr, qhi, qlo);
    fuse_k_kernel<<<8192, 256>>>(kc, kr, khi, klo);
    split(vv, vhi, vlo, 2048 * 4096);

    cudaFuncSetAttribute(attn_mma_kernel, cudaFuncAttributeMaxDynamicSharedMemorySize, ATT_SMEM);
    attn_mma_kernel<<<dim3(S_LEN / 128, NH), 256, ATT_SMEM>>>(
        qhi, qlo, khi, klo, vhi, vlo, mask, ao);

    split(ao, ao_hi, ao_lo, 2048 * 4096);
    mma_gemm_kernel<<<dim3(4096 / BN, M / BM), 256>>>(
        ao_hi, ao_lo, Wo_hi, Wo_lo, bo, out, M, 4096, 4096);
}

// round 5
// speedup vs baseline: 3.8451x; 1.1320x over previous
#include <cuda_runtime.h>
#include <cuda_bf16.h>
#include <math.h>
#include <stdint.h>

#define S_LEN 2048
#define HID   4096
#define NH    32
#define DQK   192
#define DV    128

// ---------------------------------------------------------------------------
// scratch (device globals; no allocations allowed)
// ---------------------------------------------------------------------------
__device__ float g_qc [2048*4096];
__device__ float g_qr [2048*2048];
__device__ float g_kc [2048*4096];
__device__ float g_kr [2048*128];        // padded N=128
__device__ float g_bkr[128];             // padded bias

// bf16 hi/lo splits
__device__ __align__(16) __nv_bfloat16 g_h_hi [2048*4096], g_h_lo [2048*4096];
__device__ __align__(16) __nv_bfloat16 g_cq_hi[2048*1536], g_cq_lo[2048*1536];
__device__ __align__(16) __nv_bfloat16 g_ckv_hi[2048*512], g_ckv_lo[2048*512];
__device__ __align__(16) __nv_bfloat16 g_ao_hi[2048*4096], g_ao_lo[2048*4096];
__device__ __align__(16) __nv_bfloat16 g_Wqlr_hi[1536*4096], g_Wqlr_lo[1536*4096];
__device__ __align__(16) __nv_bfloat16 g_Wqc_hi [4096*1536], g_Wqc_lo [4096*1536];
__device__ __align__(16) __nv_bfloat16 g_Wqr_hi [2048*1536], g_Wqr_lo [2048*1536];
__device__ __align__(16) __nv_bfloat16 g_Wkv_hi [512*4096],  g_Wkv_lo [512*4096];
__device__ __align__(16) __nv_bfloat16 g_Wkc_hi [4096*512],  g_Wkc_lo [4096*512];
__device__ __align__(16) __nv_bfloat16 g_Wv_hi  [4096*512],  g_Wv_lo  [4096*512];
__device__ __align__(16) __nv_bfloat16 g_Wo_hi  [4096*4096], g_Wo_lo  [4096*4096];
__device__ __align__(16) __nv_bfloat16 g_Wkr_hi [128*4096],  g_Wkr_lo [128*4096];

// attention operands in bf16 hi/lo
__device__ __align__(16) __nv_bfloat16 g_qhi[2048*32*192], g_qlo[2048*32*192];
__device__ __align__(16) __nv_bfloat16 g_khi[2048*32*192], g_klo[2048*32*192];
__device__ __align__(16) __nv_bfloat16 g_vhi[2048*4096],   g_vlo[2048*4096];

// ---------------------------------------------------------------------------
// small PTX helpers
// ---------------------------------------------------------------------------
__device__ __forceinline__ uint32_t smem_u32(const void* p) {
    uint32_t a;
    asm("{ .reg .u64 t; cvta.to.shared.u64 t, %1; cvt.u32.u64 %0, t; }" : "=r"(a) : "l"(p));
    return a;
}
#define CP_ASYNC16(dst_u32, src_ptr) \
    asm volatile("cp.async.cg.shared.global [%0], [%1], 16;" \
                 :: "r"(dst_u32), "l"(__cvta_generic_to_global(src_ptr)) : "memory")
#define CP_COMMIT() asm volatile("cp.async.commit_group;" ::: "memory")
#define CP_WAIT(n)  asm volatile("cp.async.wait_group %0;" :: "n"(n) : "memory")

__device__ __forceinline__ void ldmx4(uint32_t& r0, uint32_t& r1, uint32_t& r2, uint32_t& r3,
                                      uint32_t addr) {
    asm volatile("ldmatrix.sync.aligned.m8n8.x4.shared.b16 {%0,%1,%2,%3}, [%4];"
                 : "=r"(r0), "=r"(r1), "=r"(r2), "=r"(r3) : "r"(addr));
}
__device__ __forceinline__ void ldmx4t(uint32_t& r0, uint32_t& r1, uint32_t& r2, uint32_t& r3,
                                       uint32_t addr) {
    asm volatile("ldmatrix.sync.aligned.m8n8.x4.trans.shared.b16 {%0,%1,%2,%3}, [%4];"
                 : "=r"(r0), "=r"(r1), "=r"(r2), "=r"(r3) : "r"(addr));
}
__device__ __forceinline__ void mma_bf16(float* d, const uint32_t* a, const uint32_t* b) {
    asm volatile("mma.sync.aligned.m16n8k16.row.col.f32.bf16.bf16.f32 "
                 "{%0,%1,%2,%3}, {%4,%5,%6,%7}, {%8,%9}, {%0,%1,%2,%3};"
                 : "+f"(d[0]), "+f"(d[1]), "+f"(d[2]), "+f"(d[3])
                 : "r"(a[0]), "r"(a[1]), "r"(a[2]), "r"(a[3]), "r"(b[0]), "r"(b[1]));
}
__device__ __forceinline__ uint32_t pack_hi(float a, float b) {
    __nv_bfloat16 ha = __float2bfloat16(a), hb = __float2bfloat16(b);
    return (uint32_t)__bfloat16_as_ushort(ha) | ((uint32_t)__bfloat16_as_ushort(hb) << 16);
}
__device__ __forceinline__ uint32_t pack_lo(float a, float b) {
    __nv_bfloat16 ha = __float2bfloat16(a), hb = __float2bfloat16(b);
    __nv_bfloat16 la = __float2bfloat16(a - __bfloat162float(ha));
    __nv_bfloat16 lb = __float2bfloat16(b - __bfloat162float(hb));
    return (uint32_t)__bfloat16_as_ushort(la) | ((uint32_t)__bfloat16_as_ushort(lb) << 16);
}

// ---------------------------------------------------------------------------
// fp32 -> bf16 (hi, lo) split
// ---------------------------------------------------------------------------
__global__ void split_bf16_kernel(const float* __restrict__ x,
                                  __nv_bfloat16* __restrict__ hi,
                                  __nv_bfloat16* __restrict__ lo, int n4) {
    int i = blockIdx.x * blockDim.x + threadIdx.x;
    if (i >= n4) return;
    float4 v = ((const float4*)x)[i];
    ((uint32_t*)hi)[i*2 + 0] = pack_hi(v.x, v.y);
    ((uint32_t*)hi)[i*2 + 1] = pack_hi(v.z, v.w);
    ((uint32_t*)lo)[i*2 + 0] = pack_lo(v.x, v.y);
    ((uint32_t*)lo)[i*2 + 1] = pack_lo(v.z, v.w);
}

// padded k_rope weight split: [64,4096] -> [128,4096] (rows 64..127 zero)
__global__ void pad_krope_kernel(const float* __restrict__ W,
                                 __nv_bfloat16* __restrict__ hi,
                                 __nv_bfloat16* __restrict__ lo,
                                 const float* __restrict__ b,
                                 float* __restrict__ bp) {
    int i = blockIdx.x * blockDim.x + threadIdx.x;
    if (i < 128) bp[i] = (i < 64) ? b[i] : 0.f;
    if (i >= 128 * 4096) return;
    int r = i >> 12;
    float v = (r < 64) ? W[(size_t)r * 4096 + (i & 4095)] : 0.f;
    __nv_bfloat16 h = __float2bfloat16(v);
    hi[i] = h;
    lo[i] = __float2bfloat16(v - __bfloat162float(h));
}

// ---------------------------------------------------------------------------
// warp-MMA bf16 GEMM, fp32 emulation, combined hi/lo per K-chunk.
// C[M,N] = A[M,K] @ W[N,K]^T + bias.  CTA 128x128, BK=32, 8 warps (4x2).
// Outputs: Cf (float, optional), Chi/Clo (bf16 hi/lo split, optional).
// ---------------------------------------------------------------------------
#define ROWB 80
#define OA_HI 0
#define OA_LO 10240
#define OW_HI 20480
#define OW_LO 30720
#define G_BUF 40960
#define G_SMEM (2 * G_BUF)

__global__ void __launch_bounds__(256)
mma_gemm2(const __nv_bfloat16* __restrict__ Ahi, const __nv_bfloat16* __restrict__ Alo,
          const __nv_bfloat16* __restrict__ Whi, const __nv_bfloat16* __restrict__ Wlo,
          const float* __restrict__ bias,
          float* __restrict__ Cf,
          __nv_bfloat16* __restrict__ Chi, __nv_bfloat16* __restrict__ Clo,
          int M, int N, int K) {
    extern __shared__ char gsm[];
    const uint32_t s0 = smem_u32(gsm);
    const int tid = threadIdx.x, wid = tid >> 5, lane = tid & 31;
    const int warp_m = wid >> 1, warp_n = wid & 1;
    const int row0 = blockIdx.y * 128, col0 = blockIdx.x * 128;

    const int a_row = (lane & 7) + ((lane >> 3) & 1) * 8;
    const int a_kof = (lane >> 4) * 8;
    const int b_row = (lane & 7) + (lane >> 4) * 8;
    const int b_kof = ((lane >> 3) & 1) * 8;

    const int kc = K >> 5;

    float acc[2][8][4];
#pragma unroll
    for (int mt = 0; mt < 2; mt++)
#pragma unroll
        for (int nt = 0; nt < 8; nt++)
#pragma unroll
            for (int e = 0; e < 4; e++) acc[mt][nt][e] = 0.f;

    auto load_chunk = [&](int c, int buf) {
        const int kk = c << 5;
        const uint32_t base = s0 + buf * G_BUF;
#pragma unroll
        for (int i = 0; i < 2; i++) {
            int idx = tid + i * 256;
            int r = idx >> 2, cb = idx & 3;
            size_t src = (size_t)(row0 + r) * K + kk + cb * 8;
            CP_ASYNC16(base + OA_HI + r * ROWB + cb * 16, Ahi + src);
            CP_ASYNC16(base + OA_LO + r * ROWB + cb * 16, Alo + src);
        }
#pragma unroll
        for (int i = 0; i < 2; i++) {
            int idx = tid + i * 256;
            int r = idx >> 2, cb = idx & 3;
            size_t src = (size_t)(col0 + r) * K + kk + cb * 8;
            CP_ASYNC16(base + OW_HI + r * ROWB + cb * 16, Whi + src);
            CP_ASYNC16(base + OW_LO + r * ROWB + cb * 16, Wlo + src);
        }
        CP_COMMIT();
    };

    load_chunk(0, 0);

    for (int c = 0; c < kc; c++) {
        const int buf = c & 1;
        if (c + 1 < kc) {
            load_chunk(c + 1, buf ^ 1);
            CP_WAIT(1);
        } else {
            CP_WAIT(0);
        }
        __syncthreads();
        const uint32_t base = s0 + buf * G_BUF;

#pragma unroll
        for (int ks = 0; ks < 2; ks++) {
            const int kb = ks * 16;
            uint32_t ah[2][4], al[2][4];
#pragma unroll
            for (int mt = 0; mt < 2; mt++) {
                uint32_t ra = (warp_m * 32 + mt * 16 + a_row) * ROWB + (kb + a_kof) * 2;
                ldmx4(ah[mt][0], ah[mt][1], ah[mt][2], ah[mt][3], base + OA_HI + ra);
                ldmx4(al[mt][0], al[mt][1], al[mt][2], al[mt][3], base + OA_LO + ra);
            }
#pragma unroll
            for (int np = 0; np < 4; np++) {
                uint32_t bh[4], bl[4];
                uint32_t rb = (warp_n * 64 + np * 16 + b_row) * ROWB + (kb + b_kof) * 2;
                ldmx4(bh[0], bh[1], bh[2], bh[3], base + OW_HI + rb);
                ldmx4(bl[0], bl[1], bl[2], bl[3], base + OW_LO + rb);
#pragma unroll
                for (int j = 0; j < 2; j++) {
                    uint32_t b2h[2] = { bh[j * 2], bh[j * 2 + 1] };
                    uint32_t b2l[2] = { bl[j * 2], bl[j * 2 + 1] };
                    const int nt = np * 2 + j;
#pragma unroll
                    for (int mt = 0; mt < 2; mt++) {
                        mma_bf16(acc[mt][nt], ah[mt], b2h);
                        mma_bf16(acc[mt][nt], al[mt], b2h);
                        mma_bf16(acc[mt][nt], ah[mt], b2l);
                    }
                }
            }
        }
        __syncthreads();
    }

    const int rbase = row0 + warp_m * 32 + (lane >> 2);
    const int cbase = col0 + warp_n * 64 + (lane & 3) * 2;
#pragma unroll
    for (int mt = 0; mt < 2; mt++) {
#pragma unroll
        for (int nt = 0; nt < 8; nt++) {
            const int cc = cbase + nt * 8;
            const float b0 = bias[cc], b1 = bias[cc + 1];
            const int r0 = rbase + mt * 16;
            float v0 = acc[mt][nt][0] + b0, v1 = acc[mt][nt][1] + b1;
            float v2 = acc[mt][nt][2] + b0, v3 = acc[mt][nt][3] + b1;
            if (Cf) {
                *(float2*)&Cf[(size_t)r0 * N + cc] = make_float2(v0, v1);
                *(float2*)&Cf[(size_t)(r0 + 8) * N + cc] = make_float2(v2, v3);
            }
            if (Chi) {
                *(uint32_t*)&Chi[(size_t)r0 * N + cc]       = pack_hi(v0, v1);
                *(uint32_t*)&Chi[(size_t)(r0 + 8) * N + cc] = pack_hi(v2, v3);
                *(uint32_t*)&Clo[(size_t)r0 * N + cc]       = pack_lo(v0, v1);
                *(uint32_t*)&Clo[(size_t)(r0 + 8) * N + cc] = pack_lo(v2, v3);
            }
        }
    }
}

// ---------------- rotate-half RoPE, in place, x: [S, D], row stride ----------
__global__ void rope_kernel(float* __restrict__ x, int S, int D, int stride) {
    const int half = D / 2;
    const int idx = blockIdx.x * blockDim.x + threadIdx.x;
    if (idx >= S * half) return;
    const int s = idx / half, j = idx % half;
    float ex  = (float)(2 * j) / (float)D;
    float inv = 1.0f / powf(10000.0f, ex);
    float ang = (float)s * inv;
    float sn, c;
    sincosf(ang, &sn, &c);
    float x1 = x[(size_t)s * stride + j];
    float x2 = x[(size_t)s * stride + half + j];
    x[(size_t)s * stride + j]        = x1 * c - x2 * sn;
    x[(size_t)s * stride + half + j] = x2 * c + x1 * sn;
}

// ---------------- concat + RMSnorm over 192 -> bf16 hi/lo --------------------
__global__ void fuse_q_kernel(const float* __restrict__ qc,
                              const float* __restrict__ qr,
                              __nv_bfloat16* __restrict__ qh,
                              __nv_bfloat16* __restrict__ ql) {
    const int gw   = (blockIdx.x * blockDim.x + threadIdx.x) >> 5;
    const int lane = threadIdx.x & 31;
    const int s = gw >> 5, h = gw & 31;
    float vals[6]; float ss = 0.f;
#pragma unroll
    for (int t = 0; t < 6; t++) {
        int d = lane + 32 * t;
        float x = (d < 128) ? qc[(size_t)s * HID + h * 128 + d]
                            : qr[(size_t)s * 2048 + h * 64 + (d - 128)];
        vals[t] = x; ss += x * x;
    }
#pragma unroll
    for (int o = 16; o; o >>= 1) ss += __shfl_xor_sync(0xffffffffu, ss, o);
    float r = rsqrtf(ss * (1.f / 192.f) + 1.1920929e-7f);
#pragma unroll
    for (int t = 0; t < 6; t++) {
        float x = vals[t] * r;
        __nv_bfloat16 hb = __float2bfloat16(x);
        size_t o_ = ((size_t)s * NH + h) * DQK + lane + 32 * t;
        qh[o_] = hb;
        ql[o_] = __float2bfloat16(x - __bfloat162float(hb));
    }
}

__global__ void fuse_k_kernel(const float* __restrict__ kc,
                              const float* __restrict__ kr,
                              __nv_bfloat16* __restrict__ kh,
                              __nv_bfloat16* __restrict__ kl) {
    const int gw   = (blockIdx.x * blockDim.x + threadIdx.x) >> 5;
    const int lane = threadIdx.x & 31;
    const int s = gw >> 5, h = gw & 31;
    float vals[6]; float ss = 0.f;
#pragma unroll
    for (int t = 0; t < 6; t++) {
        int d = lane + 32 * t;
        float x = (d < 128) ? kc[(size_t)s * HID + h * 128 + d]
                            : kr[(size_t)s * 128 + (d - 128)];   // padded stride 128
        vals[t] = x; ss += x * x;
    }
#pragma unroll
    for (int o = 16; o; o >>= 1) ss += __shfl_xor_sync(0xffffffffu, ss, o);
    float r = rsqrtf(ss * (1.f / 192.f) + 1.1920929e-7f);
#pragma unroll
    for (int t = 0; t < 6; t++) {
        float x = vals[t] * r;
        __nv_bfloat16 hb = __float2bfloat16(x);
        size_t o_ = ((size_t)s * NH + h) * DQK + lane + 32 * t;
        kh[o_] = hb;
        kl[o_] = __float2bfloat16(x - __bfloat162float(hb));
    }
}

// ---------------------------------------------------------------------------
// flash attention with mma.sync (bf16 hi/lo emulation) + K/V prefetch overlap
// CTA: 128 q-rows x 1 head, 8 warps x 16 rows; key chunks of 64.
// Writes ao directly as bf16 hi/lo.
// ---------------------------------------------------------------------------
#define OQH 0
#define OQL (OQH + 128*400)
#define OKH (OQL + 128*400)
#define OKL (OKH + 64*400)
#define OVH (OKL + 64*400)
#define OVL (OVH + 64*272)
#define OPH (OVL + 64*272)
#define OPL (OPH + 128*144)
#define ATT_SMEM (OPL + 128*144)

__global__ void __launch_bounds__(256, 1)
attn_mma_kernel(const __nv_bfloat16* __restrict__ qhi, const __nv_bfloat16* __restrict__ qlo,
                const __nv_bfloat16* __restrict__ khi, const __nv_bfloat16* __restrict__ klo,
                const __nv_bfloat16* __restrict__ vhi, const __nv_bfloat16* __restrict__ vlo,
                const float* __restrict__ mask,
                __nv_bfloat16* __restrict__ aoh, __nv_bfloat16* __restrict__ aol) {
    extern __shared__ char smraw[];
    const uint32_t s0 = smem_u32(smraw);
    const int h = blockIdx.y, q0 = blockIdx.x * 128;
    const int tid = threadIdx.x, wid = tid >> 5, lane = tid & 31;

    for (int i = tid; i < 3072; i += 256) {
        int r = i / 24, cb = i % 24;
        size_t src = ((size_t)(q0 + r) * NH + h) * DQK + cb * 8;
        CP_ASYNC16(s0 + OQH + r * 400 + cb * 16, qhi + src);
        CP_ASYNC16(s0 + OQL + r * 400 + cb * 16, qlo + src);
    }
    CP_COMMIT();

    auto load_k = [&](int k0) {
        for (int i = tid; i < 1536; i += 256) {
            int r = i / 24, cb = i % 24;
            size_t src = ((size_t)(k0 + r) * NH + h) * DQK + cb * 8;
            CP_ASYNC16(s0 + OKH + r * 400 + cb * 16, khi + src);
            CP_ASYNC16(s0 + OKL + r * 400 + cb * 16, klo + src);
        }
        CP_COMMIT();
    };
    auto load_v = [&](int k0) {
        for (int i = tid; i < 1024; i += 256) {
            int r = i / 16, cb = i % 16;
            size_t src = (size_t)(k0 + r) * HID + h * DV + cb * 8;
            CP_ASYNC16(s0 + OVH + r * 272 + cb * 16, vhi + src);
            CP_ASYNC16(s0 + OVL + r * 272 + cb * 16, vlo + src);
        }
        CP_COMMIT();
    };
    load_k(0);
    load_v(0);

    const float scale = 1.0f / sqrtf(192.0f);
    float m0 = -1e30f, m1 = -1e30f, l0 = 0.f, l1 = 0.f;
    float acc[16][4];
#pragma unroll
    for (int nt = 0; nt < 16; nt++)
#pragma unroll
        for (int e = 0; e < 4; e++) acc[nt][e] = 0.f;

    const int a_r  = (lane & 7) + ((lane >> 3) & 1) * 8;
    const int a_k  = (lane >> 4) * 8;
    const int bk_r = (lane & 7) + (lane >> 4) * 8;
    const int bk_k = ((lane >> 3) & 1) * 8;
    const int prow  = lane >> 2;
    const int pcol2 = (lane & 3) * 2;

    for (int c = 0; c < 32; c++) {
        const int k0 = c * 64;
        CP_WAIT(0);
        __syncthreads();

        // ---- S = Q K^T ----
        float sacc[8][4];
#pragma unroll
        for (int nt = 0; nt < 8; nt++)
#pragma unroll
            for (int e = 0; e < 4; e++) sacc[nt][e] = 0.f;

#pragma unroll
        for (int kt = 0; kt < 12; kt++) {
            uint32_t ah[4], al[4];
            ldmx4(ah[0], ah[1], ah[2], ah[3],
                  s0 + OQH + (wid * 16 + a_r) * 400 + (kt * 16 + a_k) * 2);
            ldmx4(al[0], al[1], al[2], al[3],
                  s0 + OQL + (wid * 16 + a_r) * 400 + (kt * 16 + a_k) * 2);
#pragma unroll
            for (int n2 = 0; n2 < 4; n2++) {
                uint32_t bh[4], bl[4];
                ldmx4(bh[0], bh[1], bh[2], bh[3],
                      s0 + OKH + (n2 * 16 + bk_r) * 400 + (kt * 16 + bk_k) * 2);
                ldmx4(bl[0], bl[1], bl[2], bl[3],
                      s0 + OKL + (n2 * 16 + bk_r) * 400 + (kt * 16 + bk_k) * 2);
                uint32_t bh0[2] = { bh[0], bh[1] }, bh1[2] = { bh[2], bh[3] };
                uint32_t bl0[2] = { bl[0], bl[1] }, bl1[2] = { bl[2], bl[3] };
                mma_bf16(sacc[n2 * 2],     ah, bh0);
                mma_bf16(sacc[n2 * 2 + 1], ah, bh1);
                mma_bf16(sacc[n2 * 2],     al, bh0);
                mma_bf16(sacc[n2 * 2 + 1], al, bh1);
                mma_bf16(sacc[n2 * 2],     ah, bl0);
                mma_bf16(sacc[n2 * 2 + 1], ah, bl1);
            }
        }
        __syncthreads();                 // all warps done reading K
        if (c + 1 < 32) load_k(k0 + 64); // prefetch K(c+1) during softmax+PV

        // ---- softmax (warp-local rows) ----
        const int rg0 = q0 + wid * 16 + prow;
        float sc[8][4];
        float mx0 = -1e30f, mx1 = -1e30f;
#pragma unroll
        for (int nt = 0; nt < 8; nt++) {
            int col = k0 + nt * 8 + pcol2;
            float2 mk0 = *(const float2*)&mask[(size_t)rg0 * S_LEN + col];
            float2 mk1 = *(const float2*)&mask[(size_t)(rg0 + 8) * S_LEN + col];
            sc[nt][0] = sacc[nt][0] * scale + mk0.x;
            sc[nt][1] = sacc[nt][1] * scale + mk0.y;
            sc[nt][2] = sacc[nt][2] * scale + mk1.x;
            sc[nt][3] = sacc[nt][3] * scale + mk1.y;
            mx0 = fmaxf(mx0, fmaxf(sc[nt][0], sc[nt][1]));
            mx1 = fmaxf(mx1, fmaxf(sc[nt][2], sc[nt][3]));
        }
        mx0 = fmaxf(mx0, __shfl_xor_sync(0xffffffffu, mx0, 1));
        mx0 = fmaxf(mx0, __shfl_xor_sync(0xffffffffu, mx0, 2));
        mx1 = fmaxf(mx1, __shfl_xor_sync(0xffffffffu, mx1, 1));
        mx1 = fmaxf(mx1, __shfl_xor_sync(0xffffffffu, mx1, 2));
        float mn0 = fmaxf(m0, mx0), mn1 = fmaxf(m1, mx1);
        float al0 = __expf(m0 - mn0), al1 = __expf(m1 - mn1);
        m0 = mn0; m1 = mn1;

        float ps0 = 0.f, ps1 = 0.f;
#pragma unroll
        for (int nt = 0; nt < 8; nt++) {
            float p00 = __expf(sc[nt][0] - mn0), p01 = __expf(sc[nt][1] - mn0);
            float p10 = __expf(sc[nt][2] - mn1), p11 = __expf(sc[nt][3] - mn1);
            ps0 += p00 + p01; ps1 += p10 + p11;
            int colb = (nt * 8 + pcol2) * 2;
            *(uint32_t*)(smraw + OPH + (wid * 16 + prow) * 144 + colb)     = pack_hi(p00, p01);
            *(uint32_t*)(smraw + OPH + (wid * 16 + prow + 8) * 144 + colb) = pack_hi(p10, p11);
            *(uint32_t*)(smraw + OPL + (wid * 16 + prow) * 144 + colb)     = pack_lo(p00, p01);
            *(uint32_t*)(smraw + OPL + (wid * 16 + prow + 8) * 144 + colb) = pack_lo(p10, p11);
        }
        ps0 += __shfl_xor_sync(0xffffffffu, ps0, 1);
        ps0 += __shfl_xor_sync(0xffffffffu, ps0, 2);
        ps1 += __shfl_xor_sync(0xffffffffu, ps1, 1);
        ps1 += __shfl_xor_sync(0xffffffffu, ps1, 2);
        l0 = al0 * l0 + ps0;
        l1 = al1 * l1 + ps1;
#pragma unroll
        for (int nt = 0; nt < 16; nt++) {
            acc[nt][0] *= al0; acc[nt][1] *= al0;
            acc[nt][2] *= al1; acc[nt][3] *= al1;
        }
        __syncwarp();

        // ---- O += P V ----
#pragma unroll
        for (int kt = 0; kt < 4; kt++) {
            uint32_t ph[4], pl[4];
            ldmx4(ph[0], ph[1], ph[2], ph[3],
                  s0 + OPH + (wid * 16 + a_r) * 144 + (kt * 16 + a_k) * 2);
            ldmx4(pl[0], pl[1], pl[2], pl[3],
                  s0 + OPL + (wid * 16 + a_r) * 144 + (kt * 16 + a_k) * 2);
#pragma unroll
            for (int n2 = 0; n2 < 8; n2++) {
                uint32_t vh[4], vl[4];
                ldmx4t(vh[0], vh[1], vh[2], vh[3],
                       s0 + OVH + (kt * 16 + a_r) * 272 + (n2 * 16 + a_k) * 2);
                ldmx4t(vl[0], vl[1], vl[2], vl[3],
                       s0 + OVL + (kt * 16 + a_r) * 272 + (n2 * 16 + a_k) * 2);
                uint32_t vh0[2] = { vh[0], vh[1] }, vh1[2] = { vh[2], vh[3] };
                uint32_t vl0[2] = { vl[0], vl[1] }, vl1[2] = { vl[2], vl[3] };
                mma_bf16(acc[n2 * 2],     ph, vh0);
                mma_bf16(acc[n2 * 2 + 1], ph, vh1);
                mma_bf16(acc[n2 * 2],     pl, vh0);
                mma_bf16(acc[n2 * 2 + 1], pl, vh1);
                mma_bf16(acc[n2 * 2],     ph, vl0);
                mma_bf16(acc[n2 * 2 + 1], ph, vl1);
            }
        }
        __syncthreads();                 // all warps done reading V
        if (c + 1 < 32) load_v(k0 + 64); // prefetch V(c+1)
    }

    const float i0 = 1.f / l0, i1 = 1.f / l1;
    const int orow = q0 + wid * 16 + prow;
#pragma unroll
    for (int nt = 0; nt < 16; nt++) {
        int col = h * DV + nt * 8 + pcol2;
        float v0 = acc[nt][0] * i0, v1 = acc[nt][1] * i0;
        float v2 = acc[nt][2] * i1, v3 = acc[nt][3] * i1;
        *(uint32_t*)&aoh[(size_t)orow * HID + col]       = pack_hi(v0, v1);
        *(uint32_t*)&aoh[(size_t)(orow + 8) * HID + col] = pack_hi(v2, v3);
        *(uint32_t*)&aol[(size_t)orow * HID + col]       = pack_lo(v0, v1);
        *(uint32_t*)&aol[(size_t)(orow + 8) * HID + col] = pack_lo(v2, v3);
    }
}

// ---------------------------------------------------------------------------
// launcher
// ---------------------------------------------------------------------------
static void split(const float* x, __nv_bfloat16* hi, __nv_bfloat16* lo, int n) {
    int n4 = n / 4;
    split_bf16_kernel<<<(n4 + 255) / 256, 256>>>(x, hi, lo, n4);
}

extern "C" void kernel_launch(void* const* d_in, const int* in_sizes, int n_in,
                              void* d_out, int out_size) {
    const float* hidden  = (const float*)d_in[0];
    const float* mask    = (const float*)d_in[1];
    const float* Wq_lr   = (const float*)d_in[2];
    const float* bq_lr   = (const float*)d_in[3];
    const float* Wq_rope = (const float*)d_in[4];
    const float* bq_rope = (const float*)d_in[5];
    const float* Wq_c    = (const float*)d_in[6];
    const float* bq_c    = (const float*)d_in[7];
    const float* Wkv     = (const float*)d_in[8];
    const float* bkv     = (const float*)d_in[9];
    const float* Wk_rope = (const float*)d_in[10];
    const float* bk_rope = (const float*)d_in[11];
    const float* Wk_c    = (const float*)d_in[12];
    const float* bk_c    = (const float*)d_in[13];
    const float* Wv      = (const float*)d_in[14];
    const float* bv      = (const float*)d_in[15];
    const float* Wo      = (const float*)d_in[16];
    const float* bo      = (const float*)d_in[17];
    float* out = (float*)d_out;

    float *qc, *qr, *kc, *kr, *bkr;
    cudaGetSymbolAddress((void**)&qc,  g_qc);
    cudaGetSymbolAddress((void**)&qr,  g_qr);
    cudaGetSymbolAddress((void**)&kc,  g_kc);
    cudaGetSymbolAddress((void**)&kr,  g_kr);
    cudaGetSymbolAddress((void**)&bkr, g_bkr);

    __nv_bfloat16 *h_hi, *h_lo, *cq_hi, *cq_lo, *ckv_hi, *ckv_lo, *ao_hi, *ao_lo;
    __nv_bfloat16 *Wqlr_hi, *Wqlr_lo, *Wqc_hi, *Wqc_lo, *Wqr_hi, *Wqr_lo;
    __nv_bfloat16 *Wkv_hi, *Wkv_lo, *Wkc_hi, *Wkc_lo, *Wv_hi, *Wv_lo, *Wo_hi, *Wo_lo;
    __nv_bfloat16 *Wkr_hi, *Wkr_lo, *qhi, *qlo, *khi, *klo, *vhi, *vlo;
    cudaGetSymbolAddress((void**)&h_hi,   g_h_hi);   cudaGetSymbolAddress((void**)&h_lo,   g_h_lo);
    cudaGetSymbolAddress((void**)&cq_hi,  g_cq_hi);  cudaGetSymbolAddress((void**)&cq_lo,  g_cq_lo);
    cudaGetSymbolAddress((void**)&ckv_hi, g_ckv_hi); cudaGetSymbolAddress((void**)&ckv_lo, g_ckv_lo);
    cudaGetSymbolAddress((void**)&ao_hi,  g_ao_hi);  cudaGetSymbolAddress((void**)&ao_lo,  g_ao_lo);
    cudaGetSymbolAddress((void**)&Wqlr_hi, g_Wqlr_hi); cudaGetSymbolAddress((void**)&Wqlr_lo, g_Wqlr_lo);
    cudaGetSymbolAddress((void**)&Wqc_hi,  g_Wqc_hi);  cudaGetSymbolAddress((void**)&Wqc_lo,  g_Wqc_lo);
    cudaGetSymbolAddress((void**)&Wqr_hi,  g_Wqr_hi);  cudaGetSymbolAddress((void**)&Wqr_lo,  g_Wqr_lo);
    cudaGetSymbolAddress((void**)&Wkv_hi,  g_Wkv_hi);  cudaGetSymbolAddress((void**)&Wkv_lo,  g_Wkv_lo);
    cudaGetSymbolAddress((void**)&Wkc_hi,  g_Wkc_hi);  cudaGetSymbolAddress((void**)&Wkc_lo,  g_Wkc_lo);
    cudaGetSymbolAddress((void**)&Wv_hi,   g_Wv_hi);   cudaGetSymbolAddress((void**)&Wv_lo,   g_Wv_lo);
    cudaGetSymbolAddress((void**)&Wo_hi,   g_Wo_hi);   cudaGetSymbolAddress((void**)&Wo_lo,   g_Wo_lo);
    cudaGetSymbolAddress((void**)&Wkr_hi,  g_Wkr_hi);  cudaGetSymbolAddress((void**)&Wkr_lo,  g_Wkr_lo);
    cudaGetSymbolAddress((void**)&qhi, g_qhi); cudaGetSymbolAddress((void**)&qlo, g_qlo);
    cudaGetSymbolAddress((void**)&khi, g_khi); cudaGetSymbolAddress((void**)&klo, g_klo);
    cudaGetSymbolAddress((void**)&vhi, g_vhi); cudaGetSymbolAddress((void**)&vlo, g_vlo);

    const int M = 2048;
    cudaFuncSetAttribute(mma_gemm2, cudaFuncAttributeMaxDynamicSharedMemorySize, G_SMEM);

    split(hidden,  h_hi,    h_lo,    2048 * 4096);
    split(Wq_lr,   Wqlr_hi, Wqlr_lo, 1536 * 4096);
    split(Wq_c,    Wqc_hi,  Wqc_lo,  4096 * 1536);
    split(Wq_rope, Wqr_hi,  Wqr_lo,  2048 * 1536);
    split(Wkv,     Wkv_hi,  Wkv_lo,  512 * 4096);
    split(Wk_c,    Wkc_hi,  Wkc_lo,  4096 * 512);
    split(Wv,      Wv_hi,   Wv_lo,   4096 * 512);
    split(Wo,      Wo_hi,   Wo_lo,   4096 * 4096);
    pad_krope_kernel<<<(128 * 4096 + 255) / 256, 256>>>(Wk_rope, Wkr_hi, Wkr_lo, bk_rope, bkr);

    // c_q (bf16 out only)
    mma_gemm2<<<dim3(1536 / 128, M / 128), 256, G_SMEM>>>(
        h_hi, h_lo, Wqlr_hi, Wqlr_lo, bq_lr, nullptr, cq_hi, cq_lo, M, 1536, 4096);
    // q_content (float out)
    mma_gemm2<<<dim3(4096 / 128, M / 128), 256, G_SMEM>>>(
        cq_hi, cq_lo, Wqc_hi, Wqc_lo, bq_c, qc, nullptr, nullptr, M, 4096, 1536);
    // q_rope (float out)
    mma_gemm2<<<dim3(2048 / 128, M / 128), 256, G_SMEM>>>(
        cq_hi, cq_lo, Wqr_hi, Wqr_lo, bq_rope, qr, nullptr, nullptr, M, 2048, 1536);
    // c_kv (bf16 out only)
    mma_gemm2<<<dim3(512 / 128, M / 128), 256, G_SMEM>>>(
        h_hi, h_lo, Wkv_hi, Wkv_lo, bkv, nullptr, ckv_hi, ckv_lo, M, 512, 4096);
    // k_content (float out)
    mma_gemm2<<<dim3(4096 / 128, M / 128), 256, G_SMEM>>>(
        ckv_hi, ckv_lo, Wkc_hi, Wkc_lo, bk_c, kc, nullptr, nullptr, M, 4096, 512);
    // v (bf16 out only)
    mma_gemm2<<<dim3(4096 / 128, M / 128), 256, G_SMEM>>>(
        ckv_hi, ckv_lo, Wv_hi, Wv_lo, bv, nullptr, vhi, vlo, M, 4096, 512);
    // k_rope padded to N=128 (float out)
    mma_gemm2<<<dim3(1, M / 128), 256, G_SMEM>>>(
        h_hi, h_lo, Wkr_hi, Wkr_lo, bkr, kr, nullptr, nullptr, M, 128, 4096);

    rope_kernel<<<(2048 * 1024 + 255) / 256, 256>>>(qr, 2048, 2048, 2048);
    rope_kernel<<<(2048 * 32 + 255) / 256, 256>>>(kr, 2048, 64, 128);

    fuse_q_kernel<<<8192, 256>>>(qc, qr, qhi, qlo);
    fuse_k_kernel<<<8192, 256>>>(kc, kr, khi, klo);

    cudaFuncSetAttribute(attn_mma_kernel, cudaFuncAttributeMaxDynamicSharedMemorySize, ATT_SMEM);
    attn_mma_kernel<<<dim3(S_LEN / 128, NH), 256, ATT_SMEM>>>(
        qhi, qlo, khi, klo, vhi, vlo, mask, ao_hi, ao_lo);

    // out = ao @ Wo^T (float out)
    mma_gemm2<<<dim3(4096 / 128, M / 128), 256, G_SMEM>>>(
        ao_hi, ao_lo, Wo_hi, Wo_lo, bo, out, nullptr, nullptr, M, 4096, 4096);
}

// round 6
// speedup vs baseline: 4.2253x; 1.0989x over previous
#include <cuda_runtime.h>
#include <cuda_bf16.h>
#include <math.h>
#include <stdint.h>

#define S_LEN 2048
#define HID   4096
#define NH    32
#define DQK   192
#define DV    128

// ---------------------------------------------------------------------------
// scratch (device globals; no allocations allowed)
// ---------------------------------------------------------------------------
__device__ float g_qc [2048*4096];
__device__ float g_qr [2048*2048];
__device__ float g_kc [2048*4096];
__device__ float g_kr [2048*128];        // padded N=128
__device__ float g_bkr[128];             // padded bias

// bf16 hi/lo splits
__device__ __align__(16) __nv_bfloat16 g_h_hi [2048*4096], g_h_lo [2048*4096];
__device__ __align__(16) __nv_bfloat16 g_cq_hi[2048*1536], g_cq_lo[2048*1536];
__device__ __align__(16) __nv_bfloat16 g_ckv_hi[2048*512], g_ckv_lo[2048*512];
__device__ __align__(16) __nv_bfloat16 g_ao_hi[2048*4096], g_ao_lo[2048*4096];
__device__ __align__(16) __nv_bfloat16 g_Wqlr_hi[1536*4096], g_Wqlr_lo[1536*4096];
__device__ __align__(16) __nv_bfloat16 g_Wqc_hi [4096*1536], g_Wqc_lo [4096*1536];
__device__ __align__(16) __nv_bfloat16 g_Wqr_hi [2048*1536], g_Wqr_lo [2048*1536];
__device__ __align__(16) __nv_bfloat16 g_Wkv_hi [512*4096],  g_Wkv_lo [512*4096];
__device__ __align__(16) __nv_bfloat16 g_Wkc_hi [4096*512],  g_Wkc_lo [4096*512];
__device__ __align__(16) __nv_bfloat16 g_Wv_hi  [4096*512],  g_Wv_lo  [4096*512];
__device__ __align__(16) __nv_bfloat16 g_Wo_hi  [4096*4096], g_Wo_lo  [4096*4096];
__device__ __align__(16) __nv_bfloat16 g_Wkr_hi [128*4096],  g_Wkr_lo [128*4096];

// attention operands in bf16 hi/lo
__device__ __align__(16) __nv_bfloat16 g_qhi[2048*32*192], g_qlo[2048*32*192];
__device__ __align__(16) __nv_bfloat16 g_khi[2048*32*192], g_klo[2048*32*192];
__device__ __align__(16) __nv_bfloat16 g_vhi[2048*4096],   g_vlo[2048*4096];

// ---------------------------------------------------------------------------
// small PTX helpers
// ---------------------------------------------------------------------------
__device__ __forceinline__ uint32_t smem_u32(const void* p) {
    uint32_t a;
    asm("{ .reg .u64 t; cvta.to.shared.u64 t, %1; cvt.u32.u64 %0, t; }" : "=r"(a) : "l"(p));
    return a;
}
#define CP_ASYNC16(dst_u32, src_ptr) \
    asm volatile("cp.async.cg.shared.global [%0], [%1], 16;" \
                 :: "r"(dst_u32), "l"(__cvta_generic_to_global(src_ptr)) : "memory")
#define CP_COMMIT() asm volatile("cp.async.commit_group;" ::: "memory")
#define CP_WAIT(n)  asm volatile("cp.async.wait_group %0;" :: "n"(n) : "memory")

__device__ __forceinline__ void ldmx4(uint32_t& r0, uint32_t& r1, uint32_t& r2, uint32_t& r3,
                                      uint32_t addr) {
    asm volatile("ldmatrix.sync.aligned.m8n8.x4.shared.b16 {%0,%1,%2,%3}, [%4];"
                 : "=r"(r0), "=r"(r1), "=r"(r2), "=r"(r3) : "r"(addr));
}
__device__ __forceinline__ void ldmx4t(uint32_t& r0, uint32_t& r1, uint32_t& r2, uint32_t& r3,
                                       uint32_t addr) {
    asm volatile("ldmatrix.sync.aligned.m8n8.x4.trans.shared.b16 {%0,%1,%2,%3}, [%4];"
                 : "=r"(r0), "=r"(r1), "=r"(r2), "=r"(r3) : "r"(addr));
}
__device__ __forceinline__ void mma_bf16(float* d, const uint32_t* a, const uint32_t* b) {
    asm volatile("mma.sync.aligned.m16n8k16.row.col.f32.bf16.bf16.f32 "
                 "{%0,%1,%2,%3}, {%4,%5,%6,%7}, {%8,%9}, {%0,%1,%2,%3};"
                 : "+f"(d[0]), "+f"(d[1]), "+f"(d[2]), "+f"(d[3])
                 : "r"(a[0]), "r"(a[1]), "r"(a[2]), "r"(a[3]), "r"(b[0]), "r"(b[1]));
}
__device__ __forceinline__ uint32_t pack_hi(float a, float b) {
    __nv_bfloat16 ha = __float2bfloat16(a), hb = __float2bfloat16(b);
    return (uint32_t)__bfloat16_as_ushort(ha) | ((uint32_t)__bfloat16_as_ushort(hb) << 16);
}
__device__ __forceinline__ uint32_t pack_lo(float a, float b) {
    __nv_bfloat16 ha = __float2bfloat16(a), hb = __float2bfloat16(b);
    __nv_bfloat16 la = __float2bfloat16(a - __bfloat162float(ha));
    __nv_bfloat16 lb = __float2bfloat16(b - __bfloat162float(hb));
    return (uint32_t)__bfloat16_as_ushort(la) | ((uint32_t)__bfloat16_as_ushort(lb) << 16);
}

// ---------------------------------------------------------------------------
// mega split: all fp32 -> bf16(hi,lo) splits in ONE launch
// ---------------------------------------------------------------------------
struct SJob { const float* x; __nv_bfloat16* hi; __nv_bfloat16* lo; int n4; int blk0; };
struct SJobs { SJob j[8]; };

__global__ void multi_split_kernel(SJobs jobs) {
    int b = blockIdx.x;
    int ji = 0;
#pragma unroll
    for (int t = 1; t < 8; t++)
        if (b >= jobs.j[t].blk0) ji = t;
    const SJob jb = jobs.j[ji];
    int i = (b - jb.blk0) * 256 + threadIdx.x;
    if (i >= jb.n4) return;
    float4 v = ((const float4*)jb.x)[i];
    ((uint32_t*)jb.hi)[i*2 + 0] = pack_hi(v.x, v.y);
    ((uint32_t*)jb.hi)[i*2 + 1] = pack_hi(v.z, v.w);
    ((uint32_t*)jb.lo)[i*2 + 0] = pack_lo(v.x, v.y);
    ((uint32_t*)jb.lo)[i*2 + 1] = pack_lo(v.z, v.w);
}

// padded k_rope weight split: [64,4096] -> [128,4096] (rows 64..127 zero)
__global__ void pad_krope_kernel(const float* __restrict__ W,
                                 __nv_bfloat16* __restrict__ hi,
                                 __nv_bfloat16* __restrict__ lo,
                                 const float* __restrict__ b,
                                 float* __restrict__ bp) {
    int i = blockIdx.x * blockDim.x + threadIdx.x;
    if (i < 128) bp[i] = (i < 64) ? b[i] : 0.f;
    if (i >= 128 * 4096) return;
    int r = i >> 12;
    float v = (r < 64) ? W[(size_t)r * 4096 + (i & 4095)] : 0.f;
    __nv_bfloat16 h = __float2bfloat16(v);
    hi[i] = h;
    lo[i] = __float2bfloat16(v - __bfloat162float(h));
}

// ---------------------------------------------------------------------------
// warp-MMA bf16 GEMM, fp32 emulation, combined hi/lo per K-chunk.
// CTA 128x128, 4 warps (2x2), warp tile 64x64, BK=32, 2-stage cp.async.
// ---------------------------------------------------------------------------
#define ROWB 80
#define OA_HI 0
#define OA_LO 10240
#define OW_HI 20480
#define OW_LO 30720
#define G_BUF 40960
#define G_SMEM (2 * G_BUF)

__global__ void __launch_bounds__(128)
mma_gemm3(const __nv_bfloat16* __restrict__ Ahi, const __nv_bfloat16* __restrict__ Alo,
          const __nv_bfloat16* __restrict__ Whi, const __nv_bfloat16* __restrict__ Wlo,
          const float* __restrict__ bias,
          float* __restrict__ Cf,
          __nv_bfloat16* __restrict__ Chi, __nv_bfloat16* __restrict__ Clo,
          int M, int N, int K) {
    extern __shared__ char gsm[];
    const uint32_t s0 = smem_u32(gsm);
    const int tid = threadIdx.x, wid = tid >> 5, lane = tid & 31;
    const int warp_m = wid >> 1, warp_n = wid & 1;   // 2x2 warp grid, 64x64 tiles
    const int row0 = blockIdx.y * 128, col0 = blockIdx.x * 128;

    const int a_row = (lane & 7) + ((lane >> 3) & 1) * 8;
    const int a_kof = (lane >> 4) * 8;
    const int b_row = (lane & 7) + (lane >> 4) * 8;
    const int b_kof = ((lane >> 3) & 1) * 8;

    const int kc = K >> 5;

    float acc[4][8][4];
#pragma unroll
    for (int mt = 0; mt < 4; mt++)
#pragma unroll
        for (int nt = 0; nt < 8; nt++)
#pragma unroll
            for (int e = 0; e < 4; e++) acc[mt][nt][e] = 0.f;

    auto load_chunk = [&](int c, int buf) {
        const int kk = c << 5;
        const uint32_t base = s0 + buf * G_BUF;
#pragma unroll
        for (int i = 0; i < 4; i++) {
            int idx = tid + i * 128;
            int r = idx >> 2, cb = idx & 3;
            size_t src = (size_t)(row0 + r) * K + kk + cb * 8;
            CP_ASYNC16(base + OA_HI + r * ROWB + cb * 16, Ahi + src);
            CP_ASYNC16(base + OA_LO + r * ROWB + cb * 16, Alo + src);
        }
#pragma unroll
        for (int i = 0; i < 4; i++) {
            int idx = tid + i * 128;
            int r = idx >> 2, cb = idx & 3;
            size_t src = (size_t)(col0 + r) * K + kk + cb * 8;
            CP_ASYNC16(base + OW_HI + r * ROWB + cb * 16, Whi + src);
            CP_ASYNC16(base + OW_LO + r * ROWB + cb * 16, Wlo + src);
        }
        CP_COMMIT();
    };

    load_chunk(0, 0);

    for (int c = 0; c < kc; c++) {
        const int buf = c & 1;
        if (c + 1 < kc) {
            load_chunk(c + 1, buf ^ 1);
            CP_WAIT(1);
        } else {
            CP_WAIT(0);
        }
        __syncthreads();
        const uint32_t base = s0 + buf * G_BUF;

#pragma unroll
        for (int ks = 0; ks < 2; ks++) {
            const int kb = ks * 16;
            uint32_t ah[4][4], al[4][4];
#pragma unroll
            for (int mt = 0; mt < 4; mt++) {
                uint32_t ra = (warp_m * 64 + mt * 16 + a_row) * ROWB + (kb + a_kof) * 2;
                ldmx4(ah[mt][0], ah[mt][1], ah[mt][2], ah[mt][3], base + OA_HI + ra);
                ldmx4(al[mt][0], al[mt][1], al[mt][2], al[mt][3], base + OA_LO + ra);
            }
#pragma unroll
            for (int np = 0; np < 4; np++) {
                uint32_t bh[4], bl[4];
                uint32_t rb = (warp_n * 64 + np * 16 + b_row) * ROWB + (kb + b_kof) * 2;
                ldmx4(bh[0], bh[1], bh[2], bh[3], base + OW_HI + rb);
                ldmx4(bl[0], bl[1], bl[2], bl[3], base + OW_LO + rb);
#pragma unroll
                for (int j = 0; j < 2; j++) {
                    uint32_t b2h[2] = { bh[j * 2], bh[j * 2 + 1] };
                    uint32_t b2l[2] = { bl[j * 2], bl[j * 2 + 1] };
                    const int nt = np * 2 + j;
#pragma unroll
                    for (int mt = 0; mt < 4; mt++) {
                        mma_bf16(acc[mt][nt], ah[mt], b2h);
                        mma_bf16(acc[mt][nt], al[mt], b2h);
                        mma_bf16(acc[mt][nt], ah[mt], b2l);
                    }
                }
            }
        }
        __syncthreads();
    }

    const int rbase = row0 + warp_m * 64 + (lane >> 2);
    const int cbase = col0 + warp_n * 64 + (lane & 3) * 2;
#pragma unroll
    for (int mt = 0; mt < 4; mt++) {
#pragma unroll
        for (int nt = 0; nt < 8; nt++) {
            const int cc = cbase + nt * 8;
            const float b0 = bias[cc], b1 = bias[cc + 1];
            const int r0 = rbase + mt * 16;
            float v0 = acc[mt][nt][0] + b0, v1 = acc[mt][nt][1] + b1;
            float v2 = acc[mt][nt][2] + b0, v3 = acc[mt][nt][3] + b1;
            if (Cf) {
                *(float2*)&Cf[(size_t)r0 * N + cc] = make_float2(v0, v1);
                *(float2*)&Cf[(size_t)(r0 + 8) * N + cc] = make_float2(v2, v3);
            }
            if (Chi) {
                *(uint32_t*)&Chi[(size_t)r0 * N + cc]       = pack_hi(v0, v1);
                *(uint32_t*)&Chi[(size_t)(r0 + 8) * N + cc] = pack_hi(v2, v3);
                *(uint32_t*)&Clo[(size_t)r0 * N + cc]       = pack_lo(v0, v1);
                *(uint32_t*)&Clo[(size_t)(r0 + 8) * N + cc] = pack_lo(v2, v3);
            }
        }
    }
}

// ---------------- rotate-half RoPE, in place, x: [S, D], row stride ----------
__global__ void rope_kernel(float* __restrict__ x, int S, int D, int stride) {
    const int half = D / 2;
    const int idx = blockIdx.x * blockDim.x + threadIdx.x;
    if (idx >= S * half) return;
    const int s = idx / half, j = idx % half;
    float ex  = (float)(2 * j) / (float)D;
    float inv = 1.0f / powf(10000.0f, ex);
    float ang = (float)s * inv;
    float sn, c;
    sincosf(ang, &sn, &c);
    float x1 = x[(size_t)s * stride + j];
    float x2 = x[(size_t)s * stride + half + j];
    x[(size_t)s * stride + j]        = x1 * c - x2 * sn;
    x[(size_t)s * stride + half + j] = x2 * c + x1 * sn;
}

// ---------------- concat + RMSnorm over 192 -> bf16 hi/lo --------------------
__global__ void fuse_q_kernel(const float* __restrict__ qc,
                              const float* __restrict__ qr,
                              __nv_bfloat16* __restrict__ qh,
                              __nv_bfloat16* __restrict__ ql) {
    const int gw   = (blockIdx.x * blockDim.x + threadIdx.x) >> 5;
    const int lane = threadIdx.x & 31;
    const int s = gw >> 5, h = gw & 31;
    float vals[6]; float ss = 0.f;
#pragma unroll
    for (int t = 0; t < 6; t++) {
        int d = lane + 32 * t;
        float x = (d < 128) ? qc[(size_t)s * HID + h * 128 + d]
                            : qr[(size_t)s * 2048 + h * 64 + (d - 128)];
        vals[t] = x; ss += x * x;
    }
#pragma unroll
    for (int o = 16; o; o >>= 1) ss += __shfl_xor_sync(0xffffffffu, ss, o);
    float r = rsqrtf(ss * (1.f / 192.f) + 1.1920929e-7f);
#pragma unroll
    for (int t = 0; t < 6; t++) {
        float x = vals[t] * r;
        __nv_bfloat16 hb = __float2bfloat16(x);
        size_t o_ = ((size_t)s * NH + h) * DQK + lane + 32 * t;
        qh[o_] = hb;
        ql[o_] = __float2bfloat16(x - __bfloat162float(hb));
    }
}

__global__ void fuse_k_kernel(const float* __restrict__ kc,
                              const float* __restrict__ kr,
                              __nv_bfloat16* __restrict__ kh,
                              __nv_bfloat16* __restrict__ kl) {
    const int gw   = (blockIdx.x * blockDim.x + threadIdx.x) >> 5;
    const int lane = threadIdx.x & 31;
    const int s = gw >> 5, h = gw & 31;
    float vals[6]; float ss = 0.f;
#pragma unroll
    for (int t = 0; t < 6; t++) {
        int d = lane + 32 * t;
        float x = (d < 128) ? kc[(size_t)s * HID + h * 128 + d]
                            : kr[(size_t)s * 128 + (d - 128)];   // padded stride 128
        vals[t] = x; ss += x * x;
    }
#pragma unroll
    for (int o = 16; o; o >>= 1) ss += __shfl_xor_sync(0xffffffffu, ss, o);
    float r = rsqrtf(ss * (1.f / 192.f) + 1.1920929e-7f);
#pragma unroll
    for (int t = 0; t < 6; t++) {
        float x = vals[t] * r;
        __nv_bfloat16 hb = __float2bfloat16(x);
        size_t o_ = ((size_t)s * NH + h) * DQK + lane + 32 * t;
        kh[o_] = hb;
        kl[o_] = __float2bfloat16(x - __bfloat162float(hb));
    }
}

// ---------------------------------------------------------------------------
// flash attention with mma.sync (bf16 hi/lo emulation) + K/V prefetch overlap
// ---------------------------------------------------------------------------
#define OQH 0
#define OQL (OQH + 128*400)
#define OKH (OQL + 128*400)
#define OKL (OKH + 64*400)
#define OVH (OKL + 64*400)
#define OVL (OVH + 64*272)
#define OPH (OVL + 64*272)
#define OPL (OPH + 128*144)
#define ATT_SMEM (OPL + 128*144)

__global__ void __launch_bounds__(256, 1)
attn_mma_kernel(const __nv_bfloat16* __restrict__ qhi, const __nv_bfloat16* __restrict__ qlo,
                const __nv_bfloat16* __restrict__ khi, const __nv_bfloat16* __restrict__ klo,
                const __nv_bfloat16* __restrict__ vhi, const __nv_bfloat16* __restrict__ vlo,
                const float* __restrict__ mask,
                __nv_bfloat16* __restrict__ aoh, __nv_bfloat16* __restrict__ aol) {
    extern __shared__ char smraw[];
    const uint32_t s0 = smem_u32(smraw);
    const int h = blockIdx.y, q0 = blockIdx.x * 128;
    const int tid = threadIdx.x, wid = tid >> 5, lane = tid & 31;

    for (int i = tid; i < 3072; i += 256) {
        int r = i / 24, cb = i % 24;
        size_t src = ((size_t)(q0 + r) * NH + h) * DQK + cb * 8;
        CP_ASYNC16(s0 + OQH + r * 400 + cb * 16, qhi + src);
        CP_ASYNC16(s0 + OQL + r * 400 + cb * 16, qlo + src);
    }
    CP_COMMIT();

    auto load_k = [&](int k0) {
        for (int i = tid; i < 1536; i += 256) {
            int r = i / 24, cb = i % 24;
            size_t src = ((size_t)(k0 + r) * NH + h) * DQK + cb * 8;
            CP_ASYNC16(s0 + OKH + r * 400 + cb * 16, khi + src);
            CP_ASYNC16(s0 + OKL + r * 400 + cb * 16, klo + src);
        }
        CP_COMMIT();
    };
    auto load_v = [&](int k0) {
        for (int i = tid; i < 1024; i += 256) {
            int r = i / 16, cb = i % 16;
            size_t src = (size_t)(k0 + r) * HID + h * DV + cb * 8;
            CP_ASYNC16(s0 + OVH + r * 272 + cb * 16, vhi + src);
            CP_ASYNC16(s0 + OVL + r * 272 + cb * 16, vlo + src);
        }
        CP_COMMIT();
    };
    load_k(0);
    load_v(0);

    const float scale = 1.0f / sqrtf(192.0f);
    float m0 = -1e30f, m1 = -1e30f, l0 = 0.f, l1 = 0.f;
    float acc[16][4];
#pragma unroll
    for (int nt = 0; nt < 16; nt++)
#pragma unroll
        for (int e = 0; e < 4; e++) acc[nt][e] = 0.f;

    const int a_r  = (lane & 7) + ((lane >> 3) & 1) * 8;
    const int a_k  = (lane >> 4) * 8;
    const int bk_r = (lane & 7) + (lane >> 4) * 8;
    const int bk_k = ((lane >> 3) & 1) * 8;
    const int prow  = lane >> 2;
    const int pcol2 = (lane & 3) * 2;

    for (int c = 0; c < 32; c++) {
        const int k0 = c * 64;
        CP_WAIT(0);
        __syncthreads();

        // ---- S = Q K^T ----
        float sacc[8][4];
#pragma unroll
        for (int nt = 0; nt < 8; nt++)
#pragma unroll
            for (int e = 0; e < 4; e++) sacc[nt][e] = 0.f;

#pragma unroll
        for (int kt = 0; kt < 12; kt++) {
            uint32_t ah[4], al[4];
            ldmx4(ah[0], ah[1], ah[2], ah[3],
                  s0 + OQH + (wid * 16 + a_r) * 400 + (kt * 16 + a_k) * 2);
            ldmx4(al[0], al[1], al[2], al[3],
                  s0 + OQL + (wid * 16 + a_r) * 400 + (kt * 16 + a_k) * 2);
#pragma unroll
            for (int n2 = 0; n2 < 4; n2++) {
                uint32_t bh[4], bl[4];
                ldmx4(bh[0], bh[1], bh[2], bh[3],
                      s0 + OKH + (n2 * 16 + bk_r) * 400 + (kt * 16 + bk_k) * 2);
                ldmx4(bl[0], bl[1], bl[2], bl[3],
                      s0 + OKL + (n2 * 16 + bk_r) * 400 + (kt * 16 + bk_k) * 2);
                uint32_t bh0[2] = { bh[0], bh[1] }, bh1[2] = { bh[2], bh[3] };
                uint32_t bl0[2] = { bl[0], bl[1] }, bl1[2] = { bl[2], bl[3] };
                mma_bf16(sacc[n2 * 2],     ah, bh0);
                mma_bf16(sacc[n2 * 2 + 1], ah, bh1);
                mma_bf16(sacc[n2 * 2],     al, bh0);
                mma_bf16(sacc[n2 * 2 + 1], al, bh1);
                mma_bf16(sacc[n2 * 2],     ah, bl0);
                mma_bf16(sacc[n2 * 2 + 1], ah, bl1);
            }
        }
        __syncthreads();
        if (c + 1 < 32) load_k(k0 + 64);

        // ---- softmax (warp-local rows) ----
        const int rg0 = q0 + wid * 16 + prow;
        float sc[8][4];
        float mx0 = -1e30f, mx1 = -1e30f;
#pragma unroll
        for (int nt = 0; nt < 8; nt++) {
            int col = k0 + nt * 8 + pcol2;
            float2 mk0 = *(const float2*)&mask[(size_t)rg0 * S_LEN + col];
            float2 mk1 = *(const float2*)&mask[(size_t)(rg0 + 8) * S_LEN + col];
            sc[nt][0] = sacc[nt][0] * scale + mk0.x;
            sc[nt][1] = sacc[nt][1] * scale + mk0.y;
            sc[nt][2] = sacc[nt][2] * scale + mk1.x;
            sc[nt][3] = sacc[nt][3] * scale + mk1.y;
            mx0 = fmaxf(mx0, fmaxf(sc[nt][0], sc[nt][1]));
            mx1 = fmaxf(mx1, fmaxf(sc[nt][2], sc[nt][3]));
        }
        mx0 = fmaxf(mx0, __shfl_xor_sync(0xffffffffu, mx0, 1));
        mx0 = fmaxf(mx0, __shfl_xor_sync(0xffffffffu, mx0, 2));
        mx1 = fmaxf(mx1, __shfl_xor_sync(0xffffffffu, mx1, 1));
        mx1 = fmaxf(mx1, __shfl_xor_sync(0xffffffffu, mx1, 2));
        float mn0 = fmaxf(m0, mx0), mn1 = fmaxf(m1, mx1);
        float al0 = __expf(m0 - mn0), al1 = __expf(m1 - mn1);
        m0 = mn0; m1 = mn1;

        float ps0 = 0.f, ps1 = 0.f;
#pragma unroll
        for (int nt = 0; nt < 8; nt++) {
            float p00 = __expf(sc[nt][0] - mn0), p01 = __expf(sc[nt][1] - mn0);
            float p10 = __expf(sc[nt][2] - mn1), p11 = __expf(sc[nt][3] - mn1);
            ps0 += p00 + p01; ps1 += p10 + p11;
            int colb = (nt * 8 + pcol2) * 2;
            *(uint32_t*)(smraw + OPH + (wid * 16 + prow) * 144 + colb)     = pack_hi(p00, p01);
            *(uint32_t*)(smraw + OPH + (wid * 16 + prow + 8) * 144 + colb) = pack_hi(p10, p11);
            *(uint32_t*)(smraw + OPL + (wid * 16 + prow) * 144 + colb)     = pack_lo(p00, p01);
            *(uint32_t*)(smraw + OPL + (wid * 16 + prow + 8) * 144 + colb) = pack_lo(p10, p11);
        }
        ps0 += __shfl_xor_sync(0xffffffffu, ps0, 1);
        ps0 += __shfl_xor_sync(0xffffffffu, ps0, 2);
        ps1 += __shfl_xor_sync(0xffffffffu, ps1, 1);
        ps1 += __shfl_xor_sync(0xffffffffu, ps1, 2);
        l0 = al0 * l0 + ps0;
        l1 = al1 * l1 + ps1;
#pragma unroll
        for (int nt = 0; nt < 16; nt++) {
            acc[nt][0] *= al0; acc[nt][1] *= al0;
            acc[nt][2] *= al1; acc[nt][3] *= al1;
        }
        __syncwarp();

        // ---- O += P V ----
#pragma unroll
        for (int kt = 0; kt < 4; kt++) {
            uint32_t ph[4], pl[4];
            ldmx4(ph[0], ph[1], ph[2], ph[3],
                  s0 + OPH + (wid * 16 + a_r) * 144 + (kt * 16 + a_k) * 2);
            ldmx4(pl[0], pl[1], pl[2], pl[3],
                  s0 + OPL + (wid * 16 + a_r) * 144 + (kt * 16 + a_k) * 2);
#pragma unroll
            for (int n2 = 0; n2 < 8; n2++) {
                uint32_t vh[4], vl[4];
                ldmx4t(vh[0], vh[1], vh[2], vh[3],
                       s0 + OVH + (kt * 16 + a_r) * 272 + (n2 * 16 + a_k) * 2);
                ldmx4t(vl[0], vl[1], vl[2], vl[3],
                       s0 + OVL + (kt * 16 + a_r) * 272 + (n2 * 16 + a_k) * 2);
                uint32_t vh0[2] = { vh[0], vh[1] }, vh1[2] = { vh[2], vh[3] };
                uint32_t vl0[2] = { vl[0], vl[1] }, vl1[2] = { vl[2], vl[3] };
                mma_bf16(acc[n2 * 2],     ph, vh0);
                mma_bf16(acc[n2 * 2 + 1], ph, vh1);
                mma_bf16(acc[n2 * 2],     pl, vh0);
                mma_bf16(acc[n2 * 2 + 1], pl, vh1);
                mma_bf16(acc[n2 * 2],     ph, vl0);
                mma_bf16(acc[n2 * 2 + 1], ph, vl1);
            }
        }
        __syncthreads();
        if (c + 1 < 32) load_v(k0 + 64);
    }

    const float i0 = 1.f / l0, i1 = 1.f / l1;
    const int orow = q0 + wid * 16 + prow;
#pragma unroll
    for (int nt = 0; nt < 16; nt++) {
        int col = h * DV + nt * 8 + pcol2;
        float v0 = acc[nt][0] * i0, v1 = acc[nt][1] * i0;
        float v2 = acc[nt][2] * i1, v3 = acc[nt][3] * i1;
        *(uint32_t*)&aoh[(size_t)orow * HID + col]       = pack_hi(v0, v1);
        *(uint32_t*)&aoh[(size_t)(orow + 8) * HID + col] = pack_hi(v2, v3);
        *(uint32_t*)&aol[(size_t)orow * HID + col]       = pack_lo(v0, v1);
        *(uint32_t*)&aol[(size_t)(orow + 8) * HID + col] = pack_lo(v2, v3);
    }
}

// ---------------------------------------------------------------------------
// launcher
// ---------------------------------------------------------------------------
extern "C" void kernel_launch(void* const* d_in, const int* in_sizes, int n_in,
                              void* d_out, int out_size) {
    const float* hidden  = (const float*)d_in[0];
    const float* mask    = (const float*)d_in[1];
    const float* Wq_lr   = (const float*)d_in[2];
    const float* bq_lr   = (const float*)d_in[3];
    const float* Wq_rope = (const float*)d_in[4];
    const float* bq_rope = (const float*)d_in[5];
    const float* Wq_c    = (const float*)d_in[6];
    const float* bq_c    = (const float*)d_in[7];
    const float* Wkv     = (const float*)d_in[8];
    const float* bkv     = (const float*)d_in[9];
    const float* Wk_rope = (const float*)d_in[10];
    const float* bk_rope = (const float*)d_in[11];
    const float* Wk_c    = (const float*)d_in[12];
    const float* bk_c    = (const float*)d_in[13];
    const float* Wv      = (const float*)d_in[14];
    const float* bv      = (const float*)d_in[15];
    const float* Wo      = (const float*)d_in[16];
    const float* bo      = (const float*)d_in[17];
    float* out = (float*)d_out;

    float *qc, *qr, *kc, *kr, *bkr;
    cudaGetSymbolAddress((void**)&qc,  g_qc);
    cudaGetSymbolAddress((void**)&qr,  g_qr);
    cudaGetSymbolAddress((void**)&kc,  g_kc);
    cudaGetSymbolAddress((void**)&kr,  g_kr);
    cudaGetSymbolAddress((void**)&bkr, g_bkr);

    __nv_bfloat16 *h_hi, *h_lo, *cq_hi, *cq_lo, *ckv_hi, *ckv_lo, *ao_hi, *ao_lo;
    __nv_bfloat16 *Wqlr_hi, *Wqlr_lo, *Wqc_hi, *Wqc_lo, *Wqr_hi, *Wqr_lo;
    __nv_bfloat16 *Wkv_hi, *Wkv_lo, *Wkc_hi, *Wkc_lo, *Wv_hi, *Wv_lo, *Wo_hi, *Wo_lo;
    __nv_bfloat16 *Wkr_hi, *Wkr_lo, *qhi, *qlo, *khi, *klo, *vhi, *vlo;
    cudaGetSymbolAddress((void**)&h_hi,   g_h_hi);   cudaGetSymbolAddress((void**)&h_lo,   g_h_lo);
    cudaGetSymbolAddress((void**)&cq_hi,  g_cq_hi);  cudaGetSymbolAddress((void**)&cq_lo,  g_cq_lo);
    cudaGetSymbolAddress((void**)&ckv_hi, g_ckv_hi); cudaGetSymbolAddress((void**)&ckv_lo, g_ckv_lo);
    cudaGetSymbolAddress((void**)&ao_hi,  g_ao_hi);  cudaGetSymbolAddress((void**)&ao_lo,  g_ao_lo);
    cudaGetSymbolAddress((void**)&Wqlr_hi, g_Wqlr_hi); cudaGetSymbolAddress((void**)&Wqlr_lo, g_Wqlr_lo);
    cudaGetSymbolAddress((void**)&Wqc_hi,  g_Wqc_hi);  cudaGetSymbolAddress((void**)&Wqc_lo,  g_Wqc_lo);
    cudaGetSymbolAddress((void**)&Wqr_hi,  g_Wqr_hi);  cudaGetSymbolAddress((void**)&Wqr_lo,  g_Wqr_lo);
    cudaGetSymbolAddress((void**)&Wkv_hi,  g_Wkv_hi);  cudaGetSymbolAddress((void**)&Wkv_lo,  g_Wkv_lo);
    cudaGetSymbolAddress((void**)&Wkc_hi,  g_Wkc_hi);  cudaGetSymbolAddress((void**)&Wkc_lo,  g_Wkc_lo);
    cudaGetSymbolAddress((void**)&Wv_hi,   g_Wv_hi);   cudaGetSymbolAddress((void**)&Wv_lo,   g_Wv_lo);
    cudaGetSymbolAddress((void**)&Wo_hi,   g_Wo_hi);   cudaGetSymbolAddress((void**)&Wo_lo,   g_Wo_lo);
    cudaGetSymbolAddress((void**)&Wkr_hi,  g_Wkr_hi);  cudaGetSymbolAddress((void**)&Wkr_lo,  g_Wkr_lo);
    cudaGetSymbolAddress((void**)&qhi, g_qhi); cudaGetSymbolAddress((void**)&qlo, g_qlo);
    cudaGetSymbolAddress((void**)&khi, g_khi); cudaGetSymbolAddress((void**)&klo, g_klo);
    cudaGetSymbolAddress((void**)&vhi, g_vhi); cudaGetSymbolAddress((void**)&vlo, g_vlo);

    const int M = 2048;
    cudaFuncSetAttribute(mma_gemm3, cudaFuncAttributeMaxDynamicSharedMemorySize, G_SMEM);

    // ---- one mega split launch for all 8 fp32->bf16 splits ----
    SJobs jobs;
    const float* srcs[8] = { hidden, Wq_lr, Wq_c, Wq_rope, Wkv, Wk_c, Wv, Wo };
    __nv_bfloat16* his[8] = { h_hi, Wqlr_hi, Wqc_hi, Wqr_hi, Wkv_hi, Wkc_hi, Wv_hi, Wo_hi };
    __nv_bfloat16* los[8] = { h_lo, Wqlr_lo, Wqc_lo, Wqr_lo, Wkv_lo, Wkc_lo, Wv_lo, Wo_lo };
    int ns[8] = { 2048*4096, 1536*4096, 4096*1536, 2048*1536,
                  512*4096, 4096*512, 4096*512, 4096*4096 };
    int blk = 0;
    for (int i = 0; i < 8; i++) {
        jobs.j[i].x = srcs[i]; jobs.j[i].hi = his[i]; jobs.j[i].lo = los[i];
        jobs.j[i].n4 = ns[i] / 4; jobs.j[i].blk0 = blk;
        blk += (jobs.j[i].n4 + 255) / 256;
    }
    multi_split_kernel<<<blk, 256>>>(jobs);
    pad_krope_kernel<<<(128 * 4096 + 255) / 256, 256>>>(Wk_rope, Wkr_hi, Wkr_lo, bk_rope, bkr);

    // c_q (bf16 out only)
    mma_gemm3<<<dim3(1536 / 128, M / 128), 128, G_SMEM>>>(
        h_hi, h_lo, Wqlr_hi, Wqlr_lo, bq_lr, nullptr, cq_hi, cq_lo, M, 1536, 4096);
    // q_content (float out)
    mma_gemm3<<<dim3(4096 / 128, M / 128), 128, G_SMEM>>>(
        cq_hi, cq_lo, Wqc_hi, Wqc_lo, bq_c, qc, nullptr, nullptr, M, 4096, 1536);
    // q_rope (float out)
    mma_gemm3<<<dim3(2048 / 128, M / 128), 128, G_SMEM>>>(
        cq_hi, cq_lo, Wqr_hi, Wqr_lo, bq_rope, qr, nullptr, nullptr, M, 2048, 1536);
    // c_kv (bf16 out only)
    mma_gemm3<<<dim3(512 / 128, M / 128), 128, G_SMEM>>>(
        h_hi, h_lo, Wkv_hi, Wkv_lo, bkv, nullptr, ckv_hi, ckv_lo, M, 512, 4096);
    // k_content (float out)
    mma_gemm3<<<dim3(4096 / 128, M / 128), 128, G_SMEM>>>(
        ckv_hi, ckv_lo, Wkc_hi, Wkc_lo, bk_c, kc, nullptr, nullptr, M, 4096, 512);
    // v (bf16 out only)
    mma_gemm3<<<dim3(4096 / 128, M / 128), 128, G_SMEM>>>(
        ckv_hi, ckv_lo, Wv_hi, Wv_lo, bv, nullptr, vhi, vlo, M, 4096, 512);
    // k_rope padded to N=128 (float out)
    mma_gemm3<<<dim3(1, M / 128), 128, G_SMEM>>>(
        h_hi, h_lo, Wkr_hi, Wkr_lo, bkr, kr, nullptr, nullptr, M, 128, 4096);

    rope_kernel<<<(2048 * 1024 + 255) / 256, 256>>>(qr, 2048, 2048, 2048);
    rope_kernel<<<(2048 * 32 + 255) / 256, 256>>>(kr, 2048, 64, 128);

    fuse_q_kernel<<<8192, 256>>>(qc, qr, qhi, qlo);
    fuse_k_kernel<<<8192, 256>>>(kc, kr, khi, klo);

    cudaFuncSetAttribute(attn_mma_kernel, cudaFuncAttributeMaxDynamicSharedMemorySize, ATT_SMEM);
    attn_mma_kernel<<<dim3(S_LEN / 128, NH), 256, ATT_SMEM>>>(
        qhi, qlo, khi, klo, vhi, vlo, mask, ao_hi, ao_lo);

    // out = ao @ Wo^T (float out)
    mma_gemm3<<<dim3(4096 / 128, M / 128), 128, G_SMEM>>>(
        ao_hi, ao_lo, Wo_hi, Wo_lo, bo, out, nullptr, nullptr, M, 4096, 4096);
}

// round 7
// speedup vs baseline: 4.9235x; 1.1652x over previous
#include <cuda_runtime.h>
#include <cuda_bf16.h>
#include <math.h>
#include <stdint.h>

#define S_LEN 2048
#define HID   4096
#define NH    32
#define DQK   192
#define DV    128

// ---------------------------------------------------------------------------
// scratch (device globals; no allocations allowed)
// ---------------------------------------------------------------------------
__device__ float g_qc [2048*4096];
__device__ float g_qr [2048*2048];
__device__ float g_kc [2048*4096];
__device__ float g_kr [2048*128];        // padded N=128
__device__ float g_bkr[128];             // padded bias

// bf16 hi/lo splits
__device__ __align__(16) __nv_bfloat16 g_h_hi [2048*4096], g_h_lo [2048*4096];
__device__ __align__(16) __nv_bfloat16 g_cq_hi[2048*1536], g_cq_lo[2048*1536];
__device__ __align__(16) __nv_bfloat16 g_ckv_hi[2048*512], g_ckv_lo[2048*512];
__device__ __align__(16) __nv_bfloat16 g_ao_hi[2048*4096], g_ao_lo[2048*4096];
__device__ __align__(16) __nv_bfloat16 g_Wqlr_hi[1536*4096], g_Wqlr_lo[1536*4096];
__device__ __align__(16) __nv_bfloat16 g_Wqc_hi [4096*1536], g_Wqc_lo [4096*1536];
__device__ __align__(16) __nv_bfloat16 g_Wqr_hi [2048*1536], g_Wqr_lo [2048*1536];
__device__ __align__(16) __nv_bfloat16 g_Wkv_hi [512*4096],  g_Wkv_lo [512*4096];
__device__ __align__(16) __nv_bfloat16 g_Wkc_hi [4096*512],  g_Wkc_lo [4096*512];
__device__ __align__(16) __nv_bfloat16 g_Wv_hi  [4096*512],  g_Wv_lo  [4096*512];
__device__ __align__(16) __nv_bfloat16 g_Wo_hi  [4096*4096], g_Wo_lo  [4096*4096];
__device__ __align__(16) __nv_bfloat16 g_Wkr_hi [128*4096],  g_Wkr_lo [128*4096];

// attention operands in bf16 hi/lo
__device__ __align__(16) __nv_bfloat16 g_qhi[2048*32*192], g_qlo[2048*32*192];
__device__ __align__(16) __nv_bfloat16 g_khi[2048*32*192], g_klo[2048*32*192];
__device__ __align__(16) __nv_bfloat16 g_vhi[2048*4096],   g_vlo[2048*4096];

// ---------------------------------------------------------------------------
// small PTX helpers
// ---------------------------------------------------------------------------
__device__ __forceinline__ uint32_t smem_u32(const void* p) {
    uint32_t a;
    asm("{ .reg .u64 t; cvta.to.shared.u64 t, %1; cvt.u32.u64 %0, t; }" : "=r"(a) : "l"(p));
    return a;
}
#define CP_ASYNC16(dst_u32, src_ptr) \
    asm volatile("cp.async.cg.shared.global [%0], [%1], 16;" \
                 :: "r"(dst_u32), "l"(__cvta_generic_to_global(src_ptr)) : "memory")
#define CP_COMMIT() asm volatile("cp.async.commit_group;" ::: "memory")
#define CP_WAIT(n)  asm volatile("cp.async.wait_group %0;" :: "n"(n) : "memory")

__device__ __forceinline__ void ldmx4(uint32_t& r0, uint32_t& r1, uint32_t& r2, uint32_t& r3,
                                      uint32_t addr) {
    asm volatile("ldmatrix.sync.aligned.m8n8.x4.shared.b16 {%0,%1,%2,%3}, [%4];"
                 : "=r"(r0), "=r"(r1), "=r"(r2), "=r"(r3) : "r"(addr));
}
__device__ __forceinline__ void ldmx4t(uint32_t& r0, uint32_t& r1, uint32_t& r2, uint32_t& r3,
                                       uint32_t addr) {
    asm volatile("ldmatrix.sync.aligned.m8n8.x4.trans.shared.b16 {%0,%1,%2,%3}, [%4];"
                 : "=r"(r0), "=r"(r1), "=r"(r2), "=r"(r3) : "r"(addr));
}
__device__ __forceinline__ void mma_bf16(float* d, const uint32_t* a, const uint32_t* b) {
    asm volatile("mma.sync.aligned.m16n8k16.row.col.f32.bf16.bf16.f32 "
                 "{%0,%1,%2,%3}, {%4,%5,%6,%7}, {%8,%9}, {%0,%1,%2,%3};"
                 : "+f"(d[0]), "+f"(d[1]), "+f"(d[2]), "+f"(d[3])
                 : "r"(a[0]), "r"(a[1]), "r"(a[2]), "r"(a[3]), "r"(b[0]), "r"(b[1]));
}
__device__ __forceinline__ uint32_t pack_hi(float a, float b) {
    __nv_bfloat16 ha = __float2bfloat16(a), hb = __float2bfloat16(b);
    return (uint32_t)__bfloat16_as_ushort(ha) | ((uint32_t)__bfloat16_as_ushort(hb) << 16);
}
__device__ __forceinline__ uint32_t pack_lo(float a, float b) {
    __nv_bfloat16 ha = __float2bfloat16(a), hb = __float2bfloat16(b);
    __nv_bfloat16 la = __float2bfloat16(a - __bfloat162float(ha));
    __nv_bfloat16 lb = __float2bfloat16(b - __bfloat162float(hb));
    return (uint32_t)__bfloat16_as_ushort(la) | ((uint32_t)__bfloat16_as_ushort(lb) << 16);
}

// ---------------------------------------------------------------------------
// mega split: all fp32 -> bf16(hi,lo) splits in ONE launch
// ---------------------------------------------------------------------------
struct SJob { const float* x; __nv_bfloat16* hi; __nv_bfloat16* lo; int n4; int blk0; };
struct SJobs { SJob j[8]; };

__global__ void multi_split_kernel(SJobs jobs) {
    int b = blockIdx.x;
    int ji = 0;
#pragma unroll
    for (int t = 1; t < 8; t++)
        if (b >= jobs.j[t].blk0) ji = t;
    const SJob jb = jobs.j[ji];
    int i = (b - jb.blk0) * 256 + threadIdx.x;
    if (i >= jb.n4) return;
    float4 v = ((const float4*)jb.x)[i];
    ((uint32_t*)jb.hi)[i*2 + 0] = pack_hi(v.x, v.y);
    ((uint32_t*)jb.hi)[i*2 + 1] = pack_hi(v.z, v.w);
    ((uint32_t*)jb.lo)[i*2 + 0] = pack_lo(v.x, v.y);
    ((uint32_t*)jb.lo)[i*2 + 1] = pack_lo(v.z, v.w);
}

// padded k_rope weight split: [64,4096] -> [128,4096] (rows 64..127 zero)
__global__ void pad_krope_kernel(const float* __restrict__ W,
                                 __nv_bfloat16* __restrict__ hi,
                                 __nv_bfloat16* __restrict__ lo,
                                 const float* __restrict__ b,
                                 float* __restrict__ bp) {
    int i = blockIdx.x * blockDim.x + threadIdx.x;
    if (i < 128) bp[i] = (i < 64) ? b[i] : 0.f;
    if (i >= 128 * 4096) return;
    int r = i >> 12;
    float v = (r < 64) ? W[(size_t)r * 4096 + (i & 4095)] : 0.f;
    __nv_bfloat16 h = __float2bfloat16(v);
    hi[i] = h;
    lo[i] = __float2bfloat16(v - __bfloat162float(h));
}

// ---------------------------------------------------------------------------
// batched warp-MMA bf16 GEMM with job table (fp32 emulation, combined passes)
// CTA 128x128, 4 warps (2x2), warp tile 64x64, BK=32, 2-stage cp.async.
// Per-block job: C[M,Nj] = A_j[M,Kj] @ W_j[Nj,Kj]^T + bias_j
// ---------------------------------------------------------------------------
#define ROWB 80
#define OA_HI 0
#define OA_LO 10240
#define OW_HI 20480
#define OW_LO 30720
#define G_BUF 40960
#define G_SMEM (2 * G_BUF)

struct GJob {
    const __nv_bfloat16 *Ahi, *Alo, *Whi, *Wlo;
    const float* bias;
    float* Cf;
    __nv_bfloat16 *Chi, *Clo;
    int N, K, blk0, pad_;
};
struct GJobs { GJob j[4]; };

__global__ void __launch_bounds__(128)
mma_gemm4(GJobs jobs) {
    extern __shared__ char gsm[];
    const uint32_t s0 = smem_u32(gsm);
    const int tid = threadIdx.x, wid = tid >> 5, lane = tid & 31;
    const int warp_m = wid >> 1, warp_n = wid & 1;   // 2x2 warp grid, 64x64 tiles

    int bx = blockIdx.x;
    int ji = 0;
#pragma unroll
    for (int t = 1; t < 4; t++)
        if (bx >= jobs.j[t].blk0) ji = t;
    const GJob jb = jobs.j[ji];
    const int col0 = (bx - jb.blk0) * 128;
    const int row0 = blockIdx.y * 128;
    const int K = jb.K, N = jb.N;

    const int a_row = (lane & 7) + ((lane >> 3) & 1) * 8;
    const int a_kof = (lane >> 4) * 8;
    const int b_row = (lane & 7) + (lane >> 4) * 8;
    const int b_kof = ((lane >> 3) & 1) * 8;

    const int kc = K >> 5;

    float acc[4][8][4];
#pragma unroll
    for (int mt = 0; mt < 4; mt++)
#pragma unroll
        for (int nt = 0; nt < 8; nt++)
#pragma unroll
            for (int e = 0; e < 4; e++) acc[mt][nt][e] = 0.f;

    auto load_chunk = [&](int c, int buf) {
        const int kk = c << 5;
        const uint32_t base = s0 + buf * G_BUF;
#pragma unroll
        for (int i = 0; i < 4; i++) {
            int idx = tid + i * 128;
            int r = idx >> 2, cb = idx & 3;
            size_t src = (size_t)(row0 + r) * K + kk + cb * 8;
            CP_ASYNC16(base + OA_HI + r * ROWB + cb * 16, jb.Ahi + src);
            CP_ASYNC16(base + OA_LO + r * ROWB + cb * 16, jb.Alo + src);
        }
#pragma unroll
        for (int i = 0; i < 4; i++) {
            int idx = tid + i * 128;
            int r = idx >> 2, cb = idx & 3;
            size_t src = (size_t)(col0 + r) * K + kk + cb * 8;
            CP_ASYNC16(base + OW_HI + r * ROWB + cb * 16, jb.Whi + src);
            CP_ASYNC16(base + OW_LO + r * ROWB + cb * 16, jb.Wlo + src);
        }
        CP_COMMIT();
    };

    load_chunk(0, 0);

    for (int c = 0; c < kc; c++) {
        const int buf = c & 1;
        if (c + 1 < kc) {
            load_chunk(c + 1, buf ^ 1);
            CP_WAIT(1);
        } else {
            CP_WAIT(0);
        }
        __syncthreads();
        const uint32_t base = s0 + buf * G_BUF;

#pragma unroll
        for (int ks = 0; ks < 2; ks++) {
            const int kb = ks * 16;
            uint32_t ah[4][4], al[4][4];
#pragma unroll
            for (int mt = 0; mt < 4; mt++) {
                uint32_t ra = (warp_m * 64 + mt * 16 + a_row) * ROWB + (kb + a_kof) * 2;
                ldmx4(ah[mt][0], ah[mt][1], ah[mt][2], ah[mt][3], base + OA_HI + ra);
                ldmx4(al[mt][0], al[mt][1], al[mt][2], al[mt][3], base + OA_LO + ra);
            }
#pragma unroll
            for (int np = 0; np < 4; np++) {
                uint32_t bh[4], bl[4];
                uint32_t rb = (warp_n * 64 + np * 16 + b_row) * ROWB + (kb + b_kof) * 2;
                ldmx4(bh[0], bh[1], bh[2], bh[3], base + OW_HI + rb);
                ldmx4(bl[0], bl[1], bl[2], bl[3], base + OW_LO + rb);
#pragma unroll
                for (int j = 0; j < 2; j++) {
                    uint32_t b2h[2] = { bh[j * 2], bh[j * 2 + 1] };
                    uint32_t b2l[2] = { bl[j * 2], bl[j * 2 + 1] };
                    const int nt = np * 2 + j;
                    // pass-major order: dependent MMAs on same acc are 4 apart
#pragma unroll
                    for (int mt = 0; mt < 4; mt++) mma_bf16(acc[mt][nt], ah[mt], b2h);
#pragma unroll
                    for (int mt = 0; mt < 4; mt++) mma_bf16(acc[mt][nt], al[mt], b2h);
#pragma unroll
                    for (int mt = 0; mt < 4; mt++) mma_bf16(acc[mt][nt], ah[mt], b2l);
                }
            }
        }
        __syncthreads();
    }

    const int rbase = row0 + warp_m * 64 + (lane >> 2);
    const int cbase = col0 + warp_n * 64 + (lane & 3) * 2;
#pragma unroll
    for (int mt = 0; mt < 4; mt++) {
#pragma unroll
        for (int nt = 0; nt < 8; nt++) {
            const int cc = cbase + nt * 8;
            const float b0 = jb.bias[cc], b1 = jb.bias[cc + 1];
            const int r0 = rbase + mt * 16;
            float v0 = acc[mt][nt][0] + b0, v1 = acc[mt][nt][1] + b1;
            float v2 = acc[mt][nt][2] + b0, v3 = acc[mt][nt][3] + b1;
            if (jb.Cf) {
                *(float2*)&jb.Cf[(size_t)r0 * N + cc] = make_float2(v0, v1);
                *(float2*)&jb.Cf[(size_t)(r0 + 8) * N + cc] = make_float2(v2, v3);
            }
            if (jb.Chi) {
                *(uint32_t*)&jb.Chi[(size_t)r0 * N + cc]       = pack_hi(v0, v1);
                *(uint32_t*)&jb.Chi[(size_t)(r0 + 8) * N + cc] = pack_hi(v2, v3);
                *(uint32_t*)&jb.Clo[(size_t)r0 * N + cc]       = pack_lo(v0, v1);
                *(uint32_t*)&jb.Clo[(size_t)(r0 + 8) * N + cc] = pack_lo(v2, v3);
            }
        }
    }
}

// ---------------- rotate-half RoPE, in place, x: [S, D], row stride ----------
__global__ void rope_kernel(float* __restrict__ x, int S, int D, int stride) {
    const int half = D / 2;
    const int idx = blockIdx.x * blockDim.x + threadIdx.x;
    if (idx >= S * half) return;
    const int s = idx / half, j = idx % half;
    float ex  = (float)(2 * j) / (float)D;
    float inv = 1.0f / powf(10000.0f, ex);
    float ang = (float)s * inv;
    float sn, c;
    sincosf(ang, &sn, &c);
    float x1 = x[(size_t)s * stride + j];
    float x2 = x[(size_t)s * stride + half + j];
    x[(size_t)s * stride + j]        = x1 * c - x2 * sn;
    x[(size_t)s * stride + half + j] = x2 * c + x1 * sn;
}

// ---------------- concat + RMSnorm over 192 -> bf16 hi/lo --------------------
__global__ void fuse_q_kernel(const float* __restrict__ qc,
                              const float* __restrict__ qr,
                              __nv_bfloat16* __restrict__ qh,
                              __nv_bfloat16* __restrict__ ql) {
    const int gw   = (blockIdx.x * blockDim.x + threadIdx.x) >> 5;
    const int lane = threadIdx.x & 31;
    const int s = gw >> 5, h = gw & 31;
    float vals[6]; float ss = 0.f;
#pragma unroll
    for (int t = 0; t < 6; t++) {
        int d = lane + 32 * t;
        float x = (d < 128) ? qc[(size_t)s * HID + h * 128 + d]
                            : qr[(size_t)s * 2048 + h * 64 + (d - 128)];
        vals[t] = x; ss += x * x;
    }
#pragma unroll
    for (int o = 16; o; o >>= 1) ss += __shfl_xor_sync(0xffffffffu, ss, o);
    float r = rsqrtf(ss * (1.f / 192.f) + 1.1920929e-7f);
#pragma unroll
    for (int t = 0; t < 6; t++) {
        float x = vals[t] * r;
        __nv_bfloat16 hb = __float2bfloat16(x);
        size_t o_ = ((size_t)s * NH + h) * DQK + lane + 32 * t;
        qh[o_] = hb;
        ql[o_] = __float2bfloat16(x - __bfloat162float(hb));
    }
}

__global__ void fuse_k_kernel(const float* __restrict__ kc,
                              const float* __restrict__ kr,
                              __nv_bfloat16* __restrict__ kh,
                              __nv_bfloat16* __restrict__ kl) {
    const int gw   = (blockIdx.x * blockDim.x + threadIdx.x) >> 5;
    const int lane = threadIdx.x & 31;
    const int s = gw >> 5, h = gw & 31;
    float vals[6]; float ss = 0.f;
#pragma unroll
    for (int t = 0; t < 6; t++) {
        int d = lane + 32 * t;
        float x = (d < 128) ? kc[(size_t)s * HID + h * 128 + d]
                            : kr[(size_t)s * 128 + (d - 128)];   // padded stride 128
        vals[t] = x; ss += x * x;
    }
#pragma unroll
    for (int o = 16; o; o >>= 1) ss += __shfl_xor_sync(0xffffffffu, ss, o);
    float r = rsqrtf(ss * (1.f / 192.f) + 1.1920929e-7f);
#pragma unroll
    for (int t = 0; t < 6; t++) {
        float x = vals[t] * r;
        __nv_bfloat16 hb = __float2bfloat16(x);
        size_t o_ = ((size_t)s * NH + h) * DQK + lane + 32 * t;
        kh[o_] = hb;
        kl[o_] = __float2bfloat16(x - __bfloat162float(hb));
    }
}

// ---------------------------------------------------------------------------
// flash attention with mma.sync (bf16 hi/lo emulation) + K/V prefetch overlap
// ---------------------------------------------------------------------------
#define OQH 0
#define OQL (OQH + 128*400)
#define OKH (OQL + 128*400)
#define OKL (OKH + 64*400)
#define OVH (OKL + 64*400)
#define OVL (OVH + 64*272)
#define OPH (OVL + 64*272)
#define OPL (OPH + 128*144)
#define ATT_SMEM (OPL + 128*144)

__global__ void __launch_bounds__(256, 1)
attn_mma_kernel(const __nv_bfloat16* __restrict__ qhi, const __nv_bfloat16* __restrict__ qlo,
                const __nv_bfloat16* __restrict__ khi, const __nv_bfloat16* __restrict__ klo,
                const __nv_bfloat16* __restrict__ vhi, const __nv_bfloat16* __restrict__ vlo,
                const float* __restrict__ mask,
                __nv_bfloat16* __restrict__ aoh, __nv_bfloat16* __restrict__ aol) {
    extern __shared__ char smraw[];
    const uint32_t s0 = smem_u32(smraw);
    const int h = blockIdx.y, q0 = blockIdx.x * 128;
    const int tid = threadIdx.x, wid = tid >> 5, lane = tid & 31;

    for (int i = tid; i < 3072; i += 256) {
        int r = i / 24, cb = i % 24;
        size_t src = ((size_t)(q0 + r) * NH + h) * DQK + cb * 8;
        CP_ASYNC16(s0 + OQH + r * 400 + cb * 16, qhi + src);
        CP_ASYNC16(s0 + OQL + r * 400 + cb * 16, qlo + src);
    }
    CP_COMMIT();

    auto load_k = [&](int k0) {
        for (int i = tid; i < 1536; i += 256) {
            int r = i / 24, cb = i % 24;
            size_t src = ((size_t)(k0 + r) * NH + h) * DQK + cb * 8;
            CP_ASYNC16(s0 + OKH + r * 400 + cb * 16, khi + src);
            CP_ASYNC16(s0 + OKL + r * 400 + cb * 16, klo + src);
        }
        CP_COMMIT();
    };
    auto load_v = [&](int k0) {
        for (int i = tid; i < 1024; i += 256) {
            int r = i / 16, cb = i % 16;
            size_t src = (size_t)(k0 + r) * HID + h * DV + cb * 8;
            CP_ASYNC16(s0 + OVH + r * 272 + cb * 16, vhi + src);
            CP_ASYNC16(s0 + OVL + r * 272 + cb * 16, vlo + src);
        }
        CP_COMMIT();
    };
    load_k(0);
    load_v(0);

    const float scale = 1.0f / sqrtf(192.0f);
    float m0 = -1e30f, m1 = -1e30f, l0 = 0.f, l1 = 0.f;
    float acc[16][4];
#pragma unroll
    for (int nt = 0; nt < 16; nt++)
#pragma unroll
        for (int e = 0; e < 4; e++) acc[nt][e] = 0.f;

    const int a_r  = (lane & 7) + ((lane >> 3) & 1) * 8;
    const int a_k  = (lane >> 4) * 8;
    const int bk_r = (lane & 7) + (lane >> 4) * 8;
    const int bk_k = ((lane >> 3) & 1) * 8;
    const int prow  = lane >> 2;
    const int pcol2 = (lane & 3) * 2;

    for (int c = 0; c < 32; c++) {
        const int k0 = c * 64;
        CP_WAIT(0);
        __syncthreads();

        // ---- S = Q K^T ----
        float sacc[8][4];
#pragma unroll
        for (int nt = 0; nt < 8; nt++)
#pragma unroll
            for (int e = 0; e < 4; e++) sacc[nt][e] = 0.f;

#pragma unroll
        for (int kt = 0; kt < 12; kt++) {
            uint32_t ah[4], al[4];
            ldmx4(ah[0], ah[1], ah[2], ah[3],
                  s0 + OQH + (wid * 16 + a_r) * 400 + (kt * 16 + a_k) * 2);
            ldmx4(al[0], al[1], al[2], al[3],
                  s0 + OQL + (wid * 16 + a_r) * 400 + (kt * 16 + a_k) * 2);
#pragma unroll
            for (int n2 = 0; n2 < 4; n2++) {
                uint32_t bh[4], bl[4];
                ldmx4(bh[0], bh[1], bh[2], bh[3],
                      s0 + OKH + (n2 * 16 + bk_r) * 400 + (kt * 16 + bk_k) * 2);
                ldmx4(bl[0], bl[1], bl[2], bl[3],
                      s0 + OKL + (n2 * 16 + bk_r) * 400 + (kt * 16 + bk_k) * 2);
                uint32_t bh0[2] = { bh[0], bh[1] }, bh1[2] = { bh[2], bh[3] };
                uint32_t bl0[2] = { bl[0], bl[1] }, bl1[2] = { bl[2], bl[3] };
                mma_bf16(sacc[n2 * 2],     ah, bh0);
                mma_bf16(sacc[n2 * 2 + 1], ah, bh1);
                mma_bf16(sacc[n2 * 2],     al, bh0);
                mma_bf16(sacc[n2 * 2 + 1], al, bh1);
                mma_bf16(sacc[n2 * 2],     ah, bl0);
                mma_bf16(sacc[n2 * 2 + 1], ah, bl1);
            }
        }
        __syncthreads();
        if (c + 1 < 32) load_k(k0 + 64);

        // ---- softmax (warp-local rows) ----
        const int rg0 = q0 + wid * 16 + prow;
        float sc[8][4];
        float mx0 = -1e30f, mx1 = -1e30f;
#pragma unroll
        for (int nt = 0; nt < 8; nt++) {
            int col = k0 + nt * 8 + pcol2;
            float2 mk0 = *(const float2*)&mask[(size_t)rg0 * S_LEN + col];
            float2 mk1 = *(const float2*)&mask[(size_t)(rg0 + 8) * S_LEN + col];
            sc[nt][0] = sacc[nt][0] * scale + mk0.x;
            sc[nt][1] = sacc[nt][1] * scale + mk0.y;
            sc[nt][2] = sacc[nt][2] * scale + mk1.x;
            sc[nt][3] = sacc[nt][3] * scale + mk1.y;
            mx0 = fmaxf(mx0, fmaxf(sc[nt][0], sc[nt][1]));
            mx1 = fmaxf(mx1, fmaxf(sc[nt][2], sc[nt][3]));
        }
        mx0 = fmaxf(mx0, __shfl_xor_sync(0xffffffffu, mx0, 1));
        mx0 = fmaxf(mx0, __shfl_xor_sync(0xffffffffu, mx0, 2));
        mx1 = fmaxf(mx1, __shfl_xor_sync(0xffffffffu, mx1, 1));
        mx1 = fmaxf(mx1, __shfl_xor_sync(0xffffffffu, mx1, 2));
        float mn0 = fmaxf(m0, mx0), mn1 = fmaxf(m1, mx1);
        float al0 = __expf(m0 - mn0), al1 = __expf(m1 - mn1);
        m0 = mn0; m1 = mn1;

        float ps0 = 0.f, ps1 = 0.f;
#pragma unroll
        for (int nt = 0; nt < 8; nt++) {
            float p00 = __expf(sc[nt][0] - mn0), p01 = __expf(sc[nt][1] - mn0);
            float p10 = __expf(sc[nt][2] - mn1), p11 = __expf(sc[nt][3] - mn1);
            ps0 += p00 + p01; ps1 += p10 + p11;
            int colb = (nt * 8 + pcol2) * 2;
            *(uint32_t*)(smraw + OPH + (wid * 16 + prow) * 144 + colb)     = pack_hi(p00, p01);
            *(uint32_t*)(smraw + OPH + (wid * 16 + prow + 8) * 144 + colb) = pack_hi(p10, p11);
            *(uint32_t*)(smraw + OPL + (wid * 16 + prow) * 144 + colb)     = pack_lo(p00, p01);
            *(uint32_t*)(smraw + OPL + (wid * 16 + prow + 8) * 144 + colb) = pack_lo(p10, p11);
        }
        ps0 += __shfl_xor_sync(0xffffffffu, ps0, 1);
        ps0 += __shfl_xor_sync(0xffffffffu, ps0, 2);
        ps1 += __shfl_xor_sync(0xffffffffu, ps1, 1);
        ps1 += __shfl_xor_sync(0xffffffffu, ps1, 2);
        l0 = al0 * l0 + ps0;
        l1 = al1 * l1 + ps1;
#pragma unroll
        for (int nt = 0; nt < 16; nt++) {
            acc[nt][0] *= al0; acc[nt][1] *= al0;
            acc[nt][2] *= al1; acc[nt][3] *= al1;
        }
        __syncwarp();

        // ---- O += P V ----
#pragma unroll
        for (int kt = 0; kt < 4; kt++) {
            uint32_t ph[4], pl[4];
            ldmx4(ph[0], ph[1], ph[2], ph[3],
                  s0 + OPH + (wid * 16 + a_r) * 144 + (kt * 16 + a_k) * 2);
            ldmx4(pl[0], pl[1], pl[2], pl[3],
                  s0 + OPL + (wid * 16 + a_r) * 144 + (kt * 16 + a_k) * 2);
#pragma unroll
            for (int n2 = 0; n2 < 8; n2++) {
                uint32_t vh[4], vl[4];
                ldmx4t(vh[0], vh[1], vh[2], vh[3],
                       s0 + OVH + (kt * 16 + a_r) * 272 + (n2 * 16 + a_k) * 2);
                ldmx4t(vl[0], vl[1], vl[2], vl[3],
                       s0 + OVL + (kt * 16 + a_r) * 272 + (n2 * 16 + a_k) * 2);
                uint32_t vh0[2] = { vh[0], vh[1] }, vh1[2] = { vh[2], vh[3] };
                uint32_t vl0[2] = { vl[0], vl[1] }, vl1[2] = { vl[2], vl[3] };
                mma_bf16(acc[n2 * 2],     ph, vh0);
                mma_bf16(acc[n2 * 2 + 1], ph, vh1);
                mma_bf16(acc[n2 * 2],     pl, vh0);
                mma_bf16(acc[n2 * 2 + 1], pl, vh1);
                mma_bf16(acc[n2 * 2],     ph, vl0);
                mma_bf16(acc[n2 * 2 + 1], ph, vl1);
            }
        }
        __syncthreads();
        if (c + 1 < 32) load_v(k0 + 64);
    }

    const float i0 = 1.f / l0, i1 = 1.f / l1;
    const int orow = q0 + wid * 16 + prow;
#pragma unroll
    for (int nt = 0; nt < 16; nt++) {
        int col = h * DV + nt * 8 + pcol2;
        float v0 = acc[nt][0] * i0, v1 = acc[nt][1] * i0;
        float v2 = acc[nt][2] * i1, v3 = acc[nt][3] * i1;
        *(uint32_t*)&aoh[(size_t)orow * HID + col]       = pack_hi(v0, v1);
        *(uint32_t*)&aoh[(size_t)(orow + 8) * HID + col] = pack_hi(v2, v3);
        *(uint32_t*)&aol[(size_t)orow * HID + col]       = pack_lo(v0, v1);
        *(uint32_t*)&aol[(size_t)(orow + 8) * HID + col] = pack_lo(v2, v3);
    }
}

// ---------------------------------------------------------------------------
// launcher
// ---------------------------------------------------------------------------
extern "C" void kernel_launch(void* const* d_in, const int* in_sizes, int n_in,
                              void* d_out, int out_size) {
    const float* hidden  = (const float*)d_in[0];
    const float* mask    = (const float*)d_in[1];
    const float* Wq_lr   = (const float*)d_in[2];
    const float* bq_lr   = (const float*)d_in[3];
    const float* Wq_rope = (const float*)d_in[4];
    const float* bq_rope = (const float*)d_in[5];
    const float* Wq_c    = (const float*)d_in[6];
    const float* bq_c    = (const float*)d_in[7];
    const float* Wkv     = (const float*)d_in[8];
    const float* bkv     = (const float*)d_in[9];
    const float* Wk_rope = (const float*)d_in[10];
    const float* bk_rope = (const float*)d_in[11];
    const float* Wk_c    = (const float*)d_in[12];
    const float* bk_c    = (const float*)d_in[13];
    const float* Wv      = (const float*)d_in[14];
    const float* bv      = (const float*)d_in[15];
    const float* Wo      = (const float*)d_in[16];
    const float* bo      = (const float*)d_in[17];
    float* out = (float*)d_out;

    float *qc, *qr, *kc, *kr, *bkr;
    cudaGetSymbolAddress((void**)&qc,  g_qc);
    cudaGetSymbolAddress((void**)&qr,  g_qr);
    cudaGetSymbolAddress((void**)&kc,  g_kc);
    cudaGetSymbolAddress((void**)&kr,  g_kr);
    cudaGetSymbolAddress((void**)&bkr, g_bkr);

    __nv_bfloat16 *h_hi, *h_lo, *cq_hi, *cq_lo, *ckv_hi, *ckv_lo, *ao_hi, *ao_lo;
    __nv_bfloat16 *Wqlr_hi, *Wqlr_lo, *Wqc_hi, *Wqc_lo, *Wqr_hi, *Wqr_lo;
    __nv_bfloat16 *Wkv_hi, *Wkv_lo, *Wkc_hi, *Wkc_lo, *Wv_hi, *Wv_lo, *Wo_hi, *Wo_lo;
    __nv_bfloat16 *Wkr_hi, *Wkr_lo, *qhi, *qlo, *khi, *klo, *vhi, *vlo;
    cudaGetSymbolAddress((void**)&h_hi,   g_h_hi);   cudaGetSymbolAddress((void**)&h_lo,   g_h_lo);
    cudaGetSymbolAddress((void**)&cq_hi,  g_cq_hi);  cudaGetSymbolAddress((void**)&cq_lo,  g_cq_lo);
    cudaGetSymbolAddress((void**)&ckv_hi, g_ckv_hi); cudaGetSymbolAddress((void**)&ckv_lo, g_ckv_lo);
    cudaGetSymbolAddress((void**)&ao_hi,  g_ao_hi);  cudaGetSymbolAddress((void**)&ao_lo,  g_ao_lo);
    cudaGetSymbolAddress((void**)&Wqlr_hi, g_Wqlr_hi); cudaGetSymbolAddress((void**)&Wqlr_lo, g_Wqlr_lo);
    cudaGetSymbolAddress((void**)&Wqc_hi,  g_Wqc_hi);  cudaGetSymbolAddress((void**)&Wqc_lo,  g_Wqc_lo);
    cudaGetSymbolAddress((void**)&Wqr_hi,  g_Wqr_hi);  cudaGetSymbolAddress((void**)&Wqr_lo,  g_Wqr_lo);
    cudaGetSymbolAddress((void**)&Wkv_hi,  g_Wkv_hi);  cudaGetSymbolAddress((void**)&Wkv_lo,  g_Wkv_lo);
    cudaGetSymbolAddress((void**)&Wkc_hi,  g_Wkc_hi);  cudaGetSymbolAddress((void**)&Wkc_lo,  g_Wkc_lo);
    cudaGetSymbolAddress((void**)&Wv_hi,   g_Wv_hi);   cudaGetSymbolAddress((void**)&Wv_lo,   g_Wv_lo);
    cudaGetSymbolAddress((void**)&Wo_hi,   g_Wo_hi);   cudaGetSymbolAddress((void**)&Wo_lo,   g_Wo_lo);
    cudaGetSymbolAddress((void**)&Wkr_hi,  g_Wkr_hi);  cudaGetSymbolAddress((void**)&Wkr_lo,  g_Wkr_lo);
    cudaGetSymbolAddress((void**)&qhi, g_qhi); cudaGetSymbolAddress((void**)&qlo, g_qlo);
    cudaGetSymbolAddress((void**)&khi, g_khi); cudaGetSymbolAddress((void**)&klo, g_klo);
    cudaGetSymbolAddress((void**)&vhi, g_vhi); cudaGetSymbolAddress((void**)&vlo, g_vlo);

    cudaFuncSetAttribute(mma_gemm4, cudaFuncAttributeMaxDynamicSharedMemorySize, G_SMEM);

    // ---- one mega split launch for all 8 fp32->bf16 splits ----
    SJobs jobs;
    const float* srcs[8] = { hidden, Wq_lr, Wq_c, Wq_rope, Wkv, Wk_c, Wv, Wo };
    __nv_bfloat16* his[8] = { h_hi, Wqlr_hi, Wqc_hi, Wqr_hi, Wkv_hi, Wkc_hi, Wv_hi, Wo_hi };
    __nv_bfloat16* los[8] = { h_lo, Wqlr_lo, Wqc_lo, Wqr_lo, Wkv_lo, Wkc_lo, Wv_lo, Wo_lo };
    int ns[8] = { 2048*4096, 1536*4096, 4096*1536, 2048*1536,
                  512*4096, 4096*512, 4096*512, 4096*4096 };
    int blk = 0;
    for (int i = 0; i < 8; i++) {
        jobs.j[i].x = srcs[i]; jobs.j[i].hi = his[i]; jobs.j[i].lo = los[i];
        jobs.j[i].n4 = ns[i] / 4; jobs.j[i].blk0 = blk;
        blk += (jobs.j[i].n4 + 255) / 256;
    }
    multi_split_kernel<<<blk, 256>>>(jobs);
    pad_krope_kernel<<<(128 * 4096 + 255) / 256, 256>>>(Wk_rope, Wkr_hi, Wkr_lo, bk_rope, bkr);

    const int NONE = 0x7FFFFFFF;

    // ---- G1: A = hidden(K=4096): c_q, c_kv, k_rope in one launch ----
    {
        GJobs g{};
        g.j[0] = { h_hi, h_lo, Wqlr_hi, Wqlr_lo, bq_lr, nullptr, cq_hi, cq_lo, 1536, 4096, 0, 0 };
        g.j[1] = { h_hi, h_lo, Wkv_hi,  Wkv_lo,  bkv,   nullptr, ckv_hi, ckv_lo, 512, 4096, 12, 0 };
        g.j[2] = { h_hi, h_lo, Wkr_hi,  Wkr_lo,  bkr,   kr, nullptr, nullptr, 128, 4096, 16, 0 };
        g.j[3] = g.j[2]; g.j[3].blk0 = NONE;
        mma_gemm4<<<dim3(17, 16), 128, G_SMEM>>>(g);
    }
    // ---- G2+G3: q_c, q_r (A=cq, K=1536) + k_c, v (A=ckv, K=512) ----
    {
        GJobs g{};
        g.j[0] = { cq_hi, cq_lo, Wqc_hi, Wqc_lo, bq_c,    qc, nullptr, nullptr, 4096, 1536, 0,  0 };
        g.j[1] = { cq_hi, cq_lo, Wqr_hi, Wqr_lo, bq_rope, qr, nullptr, nullptr, 2048, 1536, 32, 0 };
        g.j[2] = { ckv_hi, ckv_lo, Wkc_hi, Wkc_lo, bk_c,  kc, nullptr, nullptr, 4096, 512, 48, 0 };
        g.j[3] = { ckv_hi, ckv_lo, Wv_hi,  Wv_lo,  bv, nullptr, vhi, vlo,       4096, 512, 80, 0 };
        mma_gemm4<<<dim3(112, 16), 128, G_SMEM>>>(g);
    }

    rope_kernel<<<(2048 * 1024 + 255) / 256, 256>>>(qr, 2048, 2048, 2048);
    rope_kernel<<<(2048 * 32 + 255) / 256, 256>>>(kr, 2048, 64, 128);

    fuse_q_kernel<<<8192, 256>>>(qc, qr, qhi, qlo);
    fuse_k_kernel<<<8192, 256>>>(kc, kr, khi, klo);

    cudaFuncSetAttribute(attn_mma_kernel, cudaFuncAttributeMaxDynamicSharedMemorySize, ATT_SMEM);
    attn_mma_kernel<<<dim3(S_LEN / 128, NH), 256, ATT_SMEM>>>(
        qhi, qlo, khi, klo, vhi, vlo, mask, ao_hi, ao_lo);

    // ---- G4: out = ao @ Wo^T ----
    {
        GJobs g{};
        g.j[0] = { ao_hi, ao_lo, Wo_hi, Wo_lo, bo, out, nullptr, nullptr, 4096, 4096, 0, 0 };
        g.j[1] = g.j[0]; g.j[1].blk0 = NONE;
        g.j[2] = g.j[0]; g.j[2].blk0 = NONE;
        g.j[3] = g.j[0]; g.j[3].blk0 = NONE;
        mma_gemm4<<<dim3(32, 16), 128, G_SMEM>>>(g);
    }
}

// round 8
// speedup vs baseline: 5.0379x; 1.0232x over previous
#include <cuda_runtime.h>
#include <cuda_bf16.h>
#include <math.h>
#include <stdint.h>

#define S_LEN 2048
#define HID   4096
#define NH    32
#define DQK   192
#define DV    128

// ---------------------------------------------------------------------------
// scratch (device globals; no allocations allowed)
// ---------------------------------------------------------------------------
__device__ float g_qc [2048*4096];
__device__ float g_qr [2048*2048];
__device__ float g_kc [2048*4096];
__device__ float g_kr [2048*128];        // padded N=128
__device__ float g_bkr[128];             // padded bias

// bf16 hi/lo splits
__device__ __align__(16) __nv_bfloat16 g_h_hi [2048*4096], g_h_lo [2048*4096];
__device__ __align__(16) __nv_bfloat16 g_cq_hi[2048*1536], g_cq_lo[2048*1536];
__device__ __align__(16) __nv_bfloat16 g_ckv_hi[2048*512], g_ckv_lo[2048*512];
__device__ __align__(16) __nv_bfloat16 g_ao_hi[2048*4096], g_ao_lo[2048*4096];
__device__ __align__(16) __nv_bfloat16 g_Wqlr_hi[1536*4096], g_Wqlr_lo[1536*4096];
__device__ __align__(16) __nv_bfloat16 g_Wqc_hi [4096*1536], g_Wqc_lo [4096*1536];
__device__ __align__(16) __nv_bfloat16 g_Wqr_hi [2048*1536], g_Wqr_lo [2048*1536];
__device__ __align__(16) __nv_bfloat16 g_Wkv_hi [512*4096],  g_Wkv_lo [512*4096];
__device__ __align__(16) __nv_bfloat16 g_Wkc_hi [4096*512],  g_Wkc_lo [4096*512];
__device__ __align__(16) __nv_bfloat16 g_Wv_hi  [4096*512],  g_Wv_lo  [4096*512];
__device__ __align__(16) __nv_bfloat16 g_Wo_hi  [4096*4096], g_Wo_lo  [4096*4096];
__device__ __align__(16) __nv_bfloat16 g_Wkr_hi [128*4096],  g_Wkr_lo [128*4096];

// attention operands in bf16 hi/lo
__device__ __align__(16) __nv_bfloat16 g_qhi[2048*32*192], g_qlo[2048*32*192];
__device__ __align__(16) __nv_bfloat16 g_khi[2048*32*192], g_klo[2048*32*192];
__device__ __align__(16) __nv_bfloat16 g_vhi[2048*4096],   g_vlo[2048*4096];

// ---------------------------------------------------------------------------
// small PTX helpers
// ---------------------------------------------------------------------------
__device__ __forceinline__ uint32_t smem_u32(const void* p) {
    uint32_t a;
    asm("{ .reg .u64 t; cvta.to.shared.u64 t, %1; cvt.u32.u64 %0, t; }" : "=r"(a) : "l"(p));
    return a;
}
#define CP_ASYNC16(dst_u32, src_ptr) \
    asm volatile("cp.async.cg.shared.global [%0], [%1], 16;" \
                 :: "r"(dst_u32), "l"(__cvta_generic_to_global(src_ptr)) : "memory")
#define CP_COMMIT() asm volatile("cp.async.commit_group;" ::: "memory")
#define CP_WAIT(n)  asm volatile("cp.async.wait_group %0;" :: "n"(n) : "memory")

__device__ __forceinline__ void ldmx4(uint32_t& r0, uint32_t& r1, uint32_t& r2, uint32_t& r3,
                                      uint32_t addr) {
    asm volatile("ldmatrix.sync.aligned.m8n8.x4.shared.b16 {%0,%1,%2,%3}, [%4];"
                 : "=r"(r0), "=r"(r1), "=r"(r2), "=r"(r3) : "r"(addr));
}
__device__ __forceinline__ void ldmx4t(uint32_t& r0, uint32_t& r1, uint32_t& r2, uint32_t& r3,
                                       uint32_t addr) {
    asm volatile("ldmatrix.sync.aligned.m8n8.x4.trans.shared.b16 {%0,%1,%2,%3}, [%4];"
                 : "=r"(r0), "=r"(r1), "=r"(r2), "=r"(r3) : "r"(addr));
}
__device__ __forceinline__ void mma_bf16(float* d, const uint32_t* a, const uint32_t* b) {
    asm volatile("mma.sync.aligned.m16n8k16.row.col.f32.bf16.bf16.f32 "
                 "{%0,%1,%2,%3}, {%4,%5,%6,%7}, {%8,%9}, {%0,%1,%2,%3};"
                 : "+f"(d[0]), "+f"(d[1]), "+f"(d[2]), "+f"(d[3])
                 : "r"(a[0]), "r"(a[1]), "r"(a[2]), "r"(a[3]), "r"(b[0]), "r"(b[1]));
}
__device__ __forceinline__ uint32_t pack_hi(float a, float b) {
    __nv_bfloat16 ha = __float2bfloat16(a), hb = __float2bfloat16(b);
    return (uint32_t)__bfloat16_as_ushort(ha) | ((uint32_t)__bfloat16_as_ushort(hb) << 16);
}
__device__ __forceinline__ uint32_t pack_lo(float a, float b) {
    __nv_bfloat16 ha = __float2bfloat16(a), hb = __float2bfloat16(b);
    __nv_bfloat16 la = __float2bfloat16(a - __bfloat162float(ha));
    __nv_bfloat16 lb = __float2bfloat16(b - __bfloat162float(hb));
    return (uint32_t)__bfloat16_as_ushort(la) | ((uint32_t)__bfloat16_as_ushort(lb) << 16);
}

// ---------------------------------------------------------------------------
// mega split: all fp32 -> bf16(hi,lo) splits in ONE launch
// ---------------------------------------------------------------------------
struct SJob { const float* x; __nv_bfloat16* hi; __nv_bfloat16* lo; int n4; int blk0; };
struct SJobs { SJob j[8]; };

__global__ void multi_split_kernel(SJobs jobs) {
    int b = blockIdx.x;
    int ji = 0;
#pragma unroll
    for (int t = 1; t < 8; t++)
        if (b >= jobs.j[t].blk0) ji = t;
    const SJob jb = jobs.j[ji];
    int i = (b - jb.blk0) * 256 + threadIdx.x;
    if (i >= jb.n4) return;
    float4 v = ((const float4*)jb.x)[i];
    ((uint32_t*)jb.hi)[i*2 + 0] = pack_hi(v.x, v.y);
    ((uint32_t*)jb.hi)[i*2 + 1] = pack_hi(v.z, v.w);
    ((uint32_t*)jb.lo)[i*2 + 0] = pack_lo(v.x, v.y);
    ((uint32_t*)jb.lo)[i*2 + 1] = pack_lo(v.z, v.w);
}

// padded k_rope weight split: [64,4096] -> [128,4096] (rows 64..127 zero)
__global__ void pad_krope_kernel(const float* __restrict__ W,
                                 __nv_bfloat16* __restrict__ hi,
                                 __nv_bfloat16* __restrict__ lo,
                                 const float* __restrict__ b,
                                 float* __restrict__ bp) {
    int i = blockIdx.x * blockDim.x + threadIdx.x;
    if (i < 128) bp[i] = (i < 64) ? b[i] : 0.f;
    if (i >= 128 * 4096) return;
    int r = i >> 12;
    float v = (r < 64) ? W[(size_t)r * 4096 + (i & 4095)] : 0.f;
    __nv_bfloat16 h = __float2bfloat16(v);
    hi[i] = h;
    lo[i] = __float2bfloat16(v - __bfloat162float(h));
}

// ---------------------------------------------------------------------------
// batched warp-MMA bf16 GEMM with job table (fp32 emulation, combined passes)
// CTA 128x128, 4 warps (2x2), warp tile 64x64, BK=32, 2-stage cp.async.
// ---------------------------------------------------------------------------
#define ROWB 80
#define OA_HI 0
#define OA_LO 10240
#define OW_HI 20480
#define OW_LO 30720
#define G_BUF 40960
#define G_SMEM (2 * G_BUF)

struct GJob {
    const __nv_bfloat16 *Ahi, *Alo, *Whi, *Wlo;
    const float* bias;
    float* Cf;
    __nv_bfloat16 *Chi, *Clo;
    int N, K, blk0, pad_;
};
struct GJobs { GJob j[4]; };

__global__ void __launch_bounds__(128)
mma_gemm4(GJobs jobs) {
    extern __shared__ char gsm[];
    const uint32_t s0 = smem_u32(gsm);
    const int tid = threadIdx.x, wid = tid >> 5, lane = tid & 31;
    const int warp_m = wid >> 1, warp_n = wid & 1;

    int bx = blockIdx.x;
    int ji = 0;
#pragma unroll
    for (int t = 1; t < 4; t++)
        if (bx >= jobs.j[t].blk0) ji = t;
    const GJob jb = jobs.j[ji];
    const int col0 = (bx - jb.blk0) * 128;
    const int row0 = blockIdx.y * 128;
    const int K = jb.K, N = jb.N;

    const int a_row = (lane & 7) + ((lane >> 3) & 1) * 8;
    const int a_kof = (lane >> 4) * 8;
    const int b_row = (lane & 7) + (lane >> 4) * 8;
    const int b_kof = ((lane >> 3) & 1) * 8;

    const int kc = K >> 5;

    float acc[4][8][4];
#pragma unroll
    for (int mt = 0; mt < 4; mt++)
#pragma unroll
        for (int nt = 0; nt < 8; nt++)
#pragma unroll
            for (int e = 0; e < 4; e++) acc[mt][nt][e] = 0.f;

    auto load_chunk = [&](int c, int buf) {
        const int kk = c << 5;
        const uint32_t base = s0 + buf * G_BUF;
#pragma unroll
        for (int i = 0; i < 4; i++) {
            int idx = tid + i * 128;
            int r = idx >> 2, cb = idx & 3;
            size_t src = (size_t)(row0 + r) * K + kk + cb * 8;
            CP_ASYNC16(base + OA_HI + r * ROWB + cb * 16, jb.Ahi + src);
            CP_ASYNC16(base + OA_LO + r * ROWB + cb * 16, jb.Alo + src);
        }
#pragma unroll
        for (int i = 0; i < 4; i++) {
            int idx = tid + i * 128;
            int r = idx >> 2, cb = idx & 3;
            size_t src = (size_t)(col0 + r) * K + kk + cb * 8;
            CP_ASYNC16(base + OW_HI + r * ROWB + cb * 16, jb.Whi + src);
            CP_ASYNC16(base + OW_LO + r * ROWB + cb * 16, jb.Wlo + src);
        }
        CP_COMMIT();
    };

    load_chunk(0, 0);

    for (int c = 0; c < kc; c++) {
        const int buf = c & 1;
        if (c + 1 < kc) {
            load_chunk(c + 1, buf ^ 1);
            CP_WAIT(1);
        } else {
            CP_WAIT(0);
        }
        __syncthreads();
        const uint32_t base = s0 + buf * G_BUF;

#pragma unroll
        for (int ks = 0; ks < 2; ks++) {
            const int kb = ks * 16;
            uint32_t ah[4][4], al[4][4];
#pragma unroll
            for (int mt = 0; mt < 4; mt++) {
                uint32_t ra = (warp_m * 64 + mt * 16 + a_row) * ROWB + (kb + a_kof) * 2;
                ldmx4(ah[mt][0], ah[mt][1], ah[mt][2], ah[mt][3], base + OA_HI + ra);
                ldmx4(al[mt][0], al[mt][1], al[mt][2], al[mt][3], base + OA_LO + ra);
            }
#pragma unroll
            for (int np = 0; np < 4; np++) {
                uint32_t bh[4], bl[4];
                uint32_t rb = (warp_n * 64 + np * 16 + b_row) * ROWB + (kb + b_kof) * 2;
                ldmx4(bh[0], bh[1], bh[2], bh[3], base + OW_HI + rb);
                ldmx4(bl[0], bl[1], bl[2], bl[3], base + OW_LO + rb);
#pragma unroll
                for (int j = 0; j < 2; j++) {
                    uint32_t b2h[2] = { bh[j * 2], bh[j * 2 + 1] };
                    uint32_t b2l[2] = { bl[j * 2], bl[j * 2 + 1] };
                    const int nt = np * 2 + j;
#pragma unroll
                    for (int mt = 0; mt < 4; mt++) mma_bf16(acc[mt][nt], ah[mt], b2h);
#pragma unroll
                    for (int mt = 0; mt < 4; mt++) mma_bf16(acc[mt][nt], al[mt], b2h);
#pragma unroll
                    for (int mt = 0; mt < 4; mt++) mma_bf16(acc[mt][nt], ah[mt], b2l);
                }
            }
        }
        __syncthreads();
    }

    const int rbase = row0 + warp_m * 64 + (lane >> 2);
    const int cbase = col0 + warp_n * 64 + (lane & 3) * 2;
#pragma unroll
    for (int mt = 0; mt < 4; mt++) {
#pragma unroll
        for (int nt = 0; nt < 8; nt++) {
            const int cc = cbase + nt * 8;
            const float b0 = jb.bias[cc], b1 = jb.bias[cc + 1];
            const int r0 = rbase + mt * 16;
            float v0 = acc[mt][nt][0] + b0, v1 = acc[mt][nt][1] + b1;
            float v2 = acc[mt][nt][2] + b0, v3 = acc[mt][nt][3] + b1;
            if (jb.Cf) {
                *(float2*)&jb.Cf[(size_t)r0 * N + cc] = make_float2(v0, v1);
                *(float2*)&jb.Cf[(size_t)(r0 + 8) * N + cc] = make_float2(v2, v3);
            }
            if (jb.Chi) {
                *(uint32_t*)&jb.Chi[(size_t)r0 * N + cc]       = pack_hi(v0, v1);
                *(uint32_t*)&jb.Chi[(size_t)(r0 + 8) * N + cc] = pack_hi(v2, v3);
                *(uint32_t*)&jb.Clo[(size_t)r0 * N + cc]       = pack_lo(v0, v1);
                *(uint32_t*)&jb.Clo[(size_t)(r0 + 8) * N + cc] = pack_lo(v2, v3);
            }
        }
    }
}

// ---------------- concat + inline RoPE + RMSnorm -> bf16 hi/lo ----------------
// q rope: qr is the raw (pre-rope) [S,2048] projection; pairs (j, j+1024).
__global__ void fuse_q_kernel(const float* __restrict__ qc,
                              const float* __restrict__ qr,
                              __nv_bfloat16* __restrict__ qh,
                              __nv_bfloat16* __restrict__ ql) {
    const int gw   = (blockIdx.x * blockDim.x + threadIdx.x) >> 5;
    const int lane = threadIdx.x & 31;
    const int s = gw >> 5, h = gw & 31;
    float vals[6]; float ss = 0.f;
#pragma unroll
    for (int t = 0; t < 6; t++) {
        int d = lane + 32 * t;
        float x;
        if (d < 128) {
            x = qc[(size_t)s * HID + h * 128 + d];
        } else {
            int j = h * 64 + (d - 128);          // index into 2048-wide rope vec
            int base = (j < 1024) ? j : j - 1024;
            float ex  = (float)(2 * base) / 2048.0f;
            float inv = 1.0f / powf(10000.0f, ex);
            float sn, c;
            sincosf((float)s * inv, &sn, &c);
            if (j < 1024)
                x = qr[(size_t)s * 2048 + j] * c - qr[(size_t)s * 2048 + j + 1024] * sn;
            else
                x = qr[(size_t)s * 2048 + j] * c + qr[(size_t)s * 2048 + base] * sn;
        }
        vals[t] = x; ss += x * x;
    }
#pragma unroll
    for (int o = 16; o; o >>= 1) ss += __shfl_xor_sync(0xffffffffu, ss, o);
    float r = rsqrtf(ss * (1.f / 192.f) + 1.1920929e-7f);
#pragma unroll
    for (int t = 0; t < 6; t++) {
        float x = vals[t] * r;
        __nv_bfloat16 hb = __float2bfloat16(x);
        size_t o_ = ((size_t)s * NH + h) * DQK + lane + 32 * t;
        qh[o_] = hb;
        ql[o_] = __float2bfloat16(x - __bfloat162float(hb));
    }
}

// k rope: kr is raw [S,128-padded], real D=64; pairs (j, j+32).
__global__ void fuse_k_kernel(const float* __restrict__ kc,
                              const float* __restrict__ kr,
                              __nv_bfloat16* __restrict__ kh,
                              __nv_bfloat16* __restrict__ kl) {
    const int gw   = (blockIdx.x * blockDim.x + threadIdx.x) >> 5;
    const int lane = threadIdx.x & 31;
    const int s = gw >> 5, h = gw & 31;
    float vals[6]; float ss = 0.f;
#pragma unroll
    for (int t = 0; t < 6; t++) {
        int d = lane + 32 * t;
        float x;
        if (d < 128) {
            x = kc[(size_t)s * HID + h * 128 + d];
        } else {
            int j = d - 128;                      // 0..63
            int base = (j < 32) ? j : j - 32;
            float ex  = (float)(2 * base) / 64.0f;
            float inv = 1.0f / powf(10000.0f, ex);
            float sn, c;
            sincosf((float)s * inv, &sn, &c);
            if (j < 32)
                x = kr[(size_t)s * 128 + j] * c - kr[(size_t)s * 128 + j + 32] * sn;
            else
                x = kr[(size_t)s * 128 + j] * c + kr[(size_t)s * 128 + base] * sn;
        }
        vals[t] = x; ss += x * x;
    }
#pragma unroll
    for (int o = 16; o; o >>= 1) ss += __shfl_xor_sync(0xffffffffu, ss, o);
    float r = rsqrtf(ss * (1.f / 192.f) + 1.1920929e-7f);
#pragma unroll
    for (int t = 0; t < 6; t++) {
        float x = vals[t] * r;
        __nv_bfloat16 hb = __float2bfloat16(x);
        size_t o_ = ((size_t)s * NH + h) * DQK + lane + 32 * t;
        kh[o_] = hb;
        kl[o_] = __float2bfloat16(x - __bfloat162float(hb));
    }
}

// ---------------------------------------------------------------------------
// flash attention with mma.sync (bf16 hi/lo emulation), register-resident P
// (FA2 accumulator->A-operand layout identity), K/V cp.async prefetch overlap.
// ---------------------------------------------------------------------------
#define OQH 0
#define OQL (OQH + 128*400)
#define OKH (OQL + 128*400)
#define OKL (OKH + 64*400)
#define OVH (OKL + 64*400)
#define OVL (OVH + 64*272)
#define ATT_SMEM (OVL + 64*272)    // 188416 bytes

__global__ void __launch_bounds__(256, 1)
attn_mma_kernel(const __nv_bfloat16* __restrict__ qhi, const __nv_bfloat16* __restrict__ qlo,
                const __nv_bfloat16* __restrict__ khi, const __nv_bfloat16* __restrict__ klo,
                const __nv_bfloat16* __restrict__ vhi, const __nv_bfloat16* __restrict__ vlo,
                const float* __restrict__ mask,
                __nv_bfloat16* __restrict__ aoh, __nv_bfloat16* __restrict__ aol) {
    extern __shared__ char smraw[];
    const uint32_t s0 = smem_u32(smraw);
    const int h = blockIdx.y, q0 = blockIdx.x * 128;
    const int tid = threadIdx.x, wid = tid >> 5, lane = tid & 31;

    for (int i = tid; i < 3072; i += 256) {
        int r = i / 24, cb = i % 24;
        size_t src = ((size_t)(q0 + r) * NH + h) * DQK + cb * 8;
        CP_ASYNC16(s0 + OQH + r * 400 + cb * 16, qhi + src);
        CP_ASYNC16(s0 + OQL + r * 400 + cb * 16, qlo + src);
    }
    CP_COMMIT();

    auto load_k = [&](int k0) {
        for (int i = tid; i < 1536; i += 256) {
            int r = i / 24, cb = i % 24;
            size_t src = ((size_t)(k0 + r) * NH + h) * DQK + cb * 8;
            CP_ASYNC16(s0 + OKH + r * 400 + cb * 16, khi + src);
            CP_ASYNC16(s0 + OKL + r * 400 + cb * 16, klo + src);
        }
        CP_COMMIT();
    };
    auto load_v = [&](int k0) {
        for (int i = tid; i < 1024; i += 256) {
            int r = i / 16, cb = i % 16;
            size_t src = (size_t)(k0 + r) * HID + h * DV + cb * 8;
            CP_ASYNC16(s0 + OVH + r * 272 + cb * 16, vhi + src);
            CP_ASYNC16(s0 + OVL + r * 272 + cb * 16, vlo + src);
        }
        CP_COMMIT();
    };
    load_k(0);
    load_v(0);

    const float scale = 1.0f / sqrtf(192.0f);
    float m0 = -1e30f, m1 = -1e30f, l0 = 0.f, l1 = 0.f;
    float acc[16][4];
#pragma unroll
    for (int nt = 0; nt < 16; nt++)
#pragma unroll
        for (int e = 0; e < 4; e++) acc[nt][e] = 0.f;

    const int a_r  = (lane & 7) + ((lane >> 3) & 1) * 8;
    const int a_k  = (lane >> 4) * 8;
    const int bk_r = (lane & 7) + (lane >> 4) * 8;
    const int bk_k = ((lane >> 3) & 1) * 8;
    const int prow  = lane >> 2;
    const int pcol2 = (lane & 3) * 2;

    for (int c = 0; c < 32; c++) {
        const int k0 = c * 64;
        CP_WAIT(0);
        __syncthreads();

        // ---- S = Q K^T ----
        float sacc[8][4];
#pragma unroll
        for (int nt = 0; nt < 8; nt++)
#pragma unroll
            for (int e = 0; e < 4; e++) sacc[nt][e] = 0.f;

#pragma unroll
        for (int kt = 0; kt < 12; kt++) {
            uint32_t ah[4], al[4];
            ldmx4(ah[0], ah[1], ah[2], ah[3],
                  s0 + OQH + (wid * 16 + a_r) * 400 + (kt * 16 + a_k) * 2);
            ldmx4(al[0], al[1], al[2], al[3],
                  s0 + OQL + (wid * 16 + a_r) * 400 + (kt * 16 + a_k) * 2);
#pragma unroll
            for (int n2 = 0; n2 < 4; n2++) {
                uint32_t bh[4], bl[4];
                ldmx4(bh[0], bh[1], bh[2], bh[3],
                      s0 + OKH + (n2 * 16 + bk_r) * 400 + (kt * 16 + bk_k) * 2);
                ldmx4(bl[0], bl[1], bl[2], bl[3],
                      s0 + OKL + (n2 * 16 + bk_r) * 400 + (kt * 16 + bk_k) * 2);
                uint32_t bh0[2] = { bh[0], bh[1] }, bh1[2] = { bh[2], bh[3] };
                uint32_t bl0[2] = { bl[0], bl[1] }, bl1[2] = { bl[2], bl[3] };
                mma_bf16(sacc[n2 * 2],     ah, bh0);
                mma_bf16(sacc[n2 * 2 + 1], ah, bh1);
                mma_bf16(sacc[n2 * 2],     al, bh0);
                mma_bf16(sacc[n2 * 2 + 1], al, bh1);
                mma_bf16(sacc[n2 * 2],     ah, bl0);
                mma_bf16(sacc[n2 * 2 + 1], ah, bl1);
            }
        }
        __syncthreads();                 // all warps done reading K
        if (c + 1 < 32) load_k(k0 + 64); // prefetch K(c+1)

        // ---- softmax (warp-local rows), P packed straight into A-frags ----
        const int rg0 = q0 + wid * 16 + prow;
        float sc[8][4];
        float mx0 = -1e30f, mx1 = -1e30f;
#pragma unroll
        for (int nt = 0; nt < 8; nt++) {
            int col = k0 + nt * 8 + pcol2;
            float2 mk0 = *(const float2*)&mask[(size_t)rg0 * S_LEN + col];
            float2 mk1 = *(const float2*)&mask[(size_t)(rg0 + 8) * S_LEN + col];
            sc[nt][0] = sacc[nt][0] * scale + mk0.x;
            sc[nt][1] = sacc[nt][1] * scale + mk0.y;
            sc[nt][2] = sacc[nt][2] * scale + mk1.x;
            sc[nt][3] = sacc[nt][3] * scale + mk1.y;
            mx0 = fmaxf(mx0, fmaxf(sc[nt][0], sc[nt][1]));
            mx1 = fmaxf(mx1, fmaxf(sc[nt][2], sc[nt][3]));
        }
        mx0 = fmaxf(mx0, __shfl_xor_sync(0xffffffffu, mx0, 1));
        mx0 = fmaxf(mx0, __shfl_xor_sync(0xffffffffu, mx0, 2));
        mx1 = fmaxf(mx1, __shfl_xor_sync(0xffffffffu, mx1, 1));
        mx1 = fmaxf(mx1, __shfl_xor_sync(0xffffffffu, mx1, 2));
        float mn0 = fmaxf(m0, mx0), mn1 = fmaxf(m1, mx1);
        float al0 = __expf(m0 - mn0), al1 = __expf(m1 - mn1);
        m0 = mn0; m1 = mn1;

        // pfh/pfl[kt][0..3]: A-operand frags for PV (k16 block kt = S tiles 2kt,2kt+1)
        uint32_t pfh[4][4], pfl[4][4];
        float ps0 = 0.f, ps1 = 0.f;
#pragma unroll
        for (int nt = 0; nt < 8; nt++) {
            float p00 = __expf(sc[nt][0] - mn0), p01 = __expf(sc[nt][1] - mn0);
            float p10 = __expf(sc[nt][2] - mn1), p11 = __expf(sc[nt][3] - mn1);
            ps0 += p00 + p01; ps1 += p10 + p11;
            const int kt = nt >> 1, sl = (nt & 1) * 2;
            pfh[kt][sl + 0] = pack_hi(p00, p01);
            pfh[kt][sl + 1] = pack_hi(p10, p11);
            pfl[kt][sl + 0] = pack_lo(p00, p01);
            pfl[kt][sl + 1] = pack_lo(p10, p11);
        }
        ps0 += __shfl_xor_sync(0xffffffffu, ps0, 1);
        ps0 += __shfl_xor_sync(0xffffffffu, ps0, 2);
        ps1 += __shfl_xor_sync(0xffffffffu, ps1, 1);
        ps1 += __shfl_xor_sync(0xffffffffu, ps1, 2);
        l0 = al0 * l0 + ps0;
        l1 = al1 * l1 + ps1;
#pragma unroll
        for (int nt = 0; nt < 16; nt++) {
            acc[nt][0] *= al0; acc[nt][1] *= al0;
            acc[nt][2] *= al1; acc[nt][3] *= al1;
        }

        // ---- O += P V (register P; V via trans ldmatrix) ----
#pragma unroll
        for (int kt = 0; kt < 4; kt++) {
#pragma unroll
            for (int n2 = 0; n2 < 8; n2++) {
                uint32_t vh[4], vl[4];
                ldmx4t(vh[0], vh[1], vh[2], vh[3],
                       s0 + OVH + (kt * 16 + a_r) * 272 + (n2 * 16 + a_k) * 2);
                ldmx4t(vl[0], vl[1], vl[2], vl[3],
                       s0 + OVL + (kt * 16 + a_r) * 272 + (n2 * 16 + a_k) * 2);
                uint32_t vh0[2] = { vh[0], vh[1] }, vh1[2] = { vh[2], vh[3] };
                uint32_t vl0[2] = { vl[0], vl[1] }, vl1[2] = { vl[2], vl[3] };
                mma_bf16(acc[n2 * 2],     pfh[kt], vh0);
                mma_bf16(acc[n2 * 2 + 1], pfh[kt], vh1);
                mma_bf16(acc[n2 * 2],     pfl[kt], vh0);
                mma_bf16(acc[n2 * 2 + 1], pfl[kt], vh1);
                mma_bf16(acc[n2 * 2],     pfh[kt], vl0);
                mma_bf16(acc[n2 * 2 + 1], pfh[kt], vl1);
            }
        }
        __syncthreads();                 // all warps done reading V
        if (c + 1 < 32) load_v(k0 + 64); // prefetch V(c+1)
    }

    const float i0 = 1.f / l0, i1 = 1.f / l1;
    const int orow = q0 + wid * 16 + prow;
#pragma unroll
    for (int nt = 0; nt < 16; nt++) {
        int col = h * DV + nt * 8 + pcol2;
        float v0 = acc[nt][0] * i0, v1 = acc[nt][1] * i0;
        float v2 = acc[nt][2] * i1, v3 = acc[nt][3] * i1;
        *(uint32_t*)&aoh[(size_t)orow * HID + col]       = pack_hi(v0, v1);
        *(uint32_t*)&aoh[(size_t)(orow + 8) * HID + col] = pack_hi(v2, v3);
        *(uint32_t*)&aol[(size_t)orow * HID + col]       = pack_lo(v0, v1);
        *(uint32_t*)&aol[(size_t)(orow + 8) * HID + col] = pack_lo(v2, v3);
    }
}

// ---------------------------------------------------------------------------
// launcher
// ---------------------------------------------------------------------------
extern "C" void kernel_launch(void* const* d_in, const int* in_sizes, int n_in,
                              void* d_out, int out_size) {
    const float* hidden  = (const float*)d_in[0];
    const float* mask    = (const float*)d_in[1];
    const float* Wq_lr   = (const float*)d_in[2];
    const float* bq_lr   = (const float*)d_in[3];
    const float* Wq_rope = (const float*)d_in[4];
    const float* bq_rope = (const float*)d_in[5];
    const float* Wq_c    = (const float*)d_in[6];
    const float* bq_c    = (const float*)d_in[7];
    const float* Wkv     = (const float*)d_in[8];
    const float* bkv     = (const float*)d_in[9];
    const float* Wk_rope = (const float*)d_in[10];
    const float* bk_rope = (const float*)d_in[11];
    const float* Wk_c    = (const float*)d_in[12];
    const float* bk_c    = (const float*)d_in[13];
    const float* Wv      = (const float*)d_in[14];
    const float* bv      = (const float*)d_in[15];
    const float* Wo      = (const float*)d_in[16];
    const float* bo      = (const float*)d_in[17];
    float* out = (float*)d_out;

    float *qc, *qr, *kc, *kr, *bkr;
    cudaGetSymbolAddress((void**)&qc,  g_qc);
    cudaGetSymbolAddress((void**)&qr,  g_qr);
    cudaGetSymbolAddress((void**)&kc,  g_kc);
    cudaGetSymbolAddress((void**)&kr,  g_kr);
    cudaGetSymbolAddress((void**)&bkr, g_bkr);

    __nv_bfloat16 *h_hi, *h_lo, *cq_hi, *cq_lo, *ckv_hi, *ckv_lo, *ao_hi, *ao_lo;
    __nv_bfloat16 *Wqlr_hi, *Wqlr_lo, *Wqc_hi, *Wqc_lo, *Wqr_hi, *Wqr_lo;
    __nv_bfloat16 *Wkv_hi, *Wkv_lo, *Wkc_hi, *Wkc_lo, *Wv_hi, *Wv_lo, *Wo_hi, *Wo_lo;
    __nv_bfloat16 *Wkr_hi, *Wkr_lo, *qhi, *qlo, *khi, *klo, *vhi, *vlo;
    cudaGetSymbolAddress((void**)&h_hi,   g_h_hi);   cudaGetSymbolAddress((void**)&h_lo,   g_h_lo);
    cudaGetSymbolAddress((void**)&cq_hi,  g_cq_hi);  cudaGetSymbolAddress((void**)&cq_lo,  g_cq_lo);
    cudaGetSymbolAddress((void**)&ckv_hi, g_ckv_hi); cudaGetSymbolAddress((void**)&ckv_lo, g_ckv_lo);
    cudaGetSymbolAddress((void**)&ao_hi,  g_ao_hi);  cudaGetSymbolAddress((void**)&ao_lo,  g_ao_lo);
    cudaGetSymbolAddress((void**)&Wqlr_hi, g_Wqlr_hi); cudaGetSymbolAddress((void**)&Wqlr_lo, g_Wqlr_lo);
    cudaGetSymbolAddress((void**)&Wqc_hi,  g_Wqc_hi);  cudaGetSymbolAddress((void**)&Wqc_lo,  g_Wqc_lo);
    cudaGetSymbolAddress((void**)&Wqr_hi,  g_Wqr_hi);  cudaGetSymbolAddress((void**)&Wqr_lo,  g_Wqr_lo);
    cudaGetSymbolAddress((void**)&Wkv_hi,  g_Wkv_hi);  cudaGetSymbolAddress((void**)&Wkv_lo,  g_Wkv_lo);
    cudaGetSymbolAddress((void**)&Wkc_hi,  g_Wkc_hi);  cudaGetSymbolAddress((void**)&Wkc_lo,  g_Wkc_lo);
    cudaGetSymbolAddress((void**)&Wv_hi,   g_Wv_hi);   cudaGetSymbolAddress((void**)&Wv_lo,   g_Wv_lo);
    cudaGetSymbolAddress((void**)&Wo_hi,   g_Wo_hi);   cudaGetSymbolAddress((void**)&Wo_lo,   g_Wo_lo);
    cudaGetSymbolAddress((void**)&Wkr_hi,  g_Wkr_hi);  cudaGetSymbolAddress((void**)&Wkr_lo,  g_Wkr_lo);
    cudaGetSymbolAddress((void**)&qhi, g_qhi); cudaGetSymbolAddress((void**)&qlo, g_qlo);
    cudaGetSymbolAddress((void**)&khi, g_khi); cudaGetSymbolAddress((void**)&klo, g_klo);
    cudaGetSymbolAddress((void**)&vhi, g_vhi); cudaGetSymbolAddress((void**)&vlo, g_vlo);

    cudaFuncSetAttribute(mma_gemm4, cudaFuncAttributeMaxDynamicSharedMemorySize, G_SMEM);

    // ---- one mega split launch for all 8 fp32->bf16 splits ----
    SJobs jobs;
    const float* srcs[8] = { hidden, Wq_lr, Wq_c, Wq_rope, Wkv, Wk_c, Wv, Wo };
    __nv_bfloat16* his[8] = { h_hi, Wqlr_hi, Wqc_hi, Wqr_hi, Wkv_hi, Wkc_hi, Wv_hi, Wo_hi };
    __nv_bfloat16* los[8] = { h_lo, Wqlr_lo, Wqc_lo, Wqr_lo, Wkv_lo, Wkc_lo, Wv_lo, Wo_lo };
    int ns[8] = { 2048*4096, 1536*4096, 4096*1536, 2048*1536,
                  512*4096, 4096*512, 4096*512, 4096*4096 };
    int blk = 0;
    for (int i = 0; i < 8; i++) {
        jobs.j[i].x = srcs[i]; jobs.j[i].hi = his[i]; jobs.j[i].lo = los[i];
        jobs.j[i].n4 = ns[i] / 4; jobs.j[i].blk0 = blk;
        blk += (jobs.j[i].n4 + 255) / 256;
    }
    multi_split_kernel<<<blk, 256>>>(jobs);
    pad_krope_kernel<<<(128 * 4096 + 255) / 256, 256>>>(Wk_rope, Wkr_hi, Wkr_lo, bk_rope, bkr);

    const int NONE = 0x7FFFFFFF;

    // ---- G1: A = hidden(K=4096): c_q, c_kv, k_rope in one launch ----
    {
        GJobs g{};
        g.j[0] = { h_hi, h_lo, Wqlr_hi, Wqlr_lo, bq_lr, nullptr, cq_hi, cq_lo, 1536, 4096, 0, 0 };
        g.j[1] = { h_hi, h_lo, Wkv_hi,  Wkv_lo,  bkv,   nullptr, ckv_hi, ckv_lo, 512, 4096, 12, 0 };
        g.j[2] = { h_hi, h_lo, Wkr_hi,  Wkr_lo,  bkr,   kr, nullptr, nullptr, 128, 4096, 16, 0 };
        g.j[3] = g.j[2]; g.j[3].blk0 = NONE;
        mma_gemm4<<<dim3(17, 16), 128, G_SMEM>>>(g);
    }
    // ---- G2+G3: q_c, q_r (A=cq, K=1536) + k_c, v (A=ckv, K=512) ----
    {
        GJobs g{};
        g.j[0] = { cq_hi, cq_lo, Wqc_hi, Wqc_lo, bq_c,    qc, nullptr, nullptr, 4096, 1536, 0,  0 };
        g.j[1] = { cq_hi, cq_lo, Wqr_hi, Wqr_lo, bq_rope, qr, nullptr, nullptr, 2048, 1536, 32, 0 };
        g.j[2] = { ckv_hi, ckv_lo, Wkc_hi, Wkc_lo, bk_c,  kc, nullptr, nullptr, 4096, 512, 48, 0 };
        g.j[3] = { ckv_hi, ckv_lo, Wv_hi,  Wv_lo,  bv, nullptr, vhi, vlo,       4096, 512, 80, 0 };
        mma_gemm4<<<dim3(112, 16), 128, G_SMEM>>>(g);
    }

    // fuse kernels apply RoPE inline (no separate rope launches)
    fuse_q_kernel<<<8192, 256>>>(qc, qr, qhi, qlo);
    fuse_k_kernel<<<8192, 256>>>(kc, kr, khi, klo);

    cudaFuncSetAttribute(attn_mma_kernel, cudaFuncAttributeMaxDynamicSharedMemorySize, ATT_SMEM);
    attn_mma_kernel<<<dim3(S_LEN / 128, NH), 256, ATT_SMEM>>>(
        qhi, qlo, khi, klo, vhi, vlo, mask, ao_hi, ao_lo);

    // ---- G4: out = ao @ Wo^T ----
    {
        GJobs g{};
        g.j[0] = { ao_hi, ao_lo, Wo_hi, Wo_lo, bo, out, nullptr, nullptr, 4096, 4096, 0, 0 };
        g.j[1] = g.j[0]; g.j[1].blk0 = NONE;
        g.j[2] = g.j[0]; g.j[2].blk0 = NONE;
        g.j[3] = g.j[0]; g.j[3].blk0 = NONE;
        mma_gemm4<<<dim3(32, 16), 128, G_SMEM>>>(g);
    }
}

// round 10
// speedup vs baseline: 5.4867x; 1.0891x over previous
#include <cuda_runtime.h>
#include <cuda_bf16.h>
#include <math.h>
#include <stdint.h>

#define S_LEN 2048
#define HID   4096
#define NH    32
#define DQK   192
#define DV    128

// ---------------------------------------------------------------------------
// scratch (device globals; no allocations allowed)
// ---------------------------------------------------------------------------
__device__ float g_qc [2048*4096];
__device__ float g_qr [2048*2048];
__device__ float g_kc [2048*4096];
__device__ float g_kr [2048*128];
__device__ float g_bkr[128];

__device__ __align__(16) __nv_bfloat16 g_h_hi [2048*4096], g_h_lo [2048*4096];
__device__ __align__(16) __nv_bfloat16 g_cq_hi[2048*1536], g_cq_lo[2048*1536];
__device__ __align__(16) __nv_bfloat16 g_ckv_hi[2048*512], g_ckv_lo[2048*512];
__device__ __align__(16) __nv_bfloat16 g_ao_hi[2048*4096], g_ao_lo[2048*4096];
__device__ __align__(16) __nv_bfloat16 g_Wqlr_hi[1536*4096], g_Wqlr_lo[1536*4096];
__device__ __align__(16) __nv_bfloat16 g_Wqc_hi [4096*1536], g_Wqc_lo [4096*1536];
__device__ __align__(16) __nv_bfloat16 g_Wqr_hi [2048*1536], g_Wqr_lo [2048*1536];
__device__ __align__(16) __nv_bfloat16 g_Wkv_hi [512*4096],  g_Wkv_lo [512*4096];
__device__ __align__(16) __nv_bfloat16 g_Wkc_hi [4096*512],  g_Wkc_lo [4096*512];
__device__ __align__(16) __nv_bfloat16 g_Wv_hi  [4096*512],  g_Wv_lo  [4096*512];
__device__ __align__(16) __nv_bfloat16 g_Wo_hi  [4096*4096], g_Wo_lo  [4096*4096];
__device__ __align__(16) __nv_bfloat16 g_Wkr_hi [128*4096],  g_Wkr_lo [128*4096];

__device__ __align__(16) __nv_bfloat16 g_qhi[2048*32*192], g_qlo[2048*32*192];
__device__ __align__(16) __nv_bfloat16 g_khi[2048*32*192], g_klo[2048*32*192];
__device__ __align__(16) __nv_bfloat16 g_vhi[2048*4096],   g_vlo[2048*4096];

// ---------------------------------------------------------------------------
// small PTX helpers
// ---------------------------------------------------------------------------
__device__ __forceinline__ uint32_t smem_u32(const void* p) {
    uint32_t a;
    asm("{ .reg .u64 t; cvta.to.shared.u64 t, %1; cvt.u32.u64 %0, t; }" : "=r"(a) : "l"(p));
    return a;
}
#define CP_ASYNC16(dst_u32, src_ptr) \
    asm volatile("cp.async.cg.shared.global [%0], [%1], 16;" \
                 :: "r"(dst_u32), "l"(__cvta_generic_to_global(src_ptr)) : "memory")
#define CP_COMMIT() asm volatile("cp.async.commit_group;" ::: "memory")
#define CP_WAIT(n)  asm volatile("cp.async.wait_group %0;" :: "n"(n) : "memory")

__device__ __forceinline__ void ldmx4(uint32_t& r0, uint32_t& r1, uint32_t& r2, uint32_t& r3,
                                      uint32_t addr) {
    asm volatile("ldmatrix.sync.aligned.m8n8.x4.shared.b16 {%0,%1,%2,%3}, [%4];"
                 : "=r"(r0), "=r"(r1), "=r"(r2), "=r"(r3) : "r"(addr));
}
__device__ __forceinline__ void ldmx4t(uint32_t& r0, uint32_t& r1, uint32_t& r2, uint32_t& r3,
                                       uint32_t addr) {
    asm volatile("ldmatrix.sync.aligned.m8n8.x4.trans.shared.b16 {%0,%1,%2,%3}, [%4];"
                 : "=r"(r0), "=r"(r1), "=r"(r2), "=r"(r3) : "r"(addr));
}
__device__ __forceinline__ void mma_bf16(float* d, const uint32_t* a, const uint32_t* b) {
    asm volatile("mma.sync.aligned.m16n8k16.row.col.f32.bf16.bf16.f32 "
                 "{%0,%1,%2,%3}, {%4,%5,%6,%7}, {%8,%9}, {%0,%1,%2,%3};"
                 : "+f"(d[0]), "+f"(d[1]), "+f"(d[2]), "+f"(d[3])
                 : "r"(a[0]), "r"(a[1]), "r"(a[2]), "r"(a[3]), "r"(b[0]), "r"(b[1]));
}
__device__ __forceinline__ uint32_t pack_hi(float a, float b) {
    __nv_bfloat16 ha = __float2bfloat16(a), hb = __float2bfloat16(b);
    return (uint32_t)__bfloat16_as_ushort(ha) | ((uint32_t)__bfloat16_as_ushort(hb) << 16);
}
__device__ __forceinline__ uint32_t pack_lo(float a, float b) {
    __nv_bfloat16 ha = __float2bfloat16(a), hb = __float2bfloat16(b);
    __nv_bfloat16 la = __float2bfloat16(a - __bfloat162float(ha));
    __nv_bfloat16 lb = __float2bfloat16(b - __bfloat162float(hb));
    return (uint32_t)__bfloat16_as_ushort(la) | ((uint32_t)__bfloat16_as_ushort(lb) << 16);
}

// ---------------------------------------------------------------------------
// mega split
// ---------------------------------------------------------------------------
struct SJob { const float* x; __nv_bfloat16* hi; __nv_bfloat16* lo; int n4; int blk0; };
struct SJobs { SJob j[8]; };

__global__ void multi_split_kernel(SJobs jobs) {
    int b = blockIdx.x;
    int ji = 0;
#pragma unroll
    for (int t = 1; t < 8; t++)
        if (b >= jobs.j[t].blk0) ji = t;
    const SJob jb = jobs.j[ji];
    int i = (b - jb.blk0) * 256 + threadIdx.x;
    if (i >= jb.n4) return;
    float4 v = ((const float4*)jb.x)[i];
    ((uint32_t*)jb.hi)[i*2 + 0] = pack_hi(v.x, v.y);
    ((uint32_t*)jb.hi)[i*2 + 1] = pack_hi(v.z, v.w);
    ((uint32_t*)jb.lo)[i*2 + 0] = pack_lo(v.x, v.y);
    ((uint32_t*)jb.lo)[i*2 + 1] = pack_lo(v.z, v.w);
}

__global__ void pad_krope_kernel(const float* __restrict__ W,
                                 __nv_bfloat16* __restrict__ hi,
                                 __nv_bfloat16* __restrict__ lo,
                                 const float* __restrict__ b,
                                 float* __restrict__ bp) {
    int i = blockIdx.x * blockDim.x + threadIdx.x;
    if (i < 128) bp[i] = (i < 64) ? b[i] : 0.f;
    if (i >= 128 * 4096) return;
    int r = i >> 12;
    float v = (r < 64) ? W[(size_t)r * 4096 + (i & 4095)] : 0.f;
    __nv_bfloat16 h = __float2bfloat16(v);
    hi[i] = h;
    lo[i] = __float2bfloat16(v - __bfloat162float(h));
}

// ---------------------------------------------------------------------------
// batched GEMM: 3-stage cp.async pipeline, ONE barrier per chunk,
// 64B rows with XOR bank swizzle (conflict-free ldmatrix, in-bounds).
// CTA 128x128, 4 warps (2x2), warp tile 64x64, BK=32.
// ---------------------------------------------------------------------------
#define OA_HI 0
#define OA_LO 8192
#define OW_HI 16384
#define OW_LO 24576
#define ST_BUF 32768
#define G_SMEM (3 * ST_BUF)

// swizzled byte offset within a 64B-row tile: row r, 16B-chunk c (0..3).
// bank-unit = (4r + c') mod 8: even rows hit units {0..3}, odd rows {4..7},
// and c' = c ^ ((r>>1)&3) makes same-parity rows within any 8-row group
// hit distinct units -> conflict-free ldmatrix.
__device__ __forceinline__ uint32_t swz64(int r, int c) {
    return (uint32_t)(r * 64 + ((c ^ ((r >> 1) & 3)) << 4));
}

struct GJob {
    const __nv_bfloat16 *Ahi, *Alo, *Whi, *Wlo;
    const float* bias;
    float* Cf;
    __nv_bfloat16 *Chi, *Clo;
    int N, K, blk0, pad_;
};
struct GJobs { GJob j[4]; };

__global__ void __launch_bounds__(128)
mma_gemm5(GJobs jobs) {
    extern __shared__ char gsm[];
    const uint32_t s0 = smem_u32(gsm);
    const int tid = threadIdx.x, wid = tid >> 5, lane = tid & 31;
    const int warp_m = wid >> 1, warp_n = wid & 1;

    int bx = blockIdx.x;
    int ji = 0;
#pragma unroll
    for (int t = 1; t < 4; t++)
        if (bx >= jobs.j[t].blk0) ji = t;
    const GJob jb = jobs.j[ji];
    const int col0 = (bx - jb.blk0) * 128;
    const int row0 = blockIdx.y * 128;
    const int K = jb.K, N = jb.N;

    const int a_row = (lane & 7) + ((lane >> 3) & 1) * 8;
    const int b_row = (lane & 7) + (lane >> 4) * 8;
    const int a_c   = (lane >> 4);        // chunk offset within k16 (A)
    const int b_c   = ((lane >> 3) & 1);  // chunk offset within k16 (W)

    uint32_t adA[4][2], adW[4][2];
#pragma unroll
    for (int mt = 0; mt < 4; mt++) {
        int rr = warp_m * 64 + mt * 16 + a_row;
#pragma unroll
        for (int ks = 0; ks < 2; ks++)
            adA[mt][ks] = OA_HI + swz64(rr, ks * 2 + a_c);
    }
#pragma unroll
    for (int np = 0; np < 4; np++) {
        int rr = warp_n * 64 + np * 16 + b_row;
#pragma unroll
        for (int ks = 0; ks < 2; ks++)
            adW[np][ks] = OW_HI + swz64(rr, ks * 2 + b_c);
    }

    const int kc = K >> 5;

    float acc[4][8][4];
#pragma unroll
    for (int mt = 0; mt < 4; mt++)
#pragma unroll
        for (int nt = 0; nt < 8; nt++)
#pragma unroll
            for (int e = 0; e < 4; e++) acc[mt][nt][e] = 0.f;

    auto load_chunk = [&](int c, int st) {
        const int kk = c << 5;
        const uint32_t base = s0 + st * ST_BUF;
#pragma unroll
        for (int i = 0; i < 4; i++) {
            int idx = tid + i * 128;
            int r = idx >> 2, cb = idx & 3;
            uint32_t doff = swz64(r, cb);
            size_t src = (size_t)(row0 + r) * K + kk + cb * 8;
            CP_ASYNC16(base + OA_HI + doff, jb.Ahi + src);
            CP_ASYNC16(base + OA_LO + doff, jb.Alo + src);
        }
#pragma unroll
        for (int i = 0; i < 4; i++) {
            int idx = tid + i * 128;
            int r = idx >> 2, cb = idx & 3;
            uint32_t doff = swz64(r, cb);
            size_t src = (size_t)(col0 + r) * K + kk + cb * 8;
            CP_ASYNC16(base + OW_HI + doff, jb.Whi + src);
            CP_ASYNC16(base + OW_LO + doff, jb.Wlo + src);
        }
        CP_COMMIT();
    };

    load_chunk(0, 0);
    load_chunk(1, 1);

    int st = 0, ls = 2;
    for (int c = 0; c < kc; c++) {
        if (c + 1 < kc) { CP_WAIT(1); } else { CP_WAIT(0); }
        __syncthreads();
        if (c + 2 < kc) load_chunk(c + 2, ls);
        const uint32_t base = s0 + st * ST_BUF;

#pragma unroll
        for (int ks = 0; ks < 2; ks++) {
            uint32_t ah[4][4], al[4][4];
#pragma unroll
            for (int mt = 0; mt < 4; mt++) {
                uint32_t ra = base + adA[mt][ks];
                ldmx4(ah[mt][0], ah[mt][1], ah[mt][2], ah[mt][3], ra);
                ldmx4(al[mt][0], al[mt][1], al[mt][2], al[mt][3], ra + (OA_LO - OA_HI));
            }
#pragma unroll
            for (int np = 0; np < 4; np++) {
                uint32_t bh[4], bl[4];
                uint32_t rb = base + adW[np][ks];
                ldmx4(bh[0], bh[1], bh[2], bh[3], rb);
                ldmx4(bl[0], bl[1], bl[2], bl[3], rb + (OW_LO - OW_HI));
#pragma unroll
                for (int j = 0; j < 2; j++) {
                    uint32_t b2h[2] = { bh[j * 2], bh[j * 2 + 1] };
                    uint32_t b2l[2] = { bl[j * 2], bl[j * 2 + 1] };
                    const int nt = np * 2 + j;
#pragma unroll
                    for (int mt = 0; mt < 4; mt++) mma_bf16(acc[mt][nt], ah[mt], b2h);
#pragma unroll
                    for (int mt = 0; mt < 4; mt++) mma_bf16(acc[mt][nt], al[mt], b2h);
#pragma unroll
                    for (int mt = 0; mt < 4; mt++) mma_bf16(acc[mt][nt], ah[mt], b2l);
                }
            }
        }
        st = (st == 2) ? 0 : st + 1;
        ls = (ls == 2) ? 0 : ls + 1;
    }

    const int rbase = row0 + warp_m * 64 + (lane >> 2);
    const int cbase = col0 + warp_n * 64 + (lane & 3) * 2;
#pragma unroll
    for (int mt = 0; mt < 4; mt++) {
#pragma unroll
        for (int nt = 0; nt < 8; nt++) {
            const int cc = cbase + nt * 8;
            const float b0 = jb.bias[cc], b1 = jb.bias[cc + 1];
            const int r0 = rbase + mt * 16;
            float v0 = acc[mt][nt][0] + b0, v1 = acc[mt][nt][1] + b1;
            float v2 = acc[mt][nt][2] + b0, v3 = acc[mt][nt][3] + b1;
            if (jb.Cf) {
                *(float2*)&jb.Cf[(size_t)r0 * N + cc] = make_float2(v0, v1);
                *(float2*)&jb.Cf[(size_t)(r0 + 8) * N + cc] = make_float2(v2, v3);
            }
            if (jb.Chi) {
                *(uint32_t*)&jb.Chi[(size_t)r0 * N + cc]       = pack_hi(v0, v1);
                *(uint32_t*)&jb.Chi[(size_t)(r0 + 8) * N + cc] = pack_hi(v2, v3);
                *(uint32_t*)&jb.Clo[(size_t)r0 * N + cc]       = pack_lo(v0, v1);
                *(uint32_t*)&jb.Clo[(size_t)(r0 + 8) * N + cc] = pack_lo(v2, v3);
            }
        }
    }
}

// ---------------- concat + inline RoPE + RMSnorm -> bf16 hi/lo ----------------
__global__ void fuse_q_kernel(const float* __restrict__ qc,
                              const float* __restrict__ qr,
                              __nv_bfloat16* __restrict__ qh,
                              __nv_bfloat16* __restrict__ ql) {
    const int gw   = (blockIdx.x * blockDim.x + threadIdx.x) >> 5;
    const int lane = threadIdx.x & 31;
    const int s = gw >> 5, h = gw & 31;
    float vals[6]; float ss = 0.f;
#pragma unroll
    for (int t = 0; t < 6; t++) {
        int d = lane + 32 * t;
        float x;
        if (d < 128) {
            x = qc[(size_t)s * HID + h * 128 + d];
        } else {
            int j = h * 64 + (d - 128);
            int base = (j < 1024) ? j : j - 1024;
            float ex  = (float)(2 * base) / 2048.0f;
            float inv = 1.0f / powf(10000.0f, ex);
            float sn, c;
            sincosf((float)s * inv, &sn, &c);
            if (j < 1024)
                x = qr[(size_t)s * 2048 + j] * c - qr[(size_t)s * 2048 + j + 1024] * sn;
            else
                x = qr[(size_t)s * 2048 + j] * c + qr[(size_t)s * 2048 + base] * sn;
        }
        vals[t] = x; ss += x * x;
    }
#pragma unroll
    for (int o = 16; o; o >>= 1) ss += __shfl_xor_sync(0xffffffffu, ss, o);
    float r = rsqrtf(ss * (1.f / 192.f) + 1.1920929e-7f);
#pragma unroll
    for (int t = 0; t < 6; t++) {
        float x = vals[t] * r;
        __nv_bfloat16 hb = __float2bfloat16(x);
        size_t o_ = ((size_t)s * NH + h) * DQK + lane + 32 * t;
        qh[o_] = hb;
        ql[o_] = __float2bfloat16(x - __bfloat162float(hb));
    }
}

__global__ void fuse_k_kernel(const float* __restrict__ kc,
                              const float* __restrict__ kr,
                              __nv_bfloat16* __restrict__ kh,
                              __nv_bfloat16* __restrict__ kl) {
    const int gw   = (blockIdx.x * blockDim.x + threadIdx.x) >> 5;
    const int lane = threadIdx.x & 31;
    const int s = gw >> 5, h = gw & 31;
    float vals[6]; float ss = 0.f;
#pragma unroll
    for (int t = 0; t < 6; t++) {
        int d = lane + 32 * t;
        float x;
        if (d < 128) {
            x = kc[(size_t)s * HID + h * 128 + d];
        } else {
            int j = d - 128;
            int base = (j < 32) ? j : j - 32;
            float ex  = (float)(2 * base) / 64.0f;
            float inv = 1.0f / powf(10000.0f, ex);
            float sn, c;
            sincosf((float)s * inv, &sn, &c);
            if (j < 32)
                x = kr[(size_t)s * 128 + j] * c - kr[(size_t)s * 128 + j + 32] * sn;
            else
                x = kr[(size_t)s * 128 + j] * c + kr[(size_t)s * 128 + base] * sn;
        }
        vals[t] = x; ss += x * x;
    }
#pragma unroll
    for (int o = 16; o; o >>= 1) ss += __shfl_xor_sync(0xffffffffu, ss, o);
    float r = rsqrtf(ss * (1.f / 192.f) + 1.1920929e-7f);
#pragma unroll
    for (int t = 0; t < 6; t++) {
        float x = vals[t] * r;
        __nv_bfloat16 hb = __float2bfloat16(x);
        size_t o_ = ((size_t)s * NH + h) * DQK + lane + 32 * t;
        kh[o_] = hb;
        kl[o_] = __float2bfloat16(x - __bfloat162float(hb));
    }
}

// ---------------------------------------------------------------------------
// flash attention: register P, double-buffered V (2 barriers/chunk),
// hoisted K-fragments with term-major MMA issue.
// ---------------------------------------------------------------------------
#define OQH 0
#define OQL (128*400)
#define OKH (2*128*400)
#define OKL (OKH + 64*400)
#define OVB (OKL + 64*400)
#define VHALF (64*272)
#define VBUF (2*VHALF)
#define ATT_SMEM (OVB + 2*VBUF)   // 223232 bytes

__global__ void __launch_bounds__(256, 1)
attn_mma_kernel(const __nv_bfloat16* __restrict__ qhi, const __nv_bfloat16* __restrict__ qlo,
                const __nv_bfloat16* __restrict__ khi, const __nv_bfloat16* __restrict__ klo,
                const __nv_bfloat16* __restrict__ vhi, const __nv_bfloat16* __restrict__ vlo,
                const float* __restrict__ mask,
                __nv_bfloat16* __restrict__ aoh, __nv_bfloat16* __restrict__ aol) {
    extern __shared__ char smraw[];
    const uint32_t s0 = smem_u32(smraw);
    const int h = blockIdx.y, q0 = blockIdx.x * 128;
    const int tid = threadIdx.x, wid = tid >> 5, lane = tid & 31;

    for (int i = tid; i < 3072; i += 256) {
        int r = i / 24, cb = i % 24;
        size_t src = ((size_t)(q0 + r) * NH + h) * DQK + cb * 8;
        CP_ASYNC16(s0 + OQH + r * 400 + cb * 16, qhi + src);
        CP_ASYNC16(s0 + OQL + r * 400 + cb * 16, qlo + src);
    }
    CP_COMMIT();

    auto load_k = [&](int k0) {
        for (int i = tid; i < 1536; i += 256) {
            int r = i / 24, cb = i % 24;
            size_t src = ((size_t)(k0 + r) * NH + h) * DQK + cb * 8;
            CP_ASYNC16(s0 + OKH + r * 400 + cb * 16, khi + src);
            CP_ASYNC16(s0 + OKL + r * 400 + cb * 16, klo + src);
        }
        CP_COMMIT();
    };
    auto load_v = [&](int k0, int buf) {
        const uint32_t vb = s0 + OVB + buf * VBUF;
        for (int i = tid; i < 1024; i += 256) {
            int r = i / 16, cb = i % 16;
            size_t src = (size_t)(k0 + r) * HID + h * DV + cb * 8;
            CP_ASYNC16(vb + r * 272 + cb * 16, vhi + src);
            CP_ASYNC16(vb + VHALF + r * 272 + cb * 16, vlo + src);
        }
        CP_COMMIT();
    };
    load_k(0);
    load_v(0, 0);

    const float scale = 1.0f / sqrtf(192.0f);
    float m0 = -1e30f, m1 = -1e30f, l0 = 0.f, l1 = 0.f;
    float acc[16][4];
#pragma unroll
    for (int nt = 0; nt < 16; nt++)
#pragma unroll
        for (int e = 0; e < 4; e++) acc[nt][e] = 0.f;

    const int a_r  = (lane & 7) + ((lane >> 3) & 1) * 8;
    const int a_k  = (lane >> 4) * 8;
    const int bk_r = (lane & 7) + (lane >> 4) * 8;
    const int bk_k = ((lane >> 3) & 1) * 8;
    const int prow  = lane >> 2;
    const int pcol2 = (lane & 3) * 2;

    for (int c = 0; c < 32; c++) {
        const int k0 = c * 64;
        CP_WAIT(0);
        __syncthreads();
        if (c + 1 < 32) load_v(k0 + 64, (c + 1) & 1);

        // ---- S = Q K^T (hoisted K frags, term-major issue) ----
        float sacc[8][4];
#pragma unroll
        for (int nt = 0; nt < 8; nt++)
#pragma unroll
            for (int e = 0; e < 4; e++) sacc[nt][e] = 0.f;

#pragma unroll
        for (int kt = 0; kt < 12; kt++) {
            uint32_t ah[4], al[4];
            ldmx4(ah[0], ah[1], ah[2], ah[3],
                  s0 + OQH + (wid * 16 + a_r) * 400 + (kt * 16 + a_k) * 2);
            ldmx4(al[0], al[1], al[2], al[3],
                  s0 + OQL + (wid * 16 + a_r) * 400 + (kt * 16 + a_k) * 2);
            uint32_t bh[4][4], bl[4][4];
#pragma unroll
            for (int n2 = 0; n2 < 4; n2++) {
                uint32_t rb = (n2 * 16 + bk_r) * 400 + (kt * 16 + bk_k) * 2;
                ldmx4(bh[n2][0], bh[n2][1], bh[n2][2], bh[n2][3], s0 + OKH + rb);
                ldmx4(bl[n2][0], bl[n2][1], bl[n2][2], bl[n2][3], s0 + OKL + rb);
            }
#pragma unroll
            for (int n2 = 0; n2 < 4; n2++) {
                mma_bf16(sacc[n2 * 2],     ah, &bh[n2][0]);
                mma_bf16(sacc[n2 * 2 + 1], ah, &bh[n2][2]);
            }
#pragma unroll
            for (int n2 = 0; n2 < 4; n2++) {
                mma_bf16(sacc[n2 * 2],     al, &bh[n2][0]);
                mma_bf16(sacc[n2 * 2 + 1], al, &bh[n2][2]);
            }
#pragma unroll
            for (int n2 = 0; n2 < 4; n2++) {
                mma_bf16(sacc[n2 * 2],     ah, &bl[n2][0]);
                mma_bf16(sacc[n2 * 2 + 1], ah, &bl[n2][2]);
            }
        }
        __syncthreads();
        if (c + 1 < 32) load_k(k0 + 64);

        // ---- softmax (warp-local rows), P packed into A-frags ----
        const int rg0 = q0 + wid * 16 + prow;
        float sc[8][4];
        float mx0 = -1e30f, mx1 = -1e30f;
#pragma unroll
        for (int nt = 0; nt < 8; nt++) {
            int col = k0 + nt * 8 + pcol2;
            float2 mk0 = *(const float2*)&mask[(size_t)rg0 * S_LEN + col];
            float2 mk1 = *(const float2*)&mask[(size_t)(rg0 + 8) * S_LEN + col];
            sc[nt][0] = sacc[nt][0] * scale + mk0.x;
            sc[nt][1] = sacc[nt][1] * scale + mk0.y;
            sc[nt][2] = sacc[nt][2] * scale + mk1.x;
            sc[nt][3] = sacc[nt][3] * scale + mk1.y;
            mx0 = fmaxf(mx0, fmaxf(sc[nt][0], sc[nt][1]));
            mx1 = fmaxf(mx1, fmaxf(sc[nt][2], sc[nt][3]));
        }
        mx0 = fmaxf(mx0, __shfl_xor_sync(0xffffffffu, mx0, 1));
        mx0 = fmaxf(mx0, __shfl_xor_sync(0xffffffffu, mx0, 2));
        mx1 = fmaxf(mx1, __shfl_xor_sync(0xffffffffu, mx1, 1));
        mx1 = fmaxf(mx1, __shfl_xor_sync(0xffffffffu, mx1, 2));
        float mn0 = fmaxf(m0, mx0), mn1 = fmaxf(m1, mx1);
        float al0 = __expf(m0 - mn0), al1 = __expf(m1 - mn1);
        m0 = mn0; m1 = mn1;

        uint32_t pfh[4][4], pfl[4][4];
        float ps0 = 0.f, ps1 = 0.f;
#pragma unroll
        for (int nt = 0; nt < 8; nt++) {
            float p00 = __expf(sc[nt][0] - mn0), p01 = __expf(sc[nt][1] - mn0);
            float p10 = __expf(sc[nt][2] - mn1), p11 = __expf(sc[nt][3] - mn1);
            ps0 += p00 + p01; ps1 += p10 + p11;
            const int kt = nt >> 1, sl = (nt & 1) * 2;
            pfh[kt][sl + 0] = pack_hi(p00, p01);
            pfh[kt][sl + 1] = pack_hi(p10, p11);
            pfl[kt][sl + 0] = pack_lo(p00, p01);
            pfl[kt][sl + 1] = pack_lo(p10, p11);
        }
        ps0 += __shfl_xor_sync(0xffffffffu, ps0, 1);
        ps0 += __shfl_xor_sync(0xffffffffu, ps0, 2);
        ps1 += __shfl_xor_sync(0xffffffffu, ps1, 1);
        ps1 += __shfl_xor_sync(0xffffffffu, ps1, 2);
        l0 = al0 * l0 + ps0;
        l1 = al1 * l1 + ps1;
#pragma unroll
        for (int nt = 0; nt < 16; nt++) {
            acc[nt][0] *= al0; acc[nt][1] *= al0;
            acc[nt][2] *= al1; acc[nt][3] *= al1;
        }

        // ---- O += P V (register P; V buffer c&1) ----
        const uint32_t vb = s0 + OVB + (c & 1) * VBUF;
#pragma unroll
        for (int kt = 0; kt < 4; kt++) {
#pragma unroll
            for (int n2 = 0; n2 < 8; n2++) {
                uint32_t vh[4], vl[4];
                uint32_t rv = (kt * 16 + a_r) * 272 + (n2 * 16 + a_k) * 2;
                ldmx4t(vh[0], vh[1], vh[2], vh[3], vb + rv);
                ldmx4t(vl[0], vl[1], vl[2], vl[3], vb + VHALF + rv);
                uint32_t vh0[2] = { vh[0], vh[1] }, vh1[2] = { vh[2], vh[3] };
                uint32_t vl0[2] = { vl[0], vl[1] }, vl1[2] = { vl[2], vl[3] };
                mma_bf16(acc[n2 * 2],     pfh[kt], vh0);
                mma_bf16(acc[n2 * 2 + 1], pfh[kt], vh1);
                mma_bf16(acc[n2 * 2],     pfl[kt], vh0);
                mma_bf16(acc[n2 * 2 + 1], pfl[kt], vh1);
                mma_bf16(acc[n2 * 2],     pfh[kt], vl0);
                mma_bf16(acc[n2 * 2 + 1], pfh[kt], vl1);
            }
        }
    }

    const float i0 = 1.f / l0, i1 = 1.f / l1;
    const int orow = q0 + wid * 16 + prow;
#pragma unroll
    for (int nt = 0; nt < 16; nt++) {
        int col = h * DV + nt * 8 + pcol2;
        float v0 = acc[nt][0] * i0, v1 = acc[nt][1] * i0;
        float v2 = acc[nt][2] * i1, v3 = acc[nt][3] * i1;
        *(uint32_t*)&aoh[(size_t)orow * HID + col]       = pack_hi(v0, v1);
        *(uint32_t*)&aoh[(size_t)(orow + 8) * HID + col] = pack_hi(v2, v3);
        *(uint32_t*)&aol[(size_t)orow * HID + col]       = pack_lo(v0, v1);
        *(uint32_t*)&aol[(size_t)(orow + 8) * HID + col] = pack_lo(v2, v3);
    }
}

// ---------------------------------------------------------------------------
// launcher
// ---------------------------------------------------------------------------
extern "C" void kernel_launch(void* const* d_in, const int* in_sizes, int n_in,
                              void* d_out, int out_size) {
    const float* hidden  = (const float*)d_in[0];
    const float* mask    = (const float*)d_in[1];
    const float* Wq_lr   = (const float*)d_in[2];
    const float* bq_lr   = (const float*)d_in[3];
    const float* Wq_rope = (const float*)d_in[4];
    const float* bq_rope = (const float*)d_in[5];
    const float* Wq_c    = (const float*)d_in[6];
    const float* bq_c    = (const float*)d_in[7];
    const float* Wkv     = (const float*)d_in[8];
    const float* bkv     = (const float*)d_in[9];
    const float* Wk_rope = (const float*)d_in[10];
    const float* bk_rope = (const float*)d_in[11];
    const float* Wk_c    = (const float*)d_in[12];
    const float* bk_c    = (const float*)d_in[13];
    const float* Wv      = (const float*)d_in[14];
    const float* bv      = (const float*)d_in[15];
    const float* Wo      = (const float*)d_in[16];
    const float* bo      = (const float*)d_in[17];
    float* out = (float*)d_out;

    float *qc, *qr, *kc, *kr, *bkr;
    cudaGetSymbolAddress((void**)&qc,  g_qc);
    cudaGetSymbolAddress((void**)&qr,  g_qr);
    cudaGetSymbolAddress((void**)&kc,  g_kc);
    cudaGetSymbolAddress((void**)&kr,  g_kr);
    cudaGetSymbolAddress((void**)&bkr, g_bkr);

    __nv_bfloat16 *h_hi, *h_lo, *cq_hi, *cq_lo, *ckv_hi, *ckv_lo, *ao_hi, *ao_lo;
    __nv_bfloat16 *Wqlr_hi, *Wqlr_lo, *Wqc_hi, *Wqc_lo, *Wqr_hi, *Wqr_lo;
    __nv_bfloat16 *Wkv_hi, *Wkv_lo, *Wkc_hi, *Wkc_lo, *Wv_hi, *Wv_lo, *Wo_hi, *Wo_lo;
    __nv_bfloat16 *Wkr_hi, *Wkr_lo, *qhi, *qlo, *khi, *klo, *vhi, *vlo;
    cudaGetSymbolAddress((void**)&h_hi,   g_h_hi);   cudaGetSymbolAddress((void**)&h_lo,   g_h_lo);
    cudaGetSymbolAddress((void**)&cq_hi,  g_cq_hi);  cudaGetSymbolAddress((void**)&cq_lo,  g_cq_lo);
    cudaGetSymbolAddress((void**)&ckv_hi, g_ckv_hi); cudaGetSymbolAddress((void**)&ckv_lo, g_ckv_lo);
    cudaGetSymbolAddress((void**)&ao_hi,  g_ao_hi);  cudaGetSymbolAddress((void**)&ao_lo,  g_ao_lo);
    cudaGetSymbolAddress((void**)&Wqlr_hi, g_Wqlr_hi); cudaGetSymbolAddress((void**)&Wqlr_lo, g_Wqlr_lo);
    cudaGetSymbolAddress((void**)&Wqc_hi,  g_Wqc_hi);  cudaGetSymbolAddress((void**)&Wqc_lo,  g_Wqc_lo);
    cudaGetSymbolAddress((void**)&Wqr_hi,  g_Wqr_hi);  cudaGetSymbolAddress((void**)&Wqr_lo,  g_Wqr_lo);
    cudaGetSymbolAddress((void**)&Wkv_hi,  g_Wkv_hi);  cudaGetSymbolAddress((void**)&Wkv_lo,  g_Wkv_lo);
    cudaGetSymbolAddress((void**)&Wkc_hi,  g_Wkc_hi);  cudaGetSymbolAddress((void**)&Wkc_lo,  g_Wkc_lo);
    cudaGetSymbolAddress((void**)&Wv_hi,   g_Wv_hi);   cudaGetSymbolAddress((void**)&Wv_lo,   g_Wv_lo);
    cudaGetSymbolAddress((void**)&Wo_hi,   g_Wo_hi);   cudaGetSymbolAddress((void**)&Wo_lo,   g_Wo_lo);
    cudaGetSymbolAddress((void**)&Wkr_hi,  g_Wkr_hi);  cudaGetSymbolAddress((void**)&Wkr_lo,  g_Wkr_lo);
    cudaGetSymbolAddress((void**)&qhi, g_qhi); cudaGetSymbolAddress((void**)&qlo, g_qlo);
    cudaGetSymbolAddress((void**)&khi, g_khi); cudaGetSymbolAddress((void**)&klo, g_klo);
    cudaGetSymbolAddress((void**)&vhi, g_vhi); cudaGetSymbolAddress((void**)&vlo, g_vlo);

    cudaFuncSetAttribute(mma_gemm5, cudaFuncAttributeMaxDynamicSharedMemorySize, G_SMEM);

    SJobs jobs;
    const float* srcs[8] = { hidden, Wq_lr, Wq_c, Wq_rope, Wkv, Wk_c, Wv, Wo };
    __nv_bfloat16* his[8] = { h_hi, Wqlr_hi, Wqc_hi, Wqr_hi, Wkv_hi, Wkc_hi, Wv_hi, Wo_hi };
    __nv_bfloat16* los[8] = { h_lo, Wqlr_lo, Wqc_lo, Wqr_lo, Wkv_lo, Wkc_lo, Wv_lo, Wo_lo };
    int ns[8] = { 2048*4096, 1536*4096, 4096*1536, 2048*1536,
                  512*4096, 4096*512, 4096*512, 4096*4096 };
    int blk = 0;
    for (int i = 0; i < 8; i++) {
        jobs.j[i].x = srcs[i]; jobs.j[i].hi = his[i]; jobs.j[i].lo = los[i];
        jobs.j[i].n4 = ns[i] / 4; jobs.j[i].blk0 = blk;
        blk += (jobs.j[i].n4 + 255) / 256;
    }
    multi_split_kernel<<<blk, 256>>>(jobs);
    pad_krope_kernel<<<(128 * 4096 + 255) / 256, 256>>>(Wk_rope, Wkr_hi, Wkr_lo, bk_rope, bkr);

    const int NONE = 0x7FFFFFFF;

    // G1: A = hidden (K=4096): c_q, c_kv, k_rope
    {
        GJobs g{};
        g.j[0] = { h_hi, h_lo, Wqlr_hi, Wqlr_lo, bq_lr, nullptr, cq_hi, cq_lo, 1536, 4096, 0, 0 };
        g.j[1] = { h_hi, h_lo, Wkv_hi,  Wkv_lo,  bkv,   nullptr, ckv_hi, ckv_lo, 512, 4096, 12, 0 };
        g.j[2] = { h_hi, h_lo, Wkr_hi,  Wkr_lo,  bkr,   kr, nullptr, nullptr, 128, 4096, 16, 0 };
        g.j[3] = g.j[2]; g.j[3].blk0 = NONE;
        mma_gemm5<<<dim3(17, 16), 128, G_SMEM>>>(g);
    }
    // G2+G3
    {
        GJobs g{};
        g.j[0] = { cq_hi, cq_lo, Wqc_hi, Wqc_lo, bq_c,    qc, nullptr, nullptr, 4096, 1536, 0,  0 };
        g.j[1] = { cq_hi, cq_lo, Wqr_hi, Wqr_lo, bq_rope, qr, nullptr, nullptr, 2048, 1536, 32, 0 };
        g.j[2] = { ckv_hi, ckv_lo, Wkc_hi, Wkc_lo, bk_c,  kc, nullptr, nullptr, 4096, 512, 48, 0 };
        g.j[3] = { ckv_hi, ckv_lo, Wv_hi,  Wv_lo,  bv, nullptr, vhi, vlo,       4096, 512, 80, 0 };
        mma_gemm5<<<dim3(112, 16), 128, G_SMEM>>>(g);
    }

    fuse_q_kernel<<<8192, 256>>>(qc, qr, qhi, qlo);
    fuse_k_kernel<<<8192, 256>>>(kc, kr, khi, klo);

    cudaFuncSetAttribute(attn_mma_kernel, cudaFuncAttributeMaxDynamicSharedMemorySize, ATT_SMEM);
    attn_mma_kernel<<<dim3(S_LEN / 128, NH), 256, ATT_SMEM>>>(
        qhi, qlo, khi, klo, vhi, vlo, mask, ao_hi, ao_lo);

    // G4: out = ao @ Wo^T
    {
        GJobs g{};
        g.j[0] = { ao_hi, ao_lo, Wo_hi, Wo_lo, bo, out, nullptr, nullptr, 4096, 4096, 0, 0 };
        g.j[1] = g.j[0]; g.j[1].blk0 = NONE;
        g.j[2] = g.j[0]; g.j[2].blk0 = NONE;
        g.j[3] = g.j[0]; g.j[3].blk0 = NONE;
        mma_gemm5<<<dim3(32, 16), 128, G_SMEM>>>(g);
    }
}

// round 11
// speedup vs baseline: 5.8786x; 1.0714x over previous
#include <cuda_runtime.h>
#include <cuda_bf16.h>
#include <math.h>
#include <stdint.h>

#define S_LEN 2048
#define HID   4096
#define NH    32
#define DQK   192
#define DV    128

// ---------------------------------------------------------------------------
// scratch (device globals; no allocations allowed)
// ---------------------------------------------------------------------------
__device__ float g_qc [2048*4096];
__device__ float g_qr [2048*2048];
__device__ float g_kc [2048*4096];
__device__ float g_kr [2048*128];
__device__ float g_bkr[128];

__device__ __align__(16) __nv_bfloat16 g_h_hi [2048*4096], g_h_lo [2048*4096];
__device__ __align__(16) __nv_bfloat16 g_cq_hi[2048*1536], g_cq_lo[2048*1536];
__device__ __align__(16) __nv_bfloat16 g_ckv_hi[2048*512], g_ckv_lo[2048*512];
__device__ __align__(16) __nv_bfloat16 g_ao_hi[2048*4096], g_ao_lo[2048*4096];
__device__ __align__(16) __nv_bfloat16 g_Wqlr_hi[1536*4096], g_Wqlr_lo[1536*4096];
__device__ __align__(16) __nv_bfloat16 g_Wqc_hi [4096*1536], g_Wqc_lo [4096*1536];
__device__ __align__(16) __nv_bfloat16 g_Wqr_hi [2048*1536], g_Wqr_lo [2048*1536];
__device__ __align__(16) __nv_bfloat16 g_Wkv_hi [512*4096],  g_Wkv_lo [512*4096];
__device__ __align__(16) __nv_bfloat16 g_Wkc_hi [4096*512],  g_Wkc_lo [4096*512];
__device__ __align__(16) __nv_bfloat16 g_Wv_hi  [4096*512],  g_Wv_lo  [4096*512];
__device__ __align__(16) __nv_bfloat16 g_Wo_hi  [4096*4096], g_Wo_lo  [4096*4096];
__device__ __align__(16) __nv_bfloat16 g_Wkr_hi [128*4096],  g_Wkr_lo [128*4096];

__device__ __align__(16) __nv_bfloat16 g_qhi[2048*32*192], g_qlo[2048*32*192];
__device__ __align__(16) __nv_bfloat16 g_khi[2048*32*192], g_klo[2048*32*192];
__device__ __align__(16) __nv_bfloat16 g_vhi[2048*4096],   g_vlo[2048*4096];

// ---------------------------------------------------------------------------
// small PTX helpers
// ---------------------------------------------------------------------------
__device__ __forceinline__ uint32_t smem_u32(const void* p) {
    uint32_t a;
    asm("{ .reg .u64 t; cvta.to.shared.u64 t, %1; cvt.u32.u64 %0, t; }" : "=r"(a) : "l"(p));
    return a;
}
#define CP_ASYNC16(dst_u32, src_ptr) \
    asm volatile("cp.async.cg.shared.global [%0], [%1], 16;" \
                 :: "r"(dst_u32), "l"(__cvta_generic_to_global(src_ptr)) : "memory")
#define CP_COMMIT() asm volatile("cp.async.commit_group;" ::: "memory")
#define CP_WAIT(n)  asm volatile("cp.async.wait_group %0;" :: "n"(n) : "memory")

__device__ __forceinline__ void ldmx4(uint32_t& r0, uint32_t& r1, uint32_t& r2, uint32_t& r3,
                                      uint32_t addr) {
    asm volatile("ldmatrix.sync.aligned.m8n8.x4.shared.b16 {%0,%1,%2,%3}, [%4];"
                 : "=r"(r0), "=r"(r1), "=r"(r2), "=r"(r3) : "r"(addr));
}
__device__ __forceinline__ void ldmx4t(uint32_t& r0, uint32_t& r1, uint32_t& r2, uint32_t& r3,
                                       uint32_t addr) {
    asm volatile("ldmatrix.sync.aligned.m8n8.x4.trans.shared.b16 {%0,%1,%2,%3}, [%4];"
                 : "=r"(r0), "=r"(r1), "=r"(r2), "=r"(r3) : "r"(addr));
}
__device__ __forceinline__ void mma_bf16(float* d, const uint32_t* a, const uint32_t* b) {
    asm volatile("mma.sync.aligned.m16n8k16.row.col.f32.bf16.bf16.f32 "
                 "{%0,%1,%2,%3}, {%4,%5,%6,%7}, {%8,%9}, {%0,%1,%2,%3};"
                 : "+f"(d[0]), "+f"(d[1]), "+f"(d[2]), "+f"(d[3])
                 : "r"(a[0]), "r"(a[1]), "r"(a[2]), "r"(a[3]), "r"(b[0]), "r"(b[1]));
}
__device__ __forceinline__ uint32_t pack_hi(float a, float b) {
    __nv_bfloat16 ha = __float2bfloat16(a), hb = __float2bfloat16(b);
    return (uint32_t)__bfloat16_as_ushort(ha) | ((uint32_t)__bfloat16_as_ushort(hb) << 16);
}
__device__ __forceinline__ uint32_t pack_lo(float a, float b) {
    __nv_bfloat16 ha = __float2bfloat16(a), hb = __float2bfloat16(b);
    __nv_bfloat16 la = __float2bfloat16(a - __bfloat162float(ha));
    __nv_bfloat16 lb = __float2bfloat16(b - __bfloat162float(hb));
    return (uint32_t)__bfloat16_as_ushort(la) | ((uint32_t)__bfloat16_as_ushort(lb) << 16);
}

// ---------------------------------------------------------------------------
// mega split: 2x float4 per thread, 128-bit stores
// ---------------------------------------------------------------------------
struct SJob { const float* x; __nv_bfloat16* hi; __nv_bfloat16* lo; int n8; int blk0; };
struct SJobs { SJob j[8]; };

__global__ void multi_split_kernel(SJobs jobs) {
    int b = blockIdx.x;
    int ji = 0;
#pragma unroll
    for (int t = 1; t < 8; t++)
        if (b >= jobs.j[t].blk0) ji = t;
    const SJob jb = jobs.j[ji];
    int i = (b - jb.blk0) * 256 + threadIdx.x;
    if (i >= jb.n8) return;
    float4 v0 = ((const float4*)jb.x)[i * 2];
    float4 v1 = ((const float4*)jb.x)[i * 2 + 1];
    uint4 H, L;
    H.x = pack_hi(v0.x, v0.y); H.y = pack_hi(v0.z, v0.w);
    H.z = pack_hi(v1.x, v1.y); H.w = pack_hi(v1.z, v1.w);
    L.x = pack_lo(v0.x, v0.y); L.y = pack_lo(v0.z, v0.w);
    L.z = pack_lo(v1.x, v1.y); L.w = pack_lo(v1.z, v1.w);
    ((uint4*)jb.hi)[i] = H;
    ((uint4*)jb.lo)[i] = L;
}

__global__ void pad_krope_kernel(const float* __restrict__ W,
                                 __nv_bfloat16* __restrict__ hi,
                                 __nv_bfloat16* __restrict__ lo,
                                 const float* __restrict__ b,
                                 float* __restrict__ bp) {
    int i = blockIdx.x * blockDim.x + threadIdx.x;
    if (i < 128) bp[i] = (i < 64) ? b[i] : 0.f;
    if (i >= 128 * 4096) return;
    int r = i >> 12;
    float v = (r < 64) ? W[(size_t)r * 4096 + (i & 4095)] : 0.f;
    __nv_bfloat16 h = __float2bfloat16(v);
    hi[i] = h;
    lo[i] = __float2bfloat16(v - __bfloat162float(h));
}

// ---------------------------------------------------------------------------
// batched GEMM: 3-stage cp.async pipeline, one barrier per chunk,
// 64B rows with XOR bank swizzle; next-chunk loads issued AFTER ks=0 MMAs
// (keeps the barrier->ldsm->mma critical path free of LDGSTS issue cost).
// ---------------------------------------------------------------------------
#define OA_HI 0
#define OA_LO 8192
#define OW_HI 16384
#define OW_LO 24576
#define ST_BUF 32768
#define G_SMEM (3 * ST_BUF)

__device__ __forceinline__ uint32_t swz64(int r, int c) {
    return (uint32_t)(r * 64 + ((c ^ ((r >> 1) & 3)) << 4));
}

struct GJob {
    const __nv_bfloat16 *Ahi, *Alo, *Whi, *Wlo;
    const float* bias;
    float* Cf;
    __nv_bfloat16 *Chi, *Clo;
    int N, K, blk0, pad_;
};
struct GJobs { GJob j[4]; };

__global__ void __launch_bounds__(128)
mma_gemm6(GJobs jobs) {
    extern __shared__ char gsm[];
    const uint32_t s0 = smem_u32(gsm);
    const int tid = threadIdx.x, wid = tid >> 5, lane = tid & 31;
    const int warp_m = wid >> 1, warp_n = wid & 1;

    int bx = blockIdx.x;
    int ji = 0;
#pragma unroll
    for (int t = 1; t < 4; t++)
        if (bx >= jobs.j[t].blk0) ji = t;
    const GJob jb = jobs.j[ji];
    const int col0 = (bx - jb.blk0) * 128;
    const int row0 = blockIdx.y * 128;
    const int K = jb.K, N = jb.N;

    const int a_row = (lane & 7) + ((lane >> 3) & 1) * 8;
    const int b_row = (lane & 7) + (lane >> 4) * 8;
    const int a_c   = (lane >> 4);
    const int b_c   = ((lane >> 3) & 1);

    uint32_t adA[4][2], adW[4][2];
#pragma unroll
    for (int mt = 0; mt < 4; mt++) {
        int rr = warp_m * 64 + mt * 16 + a_row;
#pragma unroll
        for (int ks = 0; ks < 2; ks++)
            adA[mt][ks] = OA_HI + swz64(rr, ks * 2 + a_c);
    }
#pragma unroll
    for (int np = 0; np < 4; np++) {
        int rr = warp_n * 64 + np * 16 + b_row;
#pragma unroll
        for (int ks = 0; ks < 2; ks++)
            adW[np][ks] = OW_HI + swz64(rr, ks * 2 + b_c);
    }

    const int kc = K >> 5;

    float acc[4][8][4];
#pragma unroll
    for (int mt = 0; mt < 4; mt++)
#pragma unroll
        for (int nt = 0; nt < 8; nt++)
#pragma unroll
            for (int e = 0; e < 4; e++) acc[mt][nt][e] = 0.f;

    auto load_chunk = [&](int c, int st) {
        const int kk = c << 5;
        const uint32_t base = s0 + st * ST_BUF;
#pragma unroll
        for (int i = 0; i < 4; i++) {
            int idx = tid + i * 128;
            int r = idx >> 2, cb = idx & 3;
            uint32_t doff = swz64(r, cb);
            size_t src = (size_t)(row0 + r) * K + kk + cb * 8;
            CP_ASYNC16(base + OA_HI + doff, jb.Ahi + src);
            CP_ASYNC16(base + OA_LO + doff, jb.Alo + src);
        }
#pragma unroll
        for (int i = 0; i < 4; i++) {
            int idx = tid + i * 128;
            int r = idx >> 2, cb = idx & 3;
            uint32_t doff = swz64(r, cb);
            size_t src = (size_t)(col0 + r) * K + kk + cb * 8;
            CP_ASYNC16(base + OW_HI + doff, jb.Whi + src);
            CP_ASYNC16(base + OW_LO + doff, jb.Wlo + src);
        }
        CP_COMMIT();
    };

    load_chunk(0, 0);
    load_chunk(1, 1);

    int st = 0, ls = 2;
    for (int c = 0; c < kc; c++) {
        if (c + 1 < kc) { CP_WAIT(1); } else { CP_WAIT(0); }
        __syncthreads();
        const uint32_t base = s0 + st * ST_BUF;

        // ---- ks = 0: fragments + MMAs first (critical path) ----
        {
            uint32_t ah[4][4], al[4][4];
#pragma unroll
            for (int mt = 0; mt < 4; mt++) {
                uint32_t ra = base + adA[mt][0];
                ldmx4(ah[mt][0], ah[mt][1], ah[mt][2], ah[mt][3], ra);
                ldmx4(al[mt][0], al[mt][1], al[mt][2], al[mt][3], ra + (OA_LO - OA_HI));
            }
#pragma unroll
            for (int np = 0; np < 4; np++) {
                uint32_t bh[4], bl[4];
                uint32_t rb = base + adW[np][0];
                ldmx4(bh[0], bh[1], bh[2], bh[3], rb);
                ldmx4(bl[0], bl[1], bl[2], bl[3], rb + (OW_LO - OW_HI));
#pragma unroll
                for (int j = 0; j < 2; j++) {
                    uint32_t b2h[2] = { bh[j * 2], bh[j * 2 + 1] };
                    uint32_t b2l[2] = { bl[j * 2], bl[j * 2 + 1] };
                    const int nt = np * 2 + j;
#pragma unroll
                    for (int mt = 0; mt < 4; mt++) mma_bf16(acc[mt][nt], ah[mt], b2h);
#pragma unroll
                    for (int mt = 0; mt < 4; mt++) mma_bf16(acc[mt][nt], al[mt], b2h);
#pragma unroll
                    for (int mt = 0; mt < 4; mt++) mma_bf16(acc[mt][nt], ah[mt], b2l);
                }
            }
        }

        // issue next-next chunk loads while ks=1 MMAs run
        if (c + 2 < kc) load_chunk(c + 2, ls);

        // ---- ks = 1 ----
        {
            uint32_t ah[4][4], al[4][4];
#pragma unroll
            for (int mt = 0; mt < 4; mt++) {
                uint32_t ra = base + adA[mt][1];
                ldmx4(ah[mt][0], ah[mt][1], ah[mt][2], ah[mt][3], ra);
                ldmx4(al[mt][0], al[mt][1], al[mt][2], al[mt][3], ra + (OA_LO - OA_HI));
            }
#pragma unroll
            for (int np = 0; np < 4; np++) {
                uint32_t bh[4], bl[4];
                uint32_t rb = base + adW[np][1];
                ldmx4(bh[0], bh[1], bh[2], bh[3], rb);
                ldmx4(bl[0], bl[1], bl[2], bl[3], rb + (OW_LO - OW_HI));
#pragma unroll
                for (int j = 0; j < 2; j++) {
                    uint32_t b2h[2] = { bh[j * 2], bh[j * 2 + 1] };
                    uint32_t b2l[2] = { bl[j * 2], bl[j * 2 + 1] };
                    const int nt = np * 2 + j;
#pragma unroll
                    for (int mt = 0; mt < 4; mt++) mma_bf16(acc[mt][nt], ah[mt], b2h);
#pragma unroll
                    for (int mt = 0; mt < 4; mt++) mma_bf16(acc[mt][nt], al[mt], b2h);
#pragma unroll
                    for (int mt = 0; mt < 4; mt++) mma_bf16(acc[mt][nt], ah[mt], b2l);
                }
            }
        }
        st = (st == 2) ? 0 : st + 1;
        ls = (ls == 2) ? 0 : ls + 1;
    }

    const int rbase = row0 + warp_m * 64 + (lane >> 2);
    const int cbase = col0 + warp_n * 64 + (lane & 3) * 2;
#pragma unroll
    for (int mt = 0; mt < 4; mt++) {
#pragma unroll
        for (int nt = 0; nt < 8; nt++) {
            const int cc = cbase + nt * 8;
            const float b0 = jb.bias[cc], b1 = jb.bias[cc + 1];
            const int r0 = rbase + mt * 16;
            float v0 = acc[mt][nt][0] + b0, v1 = acc[mt][nt][1] + b1;
            float v2 = acc[mt][nt][2] + b0, v3 = acc[mt][nt][3] + b1;
            if (jb.Cf) {
                *(float2*)&jb.Cf[(size_t)r0 * N + cc] = make_float2(v0, v1);
                *(float2*)&jb.Cf[(size_t)(r0 + 8) * N + cc] = make_float2(v2, v3);
            }
            if (jb.Chi) {
                *(uint32_t*)&jb.Chi[(size_t)r0 * N + cc]       = pack_hi(v0, v1);
                *(uint32_t*)&jb.Chi[(size_t)(r0 + 8) * N + cc] = pack_hi(v2, v3);
                *(uint32_t*)&jb.Clo[(size_t)r0 * N + cc]       = pack_lo(v0, v1);
                *(uint32_t*)&jb.Clo[(size_t)(r0 + 8) * N + cc] = pack_lo(v2, v3);
            }
        }
    }
}

// ---------------- merged concat + inline RoPE + RMSnorm (q and k) ------------
__global__ void fuse_qk_kernel(const float* __restrict__ qc,
                               const float* __restrict__ qr,
                               const float* __restrict__ kc,
                               const float* __restrict__ kr,
                               __nv_bfloat16* __restrict__ qh,
                               __nv_bfloat16* __restrict__ ql,
                               __nv_bfloat16* __restrict__ kh,
                               __nv_bfloat16* __restrict__ kl) {
    const bool is_k = blockIdx.x >= 8192;
    const int  bx   = is_k ? blockIdx.x - 8192 : blockIdx.x;
    const int gw   = ((bx * blockDim.x) + threadIdx.x) >> 5;
    const int lane = threadIdx.x & 31;
    const int s = gw >> 5, h = gw & 31;
    float vals[6]; float ss = 0.f;
#pragma unroll
    for (int t = 0; t < 6; t++) {
        int d = lane + 32 * t;
        float x;
        if (d < 128) {
            x = is_k ? kc[(size_t)s * HID + h * 128 + d]
                     : qc[(size_t)s * HID + h * 128 + d];
        } else if (!is_k) {
            int j = h * 64 + (d - 128);
            int base = (j < 1024) ? j : j - 1024;
            float ex  = (float)(2 * base) / 2048.0f;
            float inv = 1.0f / powf(10000.0f, ex);
            float sn, c;
            sincosf((float)s * inv, &sn, &c);
            if (j < 1024)
                x = qr[(size_t)s * 2048 + j] * c - qr[(size_t)s * 2048 + j + 1024] * sn;
            else
                x = qr[(size_t)s * 2048 + j] * c + qr[(size_t)s * 2048 + base] * sn;
        } else {
            int j = d - 128;
            int base = (j < 32) ? j : j - 32;
            float ex  = (float)(2 * base) / 64.0f;
            float inv = 1.0f / powf(10000.0f, ex);
            float sn, c;
            sincosf((float)s * inv, &sn, &c);
            if (j < 32)
                x = kr[(size_t)s * 128 + j] * c - kr[(size_t)s * 128 + j + 32] * sn;
            else
                x = kr[(size_t)s * 128 + j] * c + kr[(size_t)s * 128 + base] * sn;
        }
        vals[t] = x; ss += x * x;
    }
#pragma unroll
    for (int o = 16; o; o >>= 1) ss += __shfl_xor_sync(0xffffffffu, ss, o);
    float r = rsqrtf(ss * (1.f / 192.f) + 1.1920929e-7f);
    __nv_bfloat16* dh = is_k ? kh : qh;
    __nv_bfloat16* dl = is_k ? kl : ql;
#pragma unroll
    for (int t = 0; t < 6; t++) {
        float x = vals[t] * r;
        __nv_bfloat16 hb = __float2bfloat16(x);
        size_t o_ = ((size_t)s * NH + h) * DQK + lane + 32 * t;
        dh[o_] = hb;
        dl[o_] = __float2bfloat16(x - __bfloat162float(hb));
    }
}

// ---------------------------------------------------------------------------
// flash attention (unchanged from R10 passing version)
// ---------------------------------------------------------------------------
#define OQH 0
#define OQL (128*400)
#define OKH (2*128*400)
#define OKL (OKH + 64*400)
#define OVB (OKL + 64*400)
#define VHALF (64*272)
#define VBUF (2*VHALF)
#define ATT_SMEM (OVB + 2*VBUF)

__global__ void __launch_bounds__(256, 1)
attn_mma_kernel(const __nv_bfloat16* __restrict__ qhi, const __nv_bfloat16* __restrict__ qlo,
                const __nv_bfloat16* __restrict__ khi, const __nv_bfloat16* __restrict__ klo,
                const __nv_bfloat16* __restrict__ vhi, const __nv_bfloat16* __restrict__ vlo,
                const float* __restrict__ mask,
                __nv_bfloat16* __restrict__ aoh, __nv_bfloat16* __restrict__ aol) {
    extern __shared__ char smraw[];
    const uint32_t s0 = smem_u32(smraw);
    const int h = blockIdx.y, q0 = blockIdx.x * 128;
    const int tid = threadIdx.x, wid = tid >> 5, lane = tid & 31;

    for (int i = tid; i < 3072; i += 256) {
        int r = i / 24, cb = i % 24;
        size_t src = ((size_t)(q0 + r) * NH + h) * DQK + cb * 8;
        CP_ASYNC16(s0 + OQH + r * 400 + cb * 16, qhi + src);
        CP_ASYNC16(s0 + OQL + r * 400 + cb * 16, qlo + src);
    }
    CP_COMMIT();

    auto load_k = [&](int k0) {
        for (int i = tid; i < 1536; i += 256) {
            int r = i / 24, cb = i % 24;
            size_t src = ((size_t)(k0 + r) * NH + h) * DQK + cb * 8;
            CP_ASYNC16(s0 + OKH + r * 400 + cb * 16, khi + src);
            CP_ASYNC16(s0 + OKL + r * 400 + cb * 16, klo + src);
        }
        CP_COMMIT();
    };
    auto load_v = [&](int k0, int buf) {
        const uint32_t vb = s0 + OVB + buf * VBUF;
        for (int i = tid; i < 1024; i += 256) {
            int r = i / 16, cb = i % 16;
            size_t src = (size_t)(k0 + r) * HID + h * DV + cb * 8;
            CP_ASYNC16(vb + r * 272 + cb * 16, vhi + src);
            CP_ASYNC16(vb + VHALF + r * 272 + cb * 16, vlo + src);
        }
        CP_COMMIT();
    };
    load_k(0);
    load_v(0, 0);

    const float scale = 1.0f / sqrtf(192.0f);
    float m0 = -1e30f, m1 = -1e30f, l0 = 0.f, l1 = 0.f;
    float acc[16][4];
#pragma unroll
    for (int nt = 0; nt < 16; nt++)
#pragma unroll
        for (int e = 0; e < 4; e++) acc[nt][e] = 0.f;

    const int a_r  = (lane & 7) + ((lane >> 3) & 1) * 8;
    const int a_k  = (lane >> 4) * 8;
    const int bk_r = (lane & 7) + (lane >> 4) * 8;
    const int bk_k = ((lane >> 3) & 1) * 8;
    const int prow  = lane >> 2;
    const int pcol2 = (lane & 3) * 2;

    for (int c = 0; c < 32; c++) {
        const int k0 = c * 64;
        CP_WAIT(0);
        __syncthreads();
        if (c + 1 < 32) load_v(k0 + 64, (c + 1) & 1);

        float sacc[8][4];
#pragma unroll
        for (int nt = 0; nt < 8; nt++)
#pragma unroll
            for (int e = 0; e < 4; e++) sacc[nt][e] = 0.f;

#pragma unroll
        for (int kt = 0; kt < 12; kt++) {
            uint32_t ah[4], al[4];
            ldmx4(ah[0], ah[1], ah[2], ah[3],
                  s0 + OQH + (wid * 16 + a_r) * 400 + (kt * 16 + a_k) * 2);
            ldmx4(al[0], al[1], al[2], al[3],
                  s0 + OQL + (wid * 16 + a_r) * 400 + (kt * 16 + a_k) * 2);
            uint32_t bh[4][4], bl[4][4];
#pragma unroll
            for (int n2 = 0; n2 < 4; n2++) {
                uint32_t rb = (n2 * 16 + bk_r) * 400 + (kt * 16 + bk_k) * 2;
                ldmx4(bh[n2][0], bh[n2][1], bh[n2][2], bh[n2][3], s0 + OKH + rb);
                ldmx4(bl[n2][0], bl[n2][1], bl[n2][2], bl[n2][3], s0 + OKL + rb);
            }
#pragma unroll
            for (int n2 = 0; n2 < 4; n2++) {
                mma_bf16(sacc[n2 * 2],     ah, &bh[n2][0]);
                mma_bf16(sacc[n2 * 2 + 1], ah, &bh[n2][2]);
            }
#pragma unroll
            for (int n2 = 0; n2 < 4; n2++) {
                mma_bf16(sacc[n2 * 2],     al, &bh[n2][0]);
                mma_bf16(sacc[n2 * 2 + 1], al, &bh[n2][2]);
            }
#pragma unroll
            for (int n2 = 0; n2 < 4; n2++) {
                mma_bf16(sacc[n2 * 2],     ah, &bl[n2][0]);
                mma_bf16(sacc[n2 * 2 + 1], ah, &bl[n2][2]);
            }
        }
        __syncthreads();
        if (c + 1 < 32) load_k(k0 + 64);

        const int rg0 = q0 + wid * 16 + prow;
        float sc[8][4];
        float mx0 = -1e30f, mx1 = -1e30f;
#pragma unroll
        for (int nt = 0; nt < 8; nt++) {
            int col = k0 + nt * 8 + pcol2;
            float2 mk0 = *(const float2*)&mask[(size_t)rg0 * S_LEN + col];
            float2 mk1 = *(const float2*)&mask[(size_t)(rg0 + 8) * S_LEN + col];
            sc[nt][0] = sacc[nt][0] * scale + mk0.x;
            sc[nt][1] = sacc[nt][1] * scale + mk0.y;
            sc[nt][2] = sacc[nt][2] * scale + mk1.x;
            sc[nt][3] = sacc[nt][3] * scale + mk1.y;
            mx0 = fmaxf(mx0, fmaxf(sc[nt][0], sc[nt][1]));
            mx1 = fmaxf(mx1, fmaxf(sc[nt][2], sc[nt][3]));
        }
        mx0 = fmaxf(mx0, __shfl_xor_sync(0xffffffffu, mx0, 1));
        mx0 = fmaxf(mx0, __shfl_xor_sync(0xffffffffu, mx0, 2));
        mx1 = fmaxf(mx1, __shfl_xor_sync(0xffffffffu, mx1, 1));
        mx1 = fmaxf(mx1, __shfl_xor_sync(0xffffffffu, mx1, 2));
        float mn0 = fmaxf(m0, mx0), mn1 = fmaxf(m1, mx1);
        float al0 = __expf(m0 - mn0), al1 = __expf(m1 - mn1);
        m0 = mn0; m1 = mn1;

        uint32_t pfh[4][4], pfl[4][4];
        float ps0 = 0.f, ps1 = 0.f;
#pragma unroll
        for (int nt = 0; nt < 8; nt++) {
            float p00 = __expf(sc[nt][0] - mn0), p01 = __expf(sc[nt][1] - mn0);
            float p10 = __expf(sc[nt][2] - mn1), p11 = __expf(sc[nt][3] - mn1);
            ps0 += p00 + p01; ps1 += p10 + p11;
            const int kt = nt >> 1, sl = (nt & 1) * 2;
            pfh[kt][sl + 0] = pack_hi(p00, p01);
            pfh[kt][sl + 1] = pack_hi(p10, p11);
            pfl[kt][sl + 0] = pack_lo(p00, p01);
            pfl[kt][sl + 1] = pack_lo(p10, p11);
        }
        ps0 += __shfl_xor_sync(0xffffffffu, ps0, 1);
        ps0 += __shfl_xor_sync(0xffffffffu, ps0, 2);
        ps1 += __shfl_xor_sync(0xffffffffu, ps1, 1);
        ps1 += __shfl_xor_sync(0xffffffffu, ps1, 2);
        l0 = al0 * l0 + ps0;
        l1 = al1 * l1 + ps1;
#pragma unroll
        for (int nt = 0; nt < 16; nt++) {
            acc[nt][0] *= al0; acc[nt][1] *= al0;
            acc[nt][2] *= al1; acc[nt][3] *= al1;
        }

        const uint32_t vb = s0 + OVB + (c & 1) * VBUF;
#pragma unroll
        for (int kt = 0; kt < 4; kt++) {
#pragma unroll
            for (int n2 = 0; n2 < 8; n2++) {
                uint32_t vh[4], vl[4];
                uint32_t rv = (kt * 16 + a_r) * 272 + (n2 * 16 + a_k) * 2;
                ldmx4t(vh[0], vh[1], vh[2], vh[3], vb + rv);
                ldmx4t(vl[0], vl[1], vl[2], vl[3], vb + VHALF + rv);
                uint32_t vh0[2] = { vh[0], vh[1] }, vh1[2] = { vh[2], vh[3] };
                uint32_t vl0[2] = { vl[0], vl[1] }, vl1[2] = { vl[2], vl[3] };
                mma_bf16(acc[n2 * 2],     pfh[kt], vh0);
                mma_bf16(acc[n2 * 2 + 1], pfh[kt], vh1);
                mma_bf16(acc[n2 * 2],     pfl[kt], vh0);
                mma_bf16(acc[n2 * 2 + 1], pfl[kt], vh1);
                mma_bf16(acc[n2 * 2],     pfh[kt], vl0);
                mma_bf16(acc[n2 * 2 + 1], pfh[kt], vl1);
            }
        }
    }

    const float i0 = 1.f / l0, i1 = 1.f / l1;
    const int orow = q0 + wid * 16 + prow;
#pragma unroll
    for (int nt = 0; nt < 16; nt++) {
        int col = h * DV + nt * 8 + pcol2;
        float v0 = acc[nt][0] * i0, v1 = acc[nt][1] * i0;
        float v2 = acc[nt][2] * i1, v3 = acc[nt][3] * i1;
        *(uint32_t*)&aoh[(size_t)orow * HID + col]       = pack_hi(v0, v1);
        *(uint32_t*)&aoh[(size_t)(orow + 8) * HID + col] = pack_hi(v2, v3);
        *(uint32_t*)&aol[(size_t)orow * HID + col]       = pack_lo(v0, v1);
        *(uint32_t*)&aol[(size_t)(orow + 8) * HID + col] = pack_lo(v2, v3);
    }
}

// ---------------------------------------------------------------------------
// launcher
// ---------------------------------------------------------------------------
extern "C" void kernel_launch(void* const* d_in, const int* in_sizes, int n_in,
                              void* d_out, int out_size) {
    const float* hidden  = (const float*)d_in[0];
    const float* mask    = (const float*)d_in[1];
    const float* Wq_lr   = (const float*)d_in[2];
    const float* bq_lr   = (const float*)d_in[3];
    const float* Wq_rope = (const float*)d_in[4];
    const float* bq_rope = (const float*)d_in[5];
    const float* Wq_c    = (const float*)d_in[6];
    const float* bq_c    = (const float*)d_in[7];
    const float* Wkv     = (const float*)d_in[8];
    const float* bkv     = (const float*)d_in[9];
    const float* Wk_rope = (const float*)d_in[10];
    const float* bk_rope = (const float*)d_in[11];
    const float* Wk_c    = (const float*)d_in[12];
    const float* bk_c    = (const float*)d_in[13];
    const float* Wv      = (const float*)d_in[14];
    const float* bv      = (const float*)d_in[15];
    const float* Wo      = (const float*)d_in[16];
    const float* bo      = (const float*)d_in[17];
    float* out = (float*)d_out;

    float *qc, *qr, *kc, *kr, *bkr;
    cudaGetSymbolAddress((void**)&qc,  g_qc);
    cudaGetSymbolAddress((void**)&qr,  g_qr);
    cudaGetSymbolAddress((void**)&kc,  g_kc);
    cudaGetSymbolAddress((void**)&kr,  g_kr);
    cudaGetSymbolAddress((void**)&bkr, g_bkr);

    __nv_bfloat16 *h_hi, *h_lo, *cq_hi, *cq_lo, *ckv_hi, *ckv_lo, *ao_hi, *ao_lo;
    __nv_bfloat16 *Wqlr_hi, *Wqlr_lo, *Wqc_hi, *Wqc_lo, *Wqr_hi, *Wqr_lo;
    __nv_bfloat16 *Wkv_hi, *Wkv_lo, *Wkc_hi, *Wkc_lo, *Wv_hi, *Wv_lo, *Wo_hi, *Wo_lo;
    __nv_bfloat16 *Wkr_hi, *Wkr_lo, *qhi, *qlo, *khi, *klo, *vhi, *vlo;
    cudaGetSymbolAddress((void**)&h_hi,   g_h_hi);   cudaGetSymbolAddress((void**)&h_lo,   g_h_lo);
    cudaGetSymbolAddress((void**)&cq_hi,  g_cq_hi);  cudaGetSymbolAddress((void**)&cq_lo,  g_cq_lo);
    cudaGetSymbolAddress((void**)&ckv_hi, g_ckv_hi); cudaGetSymbolAddress((void**)&ckv_lo, g_ckv_lo);
    cudaGetSymbolAddress((void**)&ao_hi,  g_ao_hi);  cudaGetSymbolAddress((void**)&ao_lo,  g_ao_lo);
    cudaGetSymbolAddress((void**)&Wqlr_hi, g_Wqlr_hi); cudaGetSymbolAddress((void**)&Wqlr_lo, g_Wqlr_lo);
    cudaGetSymbolAddress((void**)&Wqc_hi,  g_Wqc_hi);  cudaGetSymbolAddress((void**)&Wqc_lo,  g_Wqc_lo);
    cudaGetSymbolAddress((void**)&Wqr_hi,  g_Wqr_hi);  cudaGetSymbolAddress((void**)&Wqr_lo,  g_Wqr_lo);
    cudaGetSymbolAddress((void**)&Wkv_hi,  g_Wkv_hi);  cudaGetSymbolAddress((void**)&Wkv_lo,  g_Wkv_lo);
    cudaGetSymbolAddress((void**)&Wkc_hi,  g_Wkc_hi);  cudaGetSymbolAddress((void**)&Wkc_lo,  g_Wkc_lo);
    cudaGetSymbolAddress((void**)&Wv_hi,   g_Wv_hi);   cudaGetSymbolAddress((void**)&Wv_lo,   g_Wv_lo);
    cudaGetSymbolAddress((void**)&Wo_hi,   g_Wo_hi);   cudaGetSymbolAddress((void**)&Wo_lo,   g_Wo_lo);
    cudaGetSymbolAddress((void**)&Wkr_hi,  g_Wkr_hi);  cudaGetSymbolAddress((void**)&Wkr_lo,  g_Wkr_lo);
    cudaGetSymbolAddress((void**)&qhi, g_qhi); cudaGetSymbolAddress((void**)&qlo, g_qlo);
    cudaGetSymbolAddress((void**)&khi, g_khi); cudaGetSymbolAddress((void**)&klo, g_klo);
    cudaGetSymbolAddress((void**)&vhi, g_vhi); cudaGetSymbolAddress((void**)&vlo, g_vlo);

    cudaFuncSetAttribute(mma_gemm6, cudaFuncAttributeMaxDynamicSharedMemorySize, G_SMEM);

    SJobs jobs;
    const float* srcs[8] = { hidden, Wq_lr, Wq_c, Wq_rope, Wkv, Wk_c, Wv, Wo };
    __nv_bfloat16* his[8] = { h_hi, Wqlr_hi, Wqc_hi, Wqr_hi, Wkv_hi, Wkc_hi, Wv_hi, Wo_hi };
    __nv_bfloat16* los[8] = { h_lo, Wqlr_lo, Wqc_lo, Wqr_lo, Wkv_lo, Wkc_lo, Wv_lo, Wo_lo };
    int ns[8] = { 2048*4096, 1536*4096, 4096*1536, 2048*1536,
                  512*4096, 4096*512, 4096*512, 4096*4096 };
    int blk = 0;
    for (int i = 0; i < 8; i++) {
        jobs.j[i].x = srcs[i]; jobs.j[i].hi = his[i]; jobs.j[i].lo = los[i];
        jobs.j[i].n8 = ns[i] / 8; jobs.j[i].blk0 = blk;
        blk += (jobs.j[i].n8 + 255) / 256;
    }
    multi_split_kernel<<<blk, 256>>>(jobs);
    pad_krope_kernel<<<(128 * 4096 + 255) / 256, 256>>>(Wk_rope, Wkr_hi, Wkr_lo, bk_rope, bkr);

    const int NONE = 0x7FFFFFFF;

    // G1: A = hidden (K=4096): c_q, c_kv, k_rope
    {
        GJobs g{};
        g.j[0] = { h_hi, h_lo, Wqlr_hi, Wqlr_lo, bq_lr, nullptr, cq_hi, cq_lo, 1536, 4096, 0, 0 };
        g.j[1] = { h_hi, h_lo, Wkv_hi,  Wkv_lo,  bkv,   nullptr, ckv_hi, ckv_lo, 512, 4096, 12, 0 };
        g.j[2] = { h_hi, h_lo, Wkr_hi,  Wkr_lo,  bkr,   kr, nullptr, nullptr, 128, 4096, 16, 0 };
        g.j[3] = g.j[2]; g.j[3].blk0 = NONE;
        mma_gemm6<<<dim3(17, 16), 128, G_SMEM>>>(g);
    }
    // G2+G3
    {
        GJobs g{};
        g.j[0] = { cq_hi, cq_lo, Wqc_hi, Wqc_lo, bq_c,    qc, nullptr, nullptr, 4096, 1536, 0,  0 };
        g.j[1] = { cq_hi, cq_lo, Wqr_hi, Wqr_lo, bq_rope, qr, nullptr, nullptr, 2048, 1536, 32, 0 };
        g.j[2] = { ckv_hi, ckv_lo, Wkc_hi, Wkc_lo, bk_c,  kc, nullptr, nullptr, 4096, 512, 48, 0 };
        g.j[3] = { ckv_hi, ckv_lo, Wv_hi,  Wv_lo,  bv, nullptr, vhi, vlo,       4096, 512, 80, 0 };
        mma_gemm6<<<dim3(112, 16), 128, G_SMEM>>>(g);
    }

    fuse_qk_kernel<<<16384, 256>>>(qc, qr, kc, kr, qhi, qlo, khi, klo);

    cudaFuncSetAttribute(attn_mma_kernel, cudaFuncAttributeMaxDynamicSharedMemorySize, ATT_SMEM);
    attn_mma_kernel<<<dim3(S_LEN / 128, NH), 256, ATT_SMEM>>>(
        qhi, qlo, khi, klo, vhi, vlo, mask, ao_hi, ao_lo);

    // G4: out = ao @ Wo^T
    {
        GJobs g{};
        g.j[0] = { ao_hi, ao_lo, Wo_hi, Wo_lo, bo, out, nullptr, nullptr, 4096, 4096, 0, 0 };
        g.j[1] = g.j[0]; g.j[1].blk0 = NONE;
        g.j[2] = g.j[0]; g.j[2].blk0 = NONE;
        g.j[3] = g.j[0]; g.j[3].blk0 = NONE;
        mma_gemm6<<<dim3(32, 16), 128, G_SMEM>>>(g);
    }
}

// round 12
// speedup vs baseline: 6.0246x; 1.0248x over previous
#include <cuda_runtime.h>
#include <cuda_bf16.h>
#include <math.h>
#include <stdint.h>

#define S_LEN 2048
#define HID   4096
#define NH    32
#define DQK   192
#define DV    128

// ---------------------------------------------------------------------------
// scratch (device globals; no allocations allowed)
// ---------------------------------------------------------------------------
__device__ float g_qc [2048*4096];
__device__ float g_qr [2048*2048];
__device__ float g_kc [2048*4096];
__device__ float g_kr [2048*128];
__device__ float g_bkr[128];

__device__ __align__(16) __nv_bfloat16 g_h_hi [2048*4096], g_h_lo [2048*4096];
__device__ __align__(16) __nv_bfloat16 g_cq_hi[2048*1536], g_cq_lo[2048*1536];
__device__ __align__(16) __nv_bfloat16 g_ckv_hi[2048*512], g_ckv_lo[2048*512];
__device__ __align__(16) __nv_bfloat16 g_ao_hi[2048*4096], g_ao_lo[2048*4096];
__device__ __align__(16) __nv_bfloat16 g_Wqlr_hi[1536*4096], g_Wqlr_lo[1536*4096];
__device__ __align__(16) __nv_bfloat16 g_Wqc_hi [4096*1536], g_Wqc_lo [4096*1536];
__device__ __align__(16) __nv_bfloat16 g_Wqr_hi [2048*1536], g_Wqr_lo [2048*1536];
__device__ __align__(16) __nv_bfloat16 g_Wkv_hi [512*4096],  g_Wkv_lo [512*4096];
__device__ __align__(16) __nv_bfloat16 g_Wkc_hi [4096*512],  g_Wkc_lo [4096*512];
__device__ __align__(16) __nv_bfloat16 g_Wv_hi  [4096*512],  g_Wv_lo  [4096*512];
__device__ __align__(16) __nv_bfloat16 g_Wo_hi  [4096*4096], g_Wo_lo  [4096*4096];
__device__ __align__(16) __nv_bfloat16 g_Wkr_hi [128*4096],  g_Wkr_lo [128*4096];

__device__ __align__(16) __nv_bfloat16 g_qhi[2048*32*192], g_qlo[2048*32*192];
__device__ __align__(16) __nv_bfloat16 g_khi[2048*32*192], g_klo[2048*32*192];
__device__ __align__(16) __nv_bfloat16 g_vhi[2048*4096],   g_vlo[2048*4096];

// ---------------------------------------------------------------------------
// small PTX helpers
// ---------------------------------------------------------------------------
__device__ __forceinline__ uint32_t smem_u32(const void* p) {
    uint32_t a;
    asm("{ .reg .u64 t; cvta.to.shared.u64 t, %1; cvt.u32.u64 %0, t; }" : "=r"(a) : "l"(p));
    return a;
}
#define CP_ASYNC16(dst_u32, src_ptr) \
    asm volatile("cp.async.cg.shared.global [%0], [%1], 16;" \
                 :: "r"(dst_u32), "l"(__cvta_generic_to_global(src_ptr)) : "memory")
#define CP_COMMIT() asm volatile("cp.async.commit_group;" ::: "memory")
#define CP_WAIT(n)  asm volatile("cp.async.wait_group %0;" :: "n"(n) : "memory")

__device__ __forceinline__ void ldmx4(uint32_t& r0, uint32_t& r1, uint32_t& r2, uint32_t& r3,
                                      uint32_t addr) {
    asm volatile("ldmatrix.sync.aligned.m8n8.x4.shared.b16 {%0,%1,%2,%3}, [%4];"
                 : "=r"(r0), "=r"(r1), "=r"(r2), "=r"(r3) : "r"(addr));
}
__device__ __forceinline__ void ldmx4t(uint32_t& r0, uint32_t& r1, uint32_t& r2, uint32_t& r3,
                                       uint32_t addr) {
    asm volatile("ldmatrix.sync.aligned.m8n8.x4.trans.shared.b16 {%0,%1,%2,%3}, [%4];"
                 : "=r"(r0), "=r"(r1), "=r"(r2), "=r"(r3) : "r"(addr));
}
__device__ __forceinline__ void mma_bf16(float* d, const uint32_t* a, const uint32_t* b) {
    asm volatile("mma.sync.aligned.m16n8k16.row.col.f32.bf16.bf16.f32 "
                 "{%0,%1,%2,%3}, {%4,%5,%6,%7}, {%8,%9}, {%0,%1,%2,%3};"
                 : "+f"(d[0]), "+f"(d[1]), "+f"(d[2]), "+f"(d[3])
                 : "r"(a[0]), "r"(a[1]), "r"(a[2]), "r"(a[3]), "r"(b[0]), "r"(b[1]));
}
__device__ __forceinline__ uint32_t pack_hi(float a, float b) {
    __nv_bfloat16 ha = __float2bfloat16(a), hb = __float2bfloat16(b);
    return (uint32_t)__bfloat16_as_ushort(ha) | ((uint32_t)__bfloat16_as_ushort(hb) << 16);
}
__device__ __forceinline__ uint32_t pack_lo(float a, float b) {
    __nv_bfloat16 ha = __float2bfloat16(a), hb = __float2bfloat16(b);
    __nv_bfloat16 la = __float2bfloat16(a - __bfloat162float(ha));
    __nv_bfloat16 lb = __float2bfloat16(b - __bfloat162float(hb));
    return (uint32_t)__bfloat16_as_ushort(la) | ((uint32_t)__bfloat16_as_ushort(lb) << 16);
}

// ---------------------------------------------------------------------------
// mega split: 2x float4 per thread, 128-bit stores
// ---------------------------------------------------------------------------
struct SJob { const float* x; __nv_bfloat16* hi; __nv_bfloat16* lo; int n8; int blk0; };
struct SJobs { SJob j[8]; };

__global__ void multi_split_kernel(SJobs jobs) {
    int b = blockIdx.x;
    int ji = 0;
#pragma unroll
    for (int t = 1; t < 8; t++)
        if (b >= jobs.j[t].blk0) ji = t;
    const SJob jb = jobs.j[ji];
    int i = (b - jb.blk0) * 256 + threadIdx.x;
    if (i >= jb.n8) return;
    float4 v0 = ((const float4*)jb.x)[i * 2];
    float4 v1 = ((const float4*)jb.x)[i * 2 + 1];
    uint4 H, L;
    H.x = pack_hi(v0.x, v0.y); H.y = pack_hi(v0.z, v0.w);
    H.z = pack_hi(v1.x, v1.y); H.w = pack_hi(v1.z, v1.w);
    L.x = pack_lo(v0.x, v0.y); L.y = pack_lo(v0.z, v0.w);
    L.z = pack_lo(v1.x, v1.y); L.w = pack_lo(v1.z, v1.w);
    ((uint4*)jb.hi)[i] = H;
    ((uint4*)jb.lo)[i] = L;
}

__global__ void pad_krope_kernel(const float* __restrict__ W,
                                 __nv_bfloat16* __restrict__ hi,
                                 __nv_bfloat16* __restrict__ lo,
                                 const float* __restrict__ b,
                                 float* __restrict__ bp) {
    int i = blockIdx.x * blockDim.x + threadIdx.x;
    if (i < 128) bp[i] = (i < 64) ? b[i] : 0.f;
    if (i >= 128 * 4096) return;
    int r = i >> 12;
    float v = (r < 64) ? W[(size_t)r * 4096 + (i & 4095)] : 0.f;
    __nv_bfloat16 h = __float2bfloat16(v);
    hi[i] = h;
    lo[i] = __float2bfloat16(v - __bfloat162float(h));
}

// ---------------------------------------------------------------------------
// batched GEMM (unchanged from R11 passing version)
// ---------------------------------------------------------------------------
#define OA_HI 0
#define OA_LO 8192
#define OW_HI 16384
#define OW_LO 24576
#define ST_BUF 32768
#define G_SMEM (3 * ST_BUF)

__device__ __forceinline__ uint32_t swz64(int r, int c) {
    return (uint32_t)(r * 64 + ((c ^ ((r >> 1) & 3)) << 4));
}

struct GJob {
    const __nv_bfloat16 *Ahi, *Alo, *Whi, *Wlo;
    const float* bias;
    float* Cf;
    __nv_bfloat16 *Chi, *Clo;
    int N, K, blk0, pad_;
};
struct GJobs { GJob j[4]; };

__global__ void __launch_bounds__(128)
mma_gemm6(GJobs jobs) {
    extern __shared__ char gsm[];
    const uint32_t s0 = smem_u32(gsm);
    const int tid = threadIdx.x, wid = tid >> 5, lane = tid & 31;
    const int warp_m = wid >> 1, warp_n = wid & 1;

    int bx = blockIdx.x;
    int ji = 0;
#pragma unroll
    for (int t = 1; t < 4; t++)
        if (bx >= jobs.j[t].blk0) ji = t;
    const GJob jb = jobs.j[ji];
    const int col0 = (bx - jb.blk0) * 128;
    const int row0 = blockIdx.y * 128;
    const int K = jb.K, N = jb.N;

    const int a_row = (lane & 7) + ((lane >> 3) & 1) * 8;
    const int b_row = (lane & 7) + (lane >> 4) * 8;
    const int a_c   = (lane >> 4);
    const int b_c   = ((lane >> 3) & 1);

    uint32_t adA[4][2], adW[4][2];
#pragma unroll
    for (int mt = 0; mt < 4; mt++) {
        int rr = warp_m * 64 + mt * 16 + a_row;
#pragma unroll
        for (int ks = 0; ks < 2; ks++)
            adA[mt][ks] = OA_HI + swz64(rr, ks * 2 + a_c);
    }
#pragma unroll
    for (int np = 0; np < 4; np++) {
        int rr = warp_n * 64 + np * 16 + b_row;
#pragma unroll
        for (int ks = 0; ks < 2; ks++)
            adW[np][ks] = OW_HI + swz64(rr, ks * 2 + b_c);
    }

    const int kc = K >> 5;

    float acc[4][8][4];
#pragma unroll
    for (int mt = 0; mt < 4; mt++)
#pragma unroll
        for (int nt = 0; nt < 8; nt++)
#pragma unroll
            for (int e = 0; e < 4; e++) acc[mt][nt][e] = 0.f;

    auto load_chunk = [&](int c, int st) {
        const int kk = c << 5;
        const uint32_t base = s0 + st * ST_BUF;
#pragma unroll
        for (int i = 0; i < 4; i++) {
            int idx = tid + i * 128;
            int r = idx >> 2, cb = idx & 3;
            uint32_t doff = swz64(r, cb);
            size_t src = (size_t)(row0 + r) * K + kk + cb * 8;
            CP_ASYNC16(base + OA_HI + doff, jb.Ahi + src);
            CP_ASYNC16(base + OA_LO + doff, jb.Alo + src);
        }
#pragma unroll
        for (int i = 0; i < 4; i++) {
            int idx = tid + i * 128;
            int r = idx >> 2, cb = idx & 3;
            uint32_t doff = swz64(r, cb);
            size_t src = (size_t)(col0 + r) * K + kk + cb * 8;
            CP_ASYNC16(base + OW_HI + doff, jb.Whi + src);
            CP_ASYNC16(base + OW_LO + doff, jb.Wlo + src);
        }
        CP_COMMIT();
    };

    load_chunk(0, 0);
    load_chunk(1, 1);

    int st = 0, ls = 2;
    for (int c = 0; c < kc; c++) {
        if (c + 1 < kc) { CP_WAIT(1); } else { CP_WAIT(0); }
        __syncthreads();
        const uint32_t base = s0 + st * ST_BUF;

        // ks = 0 (critical path first)
        {
            uint32_t ah[4][4], al[4][4];
#pragma unroll
            for (int mt = 0; mt < 4; mt++) {
                uint32_t ra = base + adA[mt][0];
                ldmx4(ah[mt][0], ah[mt][1], ah[mt][2], ah[mt][3], ra);
                ldmx4(al[mt][0], al[mt][1], al[mt][2], al[mt][3], ra + (OA_LO - OA_HI));
            }
#pragma unroll
            for (int np = 0; np < 4; np++) {
                uint32_t bh[4], bl[4];
                uint32_t rb = base + adW[np][0];
                ldmx4(bh[0], bh[1], bh[2], bh[3], rb);
                ldmx4(bl[0], bl[1], bl[2], bl[3], rb + (OW_LO - OW_HI));
#pragma unroll
                for (int j = 0; j < 2; j++) {
                    uint32_t b2h[2] = { bh[j * 2], bh[j * 2 + 1] };
                    uint32_t b2l[2] = { bl[j * 2], bl[j * 2 + 1] };
                    const int nt = np * 2 + j;
#pragma unroll
                    for (int mt = 0; mt < 4; mt++) mma_bf16(acc[mt][nt], ah[mt], b2h);
#pragma unroll
                    for (int mt = 0; mt < 4; mt++) mma_bf16(acc[mt][nt], al[mt], b2h);
#pragma unroll
                    for (int mt = 0; mt < 4; mt++) mma_bf16(acc[mt][nt], ah[mt], b2l);
                }
            }
        }

        if (c + 2 < kc) load_chunk(c + 2, ls);

        // ks = 1
        {
            uint32_t ah[4][4], al[4][4];
#pragma unroll
            for (int mt = 0; mt < 4; mt++) {
                uint32_t ra = base + adA[mt][1];
                ldmx4(ah[mt][0], ah[mt][1], ah[mt][2], ah[mt][3], ra);
                ldmx4(al[mt][0], al[mt][1], al[mt][2], al[mt][3], ra + (OA_LO - OA_HI));
            }
#pragma unroll
            for (int np = 0; np < 4; np++) {
                uint32_t bh[4], bl[4];
                uint32_t rb = base + adW[np][1];
                ldmx4(bh[0], bh[1], bh[2], bh[3], rb);
                ldmx4(bl[0], bl[1], bl[2], bl[3], rb + (OW_LO - OW_HI));
#pragma unroll
                for (int j = 0; j < 2; j++) {
                    uint32_t b2h[2] = { bh[j * 2], bh[j * 2 + 1] };
                    uint32_t b2l[2] = { bl[j * 2], bl[j * 2 + 1] };
                    const int nt = np * 2 + j;
#pragma unroll
                    for (int mt = 0; mt < 4; mt++) mma_bf16(acc[mt][nt], ah[mt], b2h);
#pragma unroll
                    for (int mt = 0; mt < 4; mt++) mma_bf16(acc[mt][nt], al[mt], b2h);
#pragma unroll
                    for (int mt = 0; mt < 4; mt++) mma_bf16(acc[mt][nt], ah[mt], b2l);
                }
            }
        }
        st = (st == 2) ? 0 : st + 1;
        ls = (ls == 2) ? 0 : ls + 1;
    }

    const int rbase = row0 + warp_m * 64 + (lane >> 2);
    const int cbase = col0 + warp_n * 64 + (lane & 3) * 2;
#pragma unroll
    for (int mt = 0; mt < 4; mt++) {
#pragma unroll
        for (int nt = 0; nt < 8; nt++) {
            const int cc = cbase + nt * 8;
            const float b0 = jb.bias[cc], b1 = jb.bias[cc + 1];
            const int r0 = rbase + mt * 16;
            float v0 = acc[mt][nt][0] + b0, v1 = acc[mt][nt][1] + b1;
            float v2 = acc[mt][nt][2] + b0, v3 = acc[mt][nt][3] + b1;
            if (jb.Cf) {
                *(float2*)&jb.Cf[(size_t)r0 * N + cc] = make_float2(v0, v1);
                *(float2*)&jb.Cf[(size_t)(r0 + 8) * N + cc] = make_float2(v2, v3);
            }
            if (jb.Chi) {
                *(uint32_t*)&jb.Chi[(size_t)r0 * N + cc]       = pack_hi(v0, v1);
                *(uint32_t*)&jb.Chi[(size_t)(r0 + 8) * N + cc] = pack_hi(v2, v3);
                *(uint32_t*)&jb.Clo[(size_t)r0 * N + cc]       = pack_lo(v0, v1);
                *(uint32_t*)&jb.Clo[(size_t)(r0 + 8) * N + cc] = pack_lo(v2, v3);
            }
        }
    }
}

// ---------------- merged concat + inline RoPE + RMSnorm (q and k) ------------
__global__ void fuse_qk_kernel(const float* __restrict__ qc,
                               const float* __restrict__ qr,
                               const float* __restrict__ kc,
                               const float* __restrict__ kr,
                               __nv_bfloat16* __restrict__ qh,
                               __nv_bfloat16* __restrict__ ql,
                               __nv_bfloat16* __restrict__ kh,
                               __nv_bfloat16* __restrict__ kl) {
    const bool is_k = blockIdx.x >= 8192;
    const int  bx   = is_k ? blockIdx.x - 8192 : blockIdx.x;
    const int gw   = ((bx * blockDim.x) + threadIdx.x) >> 5;
    const int lane = threadIdx.x & 31;
    const int s = gw >> 5, h = gw & 31;
    float vals[6]; float ss = 0.f;
#pragma unroll
    for (int t = 0; t < 6; t++) {
        int d = lane + 32 * t;
        float x;
        if (d < 128) {
            x = is_k ? kc[(size_t)s * HID + h * 128 + d]
                     : qc[(size_t)s * HID + h * 128 + d];
        } else if (!is_k) {
            int j = h * 64 + (d - 128);
            int base = (j < 1024) ? j : j - 1024;
            float ex  = (float)(2 * base) / 2048.0f;
            float inv = 1.0f / powf(10000.0f, ex);
            float sn, c;
            sincosf((float)s * inv, &sn, &c);
            if (j < 1024)
                x = qr[(size_t)s * 2048 + j] * c - qr[(size_t)s * 2048 + j + 1024] * sn;
            else
                x = qr[(size_t)s * 2048 + j] * c + qr[(size_t)s * 2048 + base] * sn;
        } else {
            int j = d - 128;
            int base = (j < 32) ? j : j - 32;
            float ex  = (float)(2 * base) / 64.0f;
            float inv = 1.0f / powf(10000.0f, ex);
            float sn, c;
            sincosf((float)s * inv, &sn, &c);
            if (j < 32)
                x = kr[(size_t)s * 128 + j] * c - kr[(size_t)s * 128 + j + 32] * sn;
            else
                x = kr[(size_t)s * 128 + j] * c + kr[(size_t)s * 128 + base] * sn;
        }
        vals[t] = x; ss += x * x;
    }
#pragma unroll
    for (int o = 16; o; o >>= 1) ss += __shfl_xor_sync(0xffffffffu, ss, o);
    float r = rsqrtf(ss * (1.f / 192.f) + 1.1920929e-7f);
    __nv_bfloat16* dh = is_k ? kh : qh;
    __nv_bfloat16* dl = is_k ? kl : ql;
#pragma unroll
    for (int t = 0; t < 6; t++) {
        float x = vals[t] * r;
        __nv_bfloat16 hb = __float2bfloat16(x);
        size_t o_ = ((size_t)s * NH + h) * DQK + lane + 32 * t;
        dh[o_] = hb;
        dl[o_] = __float2bfloat16(x - __bfloat162float(hb));
    }
}

// ---------------------------------------------------------------------------
// flash attention: register P, double-buffered V, mask prefetch at chunk top,
// load_v deferred past kt=0 QK block (critical-path reorder).
// ---------------------------------------------------------------------------
#define OQH 0
#define OQL (128*400)
#define OKH (2*128*400)
#define OKL (OKH + 64*400)
#define OVB (OKL + 64*400)
#define VHALF (64*272)
#define VBUF (2*VHALF)
#define ATT_SMEM (OVB + 2*VBUF)

__global__ void __launch_bounds__(256, 1)
attn_mma_kernel(const __nv_bfloat16* __restrict__ qhi, const __nv_bfloat16* __restrict__ qlo,
                const __nv_bfloat16* __restrict__ khi, const __nv_bfloat16* __restrict__ klo,
                const __nv_bfloat16* __restrict__ vhi, const __nv_bfloat16* __restrict__ vlo,
                const float* __restrict__ mask,
                __nv_bfloat16* __restrict__ aoh, __nv_bfloat16* __restrict__ aol) {
    extern __shared__ char smraw[];
    const uint32_t s0 = smem_u32(smraw);
    const int h = blockIdx.y, q0 = blockIdx.x * 128;
    const int tid = threadIdx.x, wid = tid >> 5, lane = tid & 31;

    for (int i = tid; i < 3072; i += 256) {
        int r = i / 24, cb = i % 24;
        size_t src = ((size_t)(q0 + r) * NH + h) * DQK + cb * 8;
        CP_ASYNC16(s0 + OQH + r * 400 + cb * 16, qhi + src);
        CP_ASYNC16(s0 + OQL + r * 400 + cb * 16, qlo + src);
    }
    CP_COMMIT();

    auto load_k = [&](int k0) {
        for (int i = tid; i < 1536; i += 256) {
            int r = i / 24, cb = i % 24;
            size_t src = ((size_t)(k0 + r) * NH + h) * DQK + cb * 8;
            CP_ASYNC16(s0 + OKH + r * 400 + cb * 16, khi + src);
            CP_ASYNC16(s0 + OKL + r * 400 + cb * 16, klo + src);
        }
        CP_COMMIT();
    };
    auto load_v = [&](int k0, int buf) {
        const uint32_t vb = s0 + OVB + buf * VBUF;
        for (int i = tid; i < 1024; i += 256) {
            int r = i / 16, cb = i % 16;
            size_t src = (size_t)(k0 + r) * HID + h * DV + cb * 8;
            CP_ASYNC16(vb + r * 272 + cb * 16, vhi + src);
            CP_ASYNC16(vb + VHALF + r * 272 + cb * 16, vlo + src);
        }
        CP_COMMIT();
    };
    load_k(0);
    load_v(0, 0);

    const float scale = 1.0f / sqrtf(192.0f);
    float m0 = -1e30f, m1 = -1e30f, l0 = 0.f, l1 = 0.f;
    float acc[16][4];
#pragma unroll
    for (int nt = 0; nt < 16; nt++)
#pragma unroll
        for (int e = 0; e < 4; e++) acc[nt][e] = 0.f;

    const int a_r  = (lane & 7) + ((lane >> 3) & 1) * 8;
    const int a_k  = (lane >> 4) * 8;
    const int bk_r = (lane & 7) + (lane >> 4) * 8;
    const int bk_k = ((lane >> 3) & 1) * 8;
    const int prow  = lane >> 2;
    const int pcol2 = (lane & 3) * 2;
    const int rg0 = q0 + wid * 16 + prow;

    for (int c = 0; c < 32; c++) {
        const int k0 = c * 64;
        CP_WAIT(0);
        __syncthreads();

        // ---- prefetch mask into registers (consumed ~QK-duration later) ----
        float mk[8][4];
#pragma unroll
        for (int nt = 0; nt < 8; nt++) {
            int col = k0 + nt * 8 + pcol2;
            float2 m0v = *(const float2*)&mask[(size_t)rg0 * S_LEN + col];
            float2 m1v = *(const float2*)&mask[(size_t)(rg0 + 8) * S_LEN + col];
            mk[nt][0] = m0v.x; mk[nt][1] = m0v.y;
            mk[nt][2] = m1v.x; mk[nt][3] = m1v.y;
        }

        // ---- S = Q K^T ----
        float sacc[8][4];
#pragma unroll
        for (int nt = 0; nt < 8; nt++)
#pragma unroll
            for (int e = 0; e < 4; e++) sacc[nt][e] = 0.f;

#pragma unroll
        for (int kt = 0; kt < 12; kt++) {
            uint32_t ah[4], al[4];
            ldmx4(ah[0], ah[1], ah[2], ah[3],
                  s0 + OQH + (wid * 16 + a_r) * 400 + (kt * 16 + a_k) * 2);
            ldmx4(al[0], al[1], al[2], al[3],
                  s0 + OQL + (wid * 16 + a_r) * 400 + (kt * 16 + a_k) * 2);
            uint32_t bh[4][4], bl[4][4];
#pragma unroll
            for (int n2 = 0; n2 < 4; n2++) {
                uint32_t rb = (n2 * 16 + bk_r) * 400 + (kt * 16 + bk_k) * 2;
                ldmx4(bh[n2][0], bh[n2][1], bh[n2][2], bh[n2][3], s0 + OKH + rb);
                ldmx4(bl[n2][0], bl[n2][1], bl[n2][2], bl[n2][3], s0 + OKL + rb);
            }
#pragma unroll
            for (int n2 = 0; n2 < 4; n2++) {
                mma_bf16(sacc[n2 * 2],     ah, &bh[n2][0]);
                mma_bf16(sacc[n2 * 2 + 1], ah, &bh[n2][2]);
            }
#pragma unroll
            for (int n2 = 0; n2 < 4; n2++) {
                mma_bf16(sacc[n2 * 2],     al, &bh[n2][0]);
                mma_bf16(sacc[n2 * 2 + 1], al, &bh[n2][2]);
            }
#pragma unroll
            for (int n2 = 0; n2 < 4; n2++) {
                mma_bf16(sacc[n2 * 2],     ah, &bl[n2][0]);
                mma_bf16(sacc[n2 * 2 + 1], ah, &bl[n2][2]);
            }
            // defer V prefetch until after the first MMA block (critical path)
            if (kt == 0 && c + 1 < 32) load_v(k0 + 64, (c + 1) & 1);
        }
        __syncthreads();
        if (c + 1 < 32) load_k(k0 + 64);

        // ---- softmax (warp-local rows), scale+mask folded into sacc ----
        float mx0 = -1e30f, mx1 = -1e30f;
#pragma unroll
        for (int nt = 0; nt < 8; nt++) {
            sacc[nt][0] = sacc[nt][0] * scale + mk[nt][0];
            sacc[nt][1] = sacc[nt][1] * scale + mk[nt][1];
            sacc[nt][2] = sacc[nt][2] * scale + mk[nt][2];
            sacc[nt][3] = sacc[nt][3] * scale + mk[nt][3];
            mx0 = fmaxf(mx0, fmaxf(sacc[nt][0], sacc[nt][1]));
            mx1 = fmaxf(mx1, fmaxf(sacc[nt][2], sacc[nt][3]));
        }
        mx0 = fmaxf(mx0, __shfl_xor_sync(0xffffffffu, mx0, 1));
        mx0 = fmaxf(mx0, __shfl_xor_sync(0xffffffffu, mx0, 2));
        mx1 = fmaxf(mx1, __shfl_xor_sync(0xffffffffu, mx1, 1));
        mx1 = fmaxf(mx1, __shfl_xor_sync(0xffffffffu, mx1, 2));
        float mn0 = fmaxf(m0, mx0), mn1 = fmaxf(m1, mx1);
        float al0 = __expf(m0 - mn0), al1 = __expf(m1 - mn1);
        m0 = mn0; m1 = mn1;

        uint32_t pfh[4][4], pfl[4][4];
        float ps0 = 0.f, ps1 = 0.f;
#pragma unroll
        for (int nt = 0; nt < 8; nt++) {
            float p00 = __expf(sacc[nt][0] - mn0), p01 = __expf(sacc[nt][1] - mn0);
            float p10 = __expf(sacc[nt][2] - mn1), p11 = __expf(sacc[nt][3] - mn1);
            ps0 += p00 + p01; ps1 += p10 + p11;
            const int kt = nt >> 1, sl = (nt & 1) * 2;
            pfh[kt][sl + 0] = pack_hi(p00, p01);
            pfh[kt][sl + 1] = pack_hi(p10, p11);
            pfl[kt][sl + 0] = pack_lo(p00, p01);
            pfl[kt][sl + 1] = pack_lo(p10, p11);
        }
        ps0 += __shfl_xor_sync(0xffffffffu, ps0, 1);
        ps0 += __shfl_xor_sync(0xffffffffu, ps0, 2);
        ps1 += __shfl_xor_sync(0xffffffffu, ps1, 1);
        ps1 += __shfl_xor_sync(0xffffffffu, ps1, 2);
        l0 = al0 * l0 + ps0;
        l1 = al1 * l1 + ps1;
#pragma unroll
        for (int nt = 0; nt < 16; nt++) {
            acc[nt][0] *= al0; acc[nt][1] *= al0;
            acc[nt][2] *= al1; acc[nt][3] *= al1;
        }

        // ---- O += P V (register P; V buffer c&1) ----
        const uint32_t vb = s0 + OVB + (c & 1) * VBUF;
#pragma unroll
        for (int kt = 0; kt < 4; kt++) {
#pragma unroll
            for (int n2 = 0; n2 < 8; n2++) {
                uint32_t vh[4], vl[4];
                uint32_t rv = (kt * 16 + a_r) * 272 + (n2 * 16 + a_k) * 2;
                ldmx4t(vh[0], vh[1], vh[2], vh[3], vb + rv);
                ldmx4t(vl[0], vl[1], vl[2], vl[3], vb + VHALF + rv);
                uint32_t vh0[2] = { vh[0], vh[1] }, vh1[2] = { vh[2], vh[3] };
                uint32_t vl0[2] = { vl[0], vl[1] }, vl1[2] = { vl[2], vl[3] };
                mma_bf16(acc[n2 * 2],     pfh[kt], vh0);
                mma_bf16(acc[n2 * 2 + 1], pfh[kt], vh1);
                mma_bf16(acc[n2 * 2],     pfl[kt], vh0);
                mma_bf16(acc[n2 * 2 + 1], pfl[kt], vh1);
                mma_bf16(acc[n2 * 2],     pfh[kt], vl0);
                mma_bf16(acc[n2 * 2 + 1], pfh[kt], vl1);
            }
        }
    }

    const float i0 = 1.f / l0, i1 = 1.f / l1;
    const int orow = q0 + wid * 16 + prow;
#pragma unroll
    for (int nt = 0; nt < 16; nt++) {
        int col = h * DV + nt * 8 + pcol2;
        float v0 = acc[nt][0] * i0, v1 = acc[nt][1] * i0;
        float v2 = acc[nt][2] * i1, v3 = acc[nt][3] * i1;
        *(uint32_t*)&aoh[(size_t)orow * HID + col]       = pack_hi(v0, v1);
        *(uint32_t*)&aoh[(size_t)(orow + 8) * HID + col] = pack_hi(v2, v3);
        *(uint32_t*)&aol[(size_t)orow * HID + col]       = pack_lo(v0, v1);
        *(uint32_t*)&aol[(size_t)(orow + 8) * HID + col] = pack_lo(v2, v3);
    }
}

// ---------------------------------------------------------------------------
// launcher
// ---------------------------------------------------------------------------
extern "C" void kernel_launch(void* const* d_in, const int* in_sizes, int n_in,
                              void* d_out, int out_size) {
    const float* hidden  = (const float*)d_in[0];
    const float* mask    = (const float*)d_in[1];
    const float* Wq_lr   = (const float*)d_in[2];
    const float* bq_lr   = (const float*)d_in[3];
    const float* Wq_rope = (const float*)d_in[4];
    const float* bq_rope = (const float*)d_in[5];
    const float* Wq_c    = (const float*)d_in[6];
    const float* bq_c    = (const float*)d_in[7];
    const float* Wkv     = (const float*)d_in[8];
    const float* bkv     = (const float*)d_in[9];
    const float* Wk_rope = (const float*)d_in[10];
    const float* bk_rope = (const float*)d_in[11];
    const float* Wk_c    = (const float*)d_in[12];
    const float* bk_c    = (const float*)d_in[13];
    const float* Wv      = (const float*)d_in[14];
    const float* bv      = (const float*)d_in[15];
    const float* Wo      = (const float*)d_in[16];
    const float* bo      = (const float*)d_in[17];
    float* out = (float*)d_out;

    float *qc, *qr, *kc, *kr, *bkr;
    cudaGetSymbolAddress((void**)&qc,  g_qc);
    cudaGetSymbolAddress((void**)&qr,  g_qr);
    cudaGetSymbolAddress((void**)&kc,  g_kc);
    cudaGetSymbolAddress((void**)&kr,  g_kr);
    cudaGetSymbolAddress((void**)&bkr, g_bkr);

    __nv_bfloat16 *h_hi, *h_lo, *cq_hi, *cq_lo, *ckv_hi, *ckv_lo, *ao_hi, *ao_lo;
    __nv_bfloat16 *Wqlr_hi, *Wqlr_lo, *Wqc_hi, *Wqc_lo, *Wqr_hi, *Wqr_lo;
    __nv_bfloat16 *Wkv_hi, *Wkv_lo, *Wkc_hi, *Wkc_lo, *Wv_hi, *Wv_lo, *Wo_hi, *Wo_lo;
    __nv_bfloat16 *Wkr_hi, *Wkr_lo, *qhi, *qlo, *khi, *klo, *vhi, *vlo;
    cudaGetSymbolAddress((void**)&h_hi,   g_h_hi);   cudaGetSymbolAddress((void**)&h_lo,   g_h_lo);
    cudaGetSymbolAddress((void**)&cq_hi,  g_cq_hi);  cudaGetSymbolAddress((void**)&cq_lo,  g_cq_lo);
    cudaGetSymbolAddress((void**)&ckv_hi, g_ckv_hi); cudaGetSymbolAddress((void**)&ckv_lo, g_ckv_lo);
    cudaGetSymbolAddress((void**)&ao_hi,  g_ao_hi);  cudaGetSymbolAddress((void**)&ao_lo,  g_ao_lo);
    cudaGetSymbolAddress((void**)&Wqlr_hi, g_Wqlr_hi); cudaGetSymbolAddress((void**)&Wqlr_lo, g_Wqlr_lo);
    cudaGetSymbolAddress((void**)&Wqc_hi,  g_Wqc_hi);  cudaGetSymbolAddress((void**)&Wqc_lo,  g_Wqc_lo);
    cudaGetSymbolAddress((void**)&Wqr_hi,  g_Wqr_hi);  cudaGetSymbolAddress((void**)&Wqr_lo,  g_Wqr_lo);
    cudaGetSymbolAddress((void**)&Wkv_hi,  g_Wkv_hi);  cudaGetSymbolAddress((void**)&Wkv_lo,  g_Wkv_lo);
    cudaGetSymbolAddress((void**)&Wkc_hi,  g_Wkc_hi);  cudaGetSymbolAddress((void**)&Wkc_lo,  g_Wkc_lo);
    cudaGetSymbolAddress((void**)&Wv_hi,   g_Wv_hi);   cudaGetSymbolAddress((void**)&Wv_lo,   g_Wv_lo);
    cudaGetSymbolAddress((void**)&Wo_hi,   g_Wo_hi);   cudaGetSymbolAddress((void**)&Wo_lo,   g_Wo_lo);
    cudaGetSymbolAddress((void**)&Wkr_hi,  g_Wkr_hi);  cudaGetSymbolAddress((void**)&Wkr_lo,  g_Wkr_lo);
    cudaGetSymbolAddress((void**)&qhi, g_qhi); cudaGetSymbolAddress((void**)&qlo, g_qlo);
    cudaGetSymbolAddress((void**)&khi, g_khi); cudaGetSymbolAddress((void**)&klo, g_klo);
    cudaGetSymbolAddress((void**)&vhi, g_vhi); cudaGetSymbolAddress((void**)&vlo, g_vlo);

    cudaFuncSetAttribute(mma_gemm6, cudaFuncAttributeMaxDynamicSharedMemorySize, G_SMEM);

    SJobs jobs;
    const float* srcs[8] = { hidden, Wq_lr, Wq_c, Wq_rope, Wkv, Wk_c, Wv, Wo };
    __nv_bfloat16* his[8] = { h_hi, Wqlr_hi, Wqc_hi, Wqr_hi, Wkv_hi, Wkc_hi, Wv_hi, Wo_hi };
    __nv_bfloat16* los[8] = { h_lo, Wqlr_lo, Wqc_lo, Wqr_lo, Wkv_lo, Wkc_lo, Wv_lo, Wo_lo };
    int ns[8] = { 2048*4096, 1536*4096, 4096*1536, 2048*1536,
                  512*4096, 4096*512, 4096*512, 4096*4096 };
    int blk = 0;
    for (int i = 0; i < 8; i++) {
        jobs.j[i].x = srcs[i]; jobs.j[i].hi = his[i]; jobs.j[i].lo = los[i];
        jobs.j[i].n8 = ns[i] / 8; jobs.j[i].blk0 = blk;
        blk += (jobs.j[i].n8 + 255) / 256;
    }
    multi_split_kernel<<<blk, 256>>>(jobs);
    pad_krope_kernel<<<(128 * 4096 + 255) / 256, 256>>>(Wk_rope, Wkr_hi, Wkr_lo, bk_rope, bkr);

    const int NONE = 0x7FFFFFFF;

    // G1: A = hidden (K=4096): c_q, c_kv, k_rope
    {
        GJobs g{};
        g.j[0] = { h_hi, h_lo, Wqlr_hi, Wqlr_lo, bq_lr, nullptr, cq_hi, cq_lo, 1536, 4096, 0, 0 };
        g.j[1] = { h_hi, h_lo, Wkv_hi,  Wkv_lo,  bkv,   nullptr, ckv_hi, ckv_lo, 512, 4096, 12, 0 };
        g.j[2] = { h_hi, h_lo, Wkr_hi,  Wkr_lo,  bkr,   kr, nullptr, nullptr, 128, 4096, 16, 0 };
        g.j[3] = g.j[2]; g.j[3].blk0 = NONE;
        mma_gemm6<<<dim3(17, 16), 128, G_SMEM>>>(g);
    }
    // G2+G3
    {
        GJobs g{};
        g.j[0] = { cq_hi, cq_lo, Wqc_hi, Wqc_lo, bq_c,    qc, nullptr, nullptr, 4096, 1536, 0,  0 };
        g.j[1] = { cq_hi, cq_lo, Wqr_hi, Wqr_lo, bq_rope, qr, nullptr, nullptr, 2048, 1536, 32, 0 };
        g.j[2] = { ckv_hi, ckv_lo, Wkc_hi, Wkc_lo, bk_c,  kc, nullptr, nullptr, 4096, 512, 48, 0 };
        g.j[3] = { ckv_hi, ckv_lo, Wv_hi,  Wv_lo,  bv, nullptr, vhi, vlo,       4096, 512, 80, 0 };
        mma_gemm6<<<dim3(112, 16), 128, G_SMEM>>>(g);
    }

    fuse_qk_kernel<<<16384, 256>>>(qc, qr, kc, kr, qhi, qlo, khi, klo);

    cudaFuncSetAttribute(attn_mma_kernel, cudaFuncAttributeMaxDynamicSharedMemorySize, ATT_SMEM);
    attn_mma_kernel<<<dim3(S_LEN / 128, NH), 256, ATT_SMEM>>>(
        qhi, qlo, khi, klo, vhi, vlo, mask, ao_hi, ao_lo);

    // G4: out = ao @ Wo^T
    {
        GJobs g{};
        g.j[0] = { ao_hi, ao_lo, Wo_hi, Wo_lo, bo, out, nullptr, nullptr, 4096, 4096, 0, 0 };
        g.j[1] = g.j[0]; g.j[1].blk0 = NONE;
        g.j[2] = g.j[0]; g.j[2].blk0 = NONE;
        g.j[3] = g.j[0]; g.j[3].blk0 = NONE;
        mma_gemm6<<<dim3(32, 16), 128, G_SMEM>>>(g);
    }
}

// round 13
// speedup vs baseline: 6.0513x; 1.0044x over previous
#include <cuda_runtime.h>
#include <cuda_bf16.h>
#include <math.h>
#include <stdint.h>

#define S_LEN 2048
#define HID   4096
#define NH    32
#define DQK   192
#define DV    128

// ---------------------------------------------------------------------------
// scratch (device globals; no allocations allowed)
// ---------------------------------------------------------------------------
__device__ float g_qc [2048*4096];
__device__ float g_qr [2048*2048];
__device__ float g_kc [2048*4096];
__device__ float g_kr [2048*128];
__device__ float g_bkr[128];

__device__ __align__(16) __nv_bfloat16 g_h_hi [2048*4096], g_h_lo [2048*4096];
__device__ __align__(16) __nv_bfloat16 g_cq_hi[2048*1536], g_cq_lo[2048*1536];
__device__ __align__(16) __nv_bfloat16 g_ckv_hi[2048*512], g_ckv_lo[2048*512];
__device__ __align__(16) __nv_bfloat16 g_ao_hi[2048*4096], g_ao_lo[2048*4096];
__device__ __align__(16) __nv_bfloat16 g_Wqlr_hi[1536*4096], g_Wqlr_lo[1536*4096];
__device__ __align__(16) __nv_bfloat16 g_Wqc_hi [4096*1536], g_Wqc_lo [4096*1536];
__device__ __align__(16) __nv_bfloat16 g_Wqr_hi [2048*1536], g_Wqr_lo [2048*1536];
__device__ __align__(16) __nv_bfloat16 g_Wkv_hi [512*4096],  g_Wkv_lo [512*4096];
__device__ __align__(16) __nv_bfloat16 g_Wkc_hi [4096*512],  g_Wkc_lo [4096*512];
__device__ __align__(16) __nv_bfloat16 g_Wv_hi  [4096*512],  g_Wv_lo  [4096*512];
__device__ __align__(16) __nv_bfloat16 g_Wo_hi  [4096*4096], g_Wo_lo  [4096*4096];
__device__ __align__(16) __nv_bfloat16 g_Wkr_hi [128*4096],  g_Wkr_lo [128*4096];

__device__ __align__(16) __nv_bfloat16 g_qhi[2048*32*192], g_qlo[2048*32*192];
__device__ __align__(16) __nv_bfloat16 g_khi[2048*32*192], g_klo[2048*32*192];
__device__ __align__(16) __nv_bfloat16 g_vhi[2048*4096],   g_vlo[2048*4096];

// ---------------------------------------------------------------------------
// small PTX helpers
// ---------------------------------------------------------------------------
__device__ __forceinline__ uint32_t smem_u32(const void* p) {
    uint32_t a;
    asm("{ .reg .u64 t; cvta.to.shared.u64 t, %1; cvt.u32.u64 %0, t; }" : "=r"(a) : "l"(p));
    return a;
}
#define CP_ASYNC16(dst_u32, src_ptr) \
    asm volatile("cp.async.cg.shared.global [%0], [%1], 16;" \
                 :: "r"(dst_u32), "l"(__cvta_generic_to_global(src_ptr)) : "memory")
#define CP_COMMIT() asm volatile("cp.async.commit_group;" ::: "memory")
#define CP_WAIT(n)  asm volatile("cp.async.wait_group %0;" :: "n"(n) : "memory")

__device__ __forceinline__ void ldmx4(uint32_t& r0, uint32_t& r1, uint32_t& r2, uint32_t& r3,
                                      uint32_t addr) {
    asm volatile("ldmatrix.sync.aligned.m8n8.x4.shared.b16 {%0,%1,%2,%3}, [%4];"
                 : "=r"(r0), "=r"(r1), "=r"(r2), "=r"(r3) : "r"(addr));
}
__device__ __forceinline__ void ldmx4t(uint32_t& r0, uint32_t& r1, uint32_t& r2, uint32_t& r3,
                                       uint32_t addr) {
    asm volatile("ldmatrix.sync.aligned.m8n8.x4.trans.shared.b16 {%0,%1,%2,%3}, [%4];"
                 : "=r"(r0), "=r"(r1), "=r"(r2), "=r"(r3) : "r"(addr));
}
__device__ __forceinline__ void mma_bf16(float* d, const uint32_t* a, const uint32_t* b) {
    asm volatile("mma.sync.aligned.m16n8k16.row.col.f32.bf16.bf16.f32 "
                 "{%0,%1,%2,%3}, {%4,%5,%6,%7}, {%8,%9}, {%0,%1,%2,%3};"
                 : "+f"(d[0]), "+f"(d[1]), "+f"(d[2]), "+f"(d[3])
                 : "r"(a[0]), "r"(a[1]), "r"(a[2]), "r"(a[3]), "r"(b[0]), "r"(b[1]));
}
__device__ __forceinline__ uint32_t pack_hi(float a, float b) {
    __nv_bfloat16 ha = __float2bfloat16(a), hb = __float2bfloat16(b);
    return (uint32_t)__bfloat16_as_ushort(ha) | ((uint32_t)__bfloat16_as_ushort(hb) << 16);
}
__device__ __forceinline__ uint32_t pack_lo(float a, float b) {
    __nv_bfloat16 ha = __float2bfloat16(a), hb = __float2bfloat16(b);
    __nv_bfloat16 la = __float2bfloat16(a - __bfloat162float(ha));
    __nv_bfloat16 lb = __float2bfloat16(b - __bfloat162float(hb));
    return (uint32_t)__bfloat16_as_ushort(la) | ((uint32_t)__bfloat16_as_ushort(lb) << 16);
}

// ---------------------------------------------------------------------------
// mega split: 2x float4 per thread, 128-bit stores
// ---------------------------------------------------------------------------
struct SJob { const float* x; __nv_bfloat16* hi; __nv_bfloat16* lo; int n8; int blk0; };
struct SJobs { SJob j[8]; };

__global__ void multi_split_kernel(SJobs jobs) {
    int b = blockIdx.x;
    int ji = 0;
#pragma unroll
    for (int t = 1; t < 8; t++)
        if (b >= jobs.j[t].blk0) ji = t;
    const SJob jb = jobs.j[ji];
    int i = (b - jb.blk0) * 256 + threadIdx.x;
    if (i >= jb.n8) return;
    float4 v0 = ((const float4*)jb.x)[i * 2];
    float4 v1 = ((const float4*)jb.x)[i * 2 + 1];
    uint4 H, L;
    H.x = pack_hi(v0.x, v0.y); H.y = pack_hi(v0.z, v0.w);
    H.z = pack_hi(v1.x, v1.y); H.w = pack_hi(v1.z, v1.w);
    L.x = pack_lo(v0.x, v0.y); L.y = pack_lo(v0.z, v0.w);
    L.z = pack_lo(v1.x, v1.y); L.w = pack_lo(v1.z, v1.w);
    ((uint4*)jb.hi)[i] = H;
    ((uint4*)jb.lo)[i] = L;
}

__global__ void pad_krope_kernel(const float* __restrict__ W,
                                 __nv_bfloat16* __restrict__ hi,
                                 __nv_bfloat16* __restrict__ lo,
                                 const float* __restrict__ b,
                                 float* __restrict__ bp) {
    int i = blockIdx.x * blockDim.x + threadIdx.x;
    if (i < 128) bp[i] = (i < 64) ? b[i] : 0.f;
    if (i >= 128 * 4096) return;
    int r = i >> 12;
    float v = (r < 64) ? W[(size_t)r * 4096 + (i & 4095)] : 0.f;
    __nv_bfloat16 h = __float2bfloat16(v);
    hi[i] = h;
    lo[i] = __float2bfloat16(v - __bfloat162float(h));
}

// ---------------------------------------------------------------------------
// batched GEMM (unchanged from R12 passing version)
// ---------------------------------------------------------------------------
#define OA_HI 0
#define OA_LO 8192
#define OW_HI 16384
#define OW_LO 24576
#define ST_BUF 32768
#define G_SMEM (3 * ST_BUF)

__device__ __forceinline__ uint32_t swz64(int r, int c) {
    return (uint32_t)(r * 64 + ((c ^ ((r >> 1) & 3)) << 4));
}

struct GJob {
    const __nv_bfloat16 *Ahi, *Alo, *Whi, *Wlo;
    const float* bias;
    float* Cf;
    __nv_bfloat16 *Chi, *Clo;
    int N, K, blk0, pad_;
};
struct GJobs { GJob j[4]; };

__global__ void __launch_bounds__(128)
mma_gemm6(GJobs jobs) {
    extern __shared__ char gsm[];
    const uint32_t s0 = smem_u32(gsm);
    const int tid = threadIdx.x, wid = tid >> 5, lane = tid & 31;
    const int warp_m = wid >> 1, warp_n = wid & 1;

    int bx = blockIdx.x;
    int ji = 0;
#pragma unroll
    for (int t = 1; t < 4; t++)
        if (bx >= jobs.j[t].blk0) ji = t;
    const GJob jb = jobs.j[ji];
    const int col0 = (bx - jb.blk0) * 128;
    const int row0 = blockIdx.y * 128;
    const int K = jb.K, N = jb.N;

    const int a_row = (lane & 7) + ((lane >> 3) & 1) * 8;
    const int b_row = (lane & 7) + (lane >> 4) * 8;
    const int a_c   = (lane >> 4);
    const int b_c   = ((lane >> 3) & 1);

    uint32_t adA[4][2], adW[4][2];
#pragma unroll
    for (int mt = 0; mt < 4; mt++) {
        int rr = warp_m * 64 + mt * 16 + a_row;
#pragma unroll
        for (int ks = 0; ks < 2; ks++)
            adA[mt][ks] = OA_HI + swz64(rr, ks * 2 + a_c);
    }
#pragma unroll
    for (int np = 0; np < 4; np++) {
        int rr = warp_n * 64 + np * 16 + b_row;
#pragma unroll
        for (int ks = 0; ks < 2; ks++)
            adW[np][ks] = OW_HI + swz64(rr, ks * 2 + b_c);
    }

    const int kc = K >> 5;

    float acc[4][8][4];
#pragma unroll
    for (int mt = 0; mt < 4; mt++)
#pragma unroll
        for (int nt = 0; nt < 8; nt++)
#pragma unroll
            for (int e = 0; e < 4; e++) acc[mt][nt][e] = 0.f;

    auto load_chunk = [&](int c, int st) {
        const int kk = c << 5;
        const uint32_t base = s0 + st * ST_BUF;
#pragma unroll
        for (int i = 0; i < 4; i++) {
            int idx = tid + i * 128;
            int r = idx >> 2, cb = idx & 3;
            uint32_t doff = swz64(r, cb);
            size_t src = (size_t)(row0 + r) * K + kk + cb * 8;
            CP_ASYNC16(base + OA_HI + doff, jb.Ahi + src);
            CP_ASYNC16(base + OA_LO + doff, jb.Alo + src);
        }
#pragma unroll
        for (int i = 0; i < 4; i++) {
            int idx = tid + i * 128;
            int r = idx >> 2, cb = idx & 3;
            uint32_t doff = swz64(r, cb);
            size_t src = (size_t)(col0 + r) * K + kk + cb * 8;
            CP_ASYNC16(base + OW_HI + doff, jb.Whi + src);
            CP_ASYNC16(base + OW_LO + doff, jb.Wlo + src);
        }
        CP_COMMIT();
    };

    load_chunk(0, 0);
    load_chunk(1, 1);

    int st = 0, ls = 2;
    for (int c = 0; c < kc; c++) {
        if (c + 1 < kc) { CP_WAIT(1); } else { CP_WAIT(0); }
        __syncthreads();
        const uint32_t base = s0 + st * ST_BUF;

        // ks = 0 (critical path first)
        {
            uint32_t ah[4][4], al[4][4];
#pragma unroll
            for (int mt = 0; mt < 4; mt++) {
                uint32_t ra = base + adA[mt][0];
                ldmx4(ah[mt][0], ah[mt][1], ah[mt][2], ah[mt][3], ra);
                ldmx4(al[mt][0], al[mt][1], al[mt][2], al[mt][3], ra + (OA_LO - OA_HI));
            }
#pragma unroll
            for (int np = 0; np < 4; np++) {
                uint32_t bh[4], bl[4];
                uint32_t rb = base + adW[np][0];
                ldmx4(bh[0], bh[1], bh[2], bh[3], rb);
                ldmx4(bl[0], bl[1], bl[2], bl[3], rb + (OW_LO - OW_HI));
#pragma unroll
                for (int j = 0; j < 2; j++) {
                    uint32_t b2h[2] = { bh[j * 2], bh[j * 2 + 1] };
                    uint32_t b2l[2] = { bl[j * 2], bl[j * 2 + 1] };
                    const int nt = np * 2 + j;
#pragma unroll
                    for (int mt = 0; mt < 4; mt++) mma_bf16(acc[mt][nt], ah[mt], b2h);
#pragma unroll
                    for (int mt = 0; mt < 4; mt++) mma_bf16(acc[mt][nt], al[mt], b2h);
#pragma unroll
                    for (int mt = 0; mt < 4; mt++) mma_bf16(acc[mt][nt], ah[mt], b2l);
                }
            }
        }

        if (c + 2 < kc) load_chunk(c + 2, ls);

        // ks = 1
        {
            uint32_t ah[4][4], al[4][4];
#pragma unroll
            for (int mt = 0; mt < 4; mt++) {
                uint32_t ra = base + adA[mt][1];
                ldmx4(ah[mt][0], ah[mt][1], ah[mt][2], ah[mt][3], ra);
                ldmx4(al[mt][0], al[mt][1], al[mt][2], al[mt][3], ra + (OA_LO - OA_HI));
            }
#pragma unroll
            for (int np = 0; np < 4; np++) {
                uint32_t bh[4], bl[4];
                uint32_t rb = base + adW[np][1];
                ldmx4(bh[0], bh[1], bh[2], bh[3], rb);
                ldmx4(bl[0], bl[1], bl[2], bl[3], rb + (OW_LO - OW_HI));
#pragma unroll
                for (int j = 0; j < 2; j++) {
                    uint32_t b2h[2] = { bh[j * 2], bh[j * 2 + 1] };
                    uint32_t b2l[2] = { bl[j * 2], bl[j * 2 + 1] };
                    const int nt = np * 2 + j;
#pragma unroll
                    for (int mt = 0; mt < 4; mt++) mma_bf16(acc[mt][nt], ah[mt], b2h);
#pragma unroll
                    for (int mt = 0; mt < 4; mt++) mma_bf16(acc[mt][nt], al[mt], b2h);
#pragma unroll
                    for (int mt = 0; mt < 4; mt++) mma_bf16(acc[mt][nt], ah[mt], b2l);
                }
            }
        }
        st = (st == 2) ? 0 : st + 1;
        ls = (ls == 2) ? 0 : ls + 1;
    }

    const int rbase = row0 + warp_m * 64 + (lane >> 2);
    const int cbase = col0 + warp_n * 64 + (lane & 3) * 2;
#pragma unroll
    for (int mt = 0; mt < 4; mt++) {
#pragma unroll
        for (int nt = 0; nt < 8; nt++) {
            const int cc = cbase + nt * 8;
            const float b0 = jb.bias[cc], b1 = jb.bias[cc + 1];
            const int r0 = rbase + mt * 16;
            float v0 = acc[mt][nt][0] + b0, v1 = acc[mt][nt][1] + b1;
            float v2 = acc[mt][nt][2] + b0, v3 = acc[mt][nt][3] + b1;
            if (jb.Cf) {
                *(float2*)&jb.Cf[(size_t)r0 * N + cc] = make_float2(v0, v1);
                *(float2*)&jb.Cf[(size_t)(r0 + 8) * N + cc] = make_float2(v2, v3);
            }
            if (jb.Chi) {
                *(uint32_t*)&jb.Chi[(size_t)r0 * N + cc]       = pack_hi(v0, v1);
                *(uint32_t*)&jb.Chi[(size_t)(r0 + 8) * N + cc] = pack_hi(v2, v3);
                *(uint32_t*)&jb.Clo[(size_t)r0 * N + cc]       = pack_lo(v0, v1);
                *(uint32_t*)&jb.Clo[(size_t)(r0 + 8) * N + cc] = pack_lo(v2, v3);
            }
        }
    }
}

// ---------------- merged concat + inline RoPE + RMSnorm (q and k) ------------
__global__ void fuse_qk_kernel(const float* __restrict__ qc,
                               const float* __restrict__ qr,
                               const float* __restrict__ kc,
                               const float* __restrict__ kr,
                               __nv_bfloat16* __restrict__ qh,
                               __nv_bfloat16* __restrict__ ql,
                               __nv_bfloat16* __restrict__ kh,
                               __nv_bfloat16* __restrict__ kl) {
    const bool is_k = blockIdx.x >= 8192;
    const int  bx   = is_k ? blockIdx.x - 8192 : blockIdx.x;
    const int gw   = ((bx * blockDim.x) + threadIdx.x) >> 5;
    const int lane = threadIdx.x & 31;
    const int s = gw >> 5, h = gw & 31;
    float vals[6]; float ss = 0.f;
#pragma unroll
    for (int t = 0; t < 6; t++) {
        int d = lane + 32 * t;
        float x;
        if (d < 128) {
            x = is_k ? kc[(size_t)s * HID + h * 128 + d]
                     : qc[(size_t)s * HID + h * 128 + d];
        } else if (!is_k) {
            int j = h * 64 + (d - 128);
            int base = (j < 1024) ? j : j - 1024;
            float ex  = (float)(2 * base) / 2048.0f;
            float inv = 1.0f / powf(10000.0f, ex);
            float sn, c;
            sincosf((float)s * inv, &sn, &c);
            if (j < 1024)
                x = qr[(size_t)s * 2048 + j] * c - qr[(size_t)s * 2048 + j + 1024] * sn;
            else
                x = qr[(size_t)s * 2048 + j] * c + qr[(size_t)s * 2048 + base] * sn;
        } else {
            int j = d - 128;
            int base = (j < 32) ? j : j - 32;
            float ex  = (float)(2 * base) / 64.0f;
            float inv = 1.0f / powf(10000.0f, ex);
            float sn, c;
            sincosf((float)s * inv, &sn, &c);
            if (j < 32)
                x = kr[(size_t)s * 128 + j] * c - kr[(size_t)s * 128 + j + 32] * sn;
            else
                x = kr[(size_t)s * 128 + j] * c + kr[(size_t)s * 128 + base] * sn;
        }
        vals[t] = x; ss += x * x;
    }
#pragma unroll
    for (int o = 16; o; o >>= 1) ss += __shfl_xor_sync(0xffffffffu, ss, o);
    float r = rsqrtf(ss * (1.f / 192.f) + 1.1920929e-7f);
    __nv_bfloat16* dh = is_k ? kh : qh;
    __nv_bfloat16* dl = is_k ? kl : ql;
#pragma unroll
    for (int t = 0; t < 6; t++) {
        float x = vals[t] * r;
        __nv_bfloat16 hb = __float2bfloat16(x);
        size_t o_ = ((size_t)s * NH + h) * DQK + lane + 32 * t;
        dh[o_] = hb;
        dl[o_] = __float2bfloat16(x - __bfloat162float(hb));
    }
}

// ---------------------------------------------------------------------------
// flash attention: 64 q-rows x 1 head per CTA (128 thr, 4 warps x 16 rows),
// 32-key chunks, register P, double-buffered V, mask prefetch -> 2 CTAs/SM.
// ---------------------------------------------------------------------------
#define OQH 0
#define OQL (64*400)
#define OKH (2*64*400)
#define OKL (OKH + 32*400)
#define OVB (OKL + 32*400)
#define VHALF (32*272)
#define VBUF (2*VHALF)
#define ATT_SMEM (OVB + 2*VBUF)   // 111616 bytes -> 2 CTAs/SM

__global__ void __launch_bounds__(128, 2)
attn_mma_kernel(const __nv_bfloat16* __restrict__ qhi, const __nv_bfloat16* __restrict__ qlo,
                const __nv_bfloat16* __restrict__ khi, const __nv_bfloat16* __restrict__ klo,
                const __nv_bfloat16* __restrict__ vhi, const __nv_bfloat16* __restrict__ vlo,
                const float* __restrict__ mask,
                __nv_bfloat16* __restrict__ aoh, __nv_bfloat16* __restrict__ aol) {
    extern __shared__ char smraw[];
    const uint32_t s0 = smem_u32(smraw);
    const int h = blockIdx.y, q0 = blockIdx.x * 64;
    const int tid = threadIdx.x, wid = tid >> 5, lane = tid & 31;

    // Q: 64 rows x 24 16B-chunks, hi+lo
    for (int i = tid; i < 1536; i += 128) {
        int r = i / 24, cb = i % 24;
        size_t src = ((size_t)(q0 + r) * NH + h) * DQK + cb * 8;
        CP_ASYNC16(s0 + OQH + r * 400 + cb * 16, qhi + src);
        CP_ASYNC16(s0 + OQL + r * 400 + cb * 16, qlo + src);
    }
    CP_COMMIT();

    auto load_k = [&](int k0) {
        for (int i = tid; i < 768; i += 128) {
            int r = i / 24, cb = i % 24;
            size_t src = ((size_t)(k0 + r) * NH + h) * DQK + cb * 8;
            CP_ASYNC16(s0 + OKH + r * 400 + cb * 16, khi + src);
            CP_ASYNC16(s0 + OKL + r * 400 + cb * 16, klo + src);
        }
        CP_COMMIT();
    };
    auto load_v = [&](int k0, int buf) {
        const uint32_t vb = s0 + OVB + buf * VBUF;
        for (int i = tid; i < 512; i += 128) {
            int r = i / 16, cb = i % 16;
            size_t src = (size_t)(k0 + r) * HID + h * DV + cb * 8;
            CP_ASYNC16(vb + r * 272 + cb * 16, vhi + src);
            CP_ASYNC16(vb + VHALF + r * 272 + cb * 16, vlo + src);
        }
        CP_COMMIT();
    };
    load_k(0);
    load_v(0, 0);

    const float scale = 1.0f / sqrtf(192.0f);
    float m0 = -1e30f, m1 = -1e30f, l0 = 0.f, l1 = 0.f;
    float acc[16][4];
#pragma unroll
    for (int nt = 0; nt < 16; nt++)
#pragma unroll
        for (int e = 0; e < 4; e++) acc[nt][e] = 0.f;

    const int a_r  = (lane & 7) + ((lane >> 3) & 1) * 8;
    const int a_k  = (lane >> 4) * 8;
    const int bk_r = (lane & 7) + (lane >> 4) * 8;
    const int bk_k = ((lane >> 3) & 1) * 8;
    const int prow  = lane >> 2;
    const int pcol2 = (lane & 3) * 2;
    const int rg0 = q0 + wid * 16 + prow;

    for (int c = 0; c < 64; c++) {
        const int k0 = c * 32;
        CP_WAIT(0);
        __syncthreads();

        // mask prefetch (consumed after QK)
        float mk[4][4];
#pragma unroll
        for (int nt = 0; nt < 4; nt++) {
            int col = k0 + nt * 8 + pcol2;
            float2 m0v = *(const float2*)&mask[(size_t)rg0 * S_LEN + col];
            float2 m1v = *(const float2*)&mask[(size_t)(rg0 + 8) * S_LEN + col];
            mk[nt][0] = m0v.x; mk[nt][1] = m0v.y;
            mk[nt][2] = m1v.x; mk[nt][3] = m1v.y;
        }

        // ---- S = Q K^T ----
        float sacc[4][4];
#pragma unroll
        for (int nt = 0; nt < 4; nt++)
#pragma unroll
            for (int e = 0; e < 4; e++) sacc[nt][e] = 0.f;

#pragma unroll
        for (int kt = 0; kt < 12; kt++) {
            uint32_t ah[4], al[4];
            ldmx4(ah[0], ah[1], ah[2], ah[3],
                  s0 + OQH + (wid * 16 + a_r) * 400 + (kt * 16 + a_k) * 2);
            ldmx4(al[0], al[1], al[2], al[3],
                  s0 + OQL + (wid * 16 + a_r) * 400 + (kt * 16 + a_k) * 2);
            uint32_t bh[2][4], bl[2][4];
#pragma unroll
            for (int n2 = 0; n2 < 2; n2++) {
                uint32_t rb = (n2 * 16 + bk_r) * 400 + (kt * 16 + bk_k) * 2;
                ldmx4(bh[n2][0], bh[n2][1], bh[n2][2], bh[n2][3], s0 + OKH + rb);
                ldmx4(bl[n2][0], bl[n2][1], bl[n2][2], bl[n2][3], s0 + OKL + rb);
            }
#pragma unroll
            for (int n2 = 0; n2 < 2; n2++) {
                mma_bf16(sacc[n2 * 2],     ah, &bh[n2][0]);
                mma_bf16(sacc[n2 * 2 + 1], ah, &bh[n2][2]);
            }
#pragma unroll
            for (int n2 = 0; n2 < 2; n2++) {
                mma_bf16(sacc[n2 * 2],     al, &bh[n2][0]);
                mma_bf16(sacc[n2 * 2 + 1], al, &bh[n2][2]);
            }
#pragma unroll
            for (int n2 = 0; n2 < 2; n2++) {
                mma_bf16(sacc[n2 * 2],     ah, &bl[n2][0]);
                mma_bf16(sacc[n2 * 2 + 1], ah, &bl[n2][2]);
            }
            if (kt == 0 && c + 1 < 64) load_v(k0 + 32, (c + 1) & 1);
        }
        __syncthreads();
        if (c + 1 < 64) load_k(k0 + 32);

        // ---- softmax (warp-local rows) ----
        float mx0 = -1e30f, mx1 = -1e30f;
#pragma unroll
        for (int nt = 0; nt < 4; nt++) {
            sacc[nt][0] = sacc[nt][0] * scale + mk[nt][0];
            sacc[nt][1] = sacc[nt][1] * scale + mk[nt][1];
            sacc[nt][2] = sacc[nt][2] * scale + mk[nt][2];
            sacc[nt][3] = sacc[nt][3] * scale + mk[nt][3];
            mx0 = fmaxf(mx0, fmaxf(sacc[nt][0], sacc[nt][1]));
            mx1 = fmaxf(mx1, fmaxf(sacc[nt][2], sacc[nt][3]));
        }
        mx0 = fmaxf(mx0, __shfl_xor_sync(0xffffffffu, mx0, 1));
        mx0 = fmaxf(mx0, __shfl_xor_sync(0xffffffffu, mx0, 2));
        mx1 = fmaxf(mx1, __shfl_xor_sync(0xffffffffu, mx1, 1));
        mx1 = fmaxf(mx1, __shfl_xor_sync(0xffffffffu, mx1, 2));
        float mn0 = fmaxf(m0, mx0), mn1 = fmaxf(m1, mx1);
        float al0 = __expf(m0 - mn0), al1 = __expf(m1 - mn1);
        m0 = mn0; m1 = mn1;

        uint32_t pfh[2][4], pfl[2][4];
        float ps0 = 0.f, ps1 = 0.f;
#pragma unroll
        for (int nt = 0; nt < 4; nt++) {
            float p00 = __expf(sacc[nt][0] - mn0), p01 = __expf(sacc[nt][1] - mn0);
            float p10 = __expf(sacc[nt][2] - mn1), p11 = __expf(sacc[nt][3] - mn1);
            ps0 += p00 + p01; ps1 += p10 + p11;
            const int kt = nt >> 1, sl = (nt & 1) * 2;
            pfh[kt][sl + 0] = pack_hi(p00, p01);
            pfh[kt][sl + 1] = pack_hi(p10, p11);
            pfl[kt][sl + 0] = pack_lo(p00, p01);
            pfl[kt][sl + 1] = pack_lo(p10, p11);
        }
        ps0 += __shfl_xor_sync(0xffffffffu, ps0, 1);
        ps0 += __shfl_xor_sync(0xffffffffu, ps0, 2);
        ps1 += __shfl_xor_sync(0xffffffffu, ps1, 1);
        ps1 += __shfl_xor_sync(0xffffffffu, ps1, 2);
        l0 = al0 * l0 + ps0;
        l1 = al1 * l1 + ps1;
#pragma unroll
        for (int nt = 0; nt < 16; nt++) {
            acc[nt][0] *= al0; acc[nt][1] *= al0;
            acc[nt][2] *= al1; acc[nt][3] *= al1;
        }

        // ---- O += P V (register P; V buffer c&1) ----
        const uint32_t vb = s0 + OVB + (c & 1) * VBUF;
#pragma unroll
        for (int kt = 0; kt < 2; kt++) {
#pragma unroll
            for (int n2 = 0; n2 < 8; n2++) {
                uint32_t vh[4], vl[4];
                uint32_t rv = (kt * 16 + a_r) * 272 + (n2 * 16 + a_k) * 2;
                ldmx4t(vh[0], vh[1], vh[2], vh[3], vb + rv);
                ldmx4t(vl[0], vl[1], vl[2], vl[3], vb + VHALF + rv);
                uint32_t vh0[2] = { vh[0], vh[1] }, vh1[2] = { vh[2], vh[3] };
                uint32_t vl0[2] = { vl[0], vl[1] }, vl1[2] = { vl[2], vl[3] };
                mma_bf16(acc[n2 * 2],     pfh[kt], vh0);
                mma_bf16(acc[n2 * 2 + 1], pfh[kt], vh1);
                mma_bf16(acc[n2 * 2],     pfl[kt], vh0);
                mma_bf16(acc[n2 * 2 + 1], pfl[kt], vh1);
                mma_bf16(acc[n2 * 2],     pfh[kt], vl0);
                mma_bf16(acc[n2 * 2 + 1], pfh[kt], vl1);
            }
        }
    }

    const float i0 = 1.f / l0, i1 = 1.f / l1;
    const int orow = q0 + wid * 16 + prow;
#pragma unroll
    for (int nt = 0; nt < 16; nt++) {
        int col = h * DV + nt * 8 + pcol2;
        float v0 = acc[nt][0] * i0, v1 = acc[nt][1] * i0;
        float v2 = acc[nt][2] * i1, v3 = acc[nt][3] * i1;
        *(uint32_t*)&aoh[(size_t)orow * HID + col]       = pack_hi(v0, v1);
        *(uint32_t*)&aoh[(size_t)(orow + 8) * HID + col] = pack_hi(v2, v3);
        *(uint32_t*)&aol[(size_t)orow * HID + col]       = pack_lo(v0, v1);
        *(uint32_t*)&aol[(size_t)(orow + 8) * HID + col] = pack_lo(v2, v3);
    }
}

// ---------------------------------------------------------------------------
// launcher
// ---------------------------------------------------------------------------
extern "C" void kernel_launch(void* const* d_in, const int* in_sizes, int n_in,
                              void* d_out, int out_size) {
    const float* hidden  = (const float*)d_in[0];
    const float* mask    = (const float*)d_in[1];
    const float* Wq_lr   = (const float*)d_in[2];
    const float* bq_lr   = (const float*)d_in[3];
    const float* Wq_rope = (const float*)d_in[4];
    const float* bq_rope = (const float*)d_in[5];
    const float* Wq_c    = (const float*)d_in[6];
    const float* bq_c    = (const float*)d_in[7];
    const float* Wkv     = (const float*)d_in[8];
    const float* bkv     = (const float*)d_in[9];
    const float* Wk_rope = (const float*)d_in[10];
    const float* bk_rope = (const float*)d_in[11];
    const float* Wk_c    = (const float*)d_in[12];
    const float* bk_c    = (const float*)d_in[13];
    const float* Wv      = (const float*)d_in[14];
    const float* bv      = (const float*)d_in[15];
    const float* Wo      = (const float*)d_in[16];
    const float* bo      = (const float*)d_in[17];
    float* out = (float*)d_out;

    float *qc, *qr, *kc, *kr, *bkr;
    cudaGetSymbolAddress((void**)&qc,  g_qc);
    cudaGetSymbolAddress((void**)&qr,  g_qr);
    cudaGetSymbolAddress((void**)&kc,  g_kc);
    cudaGetSymbolAddress((void**)&kr,  g_kr);
    cudaGetSymbolAddress((void**)&bkr, g_bkr);

    __nv_bfloat16 *h_hi, *h_lo, *cq_hi, *cq_lo, *ckv_hi, *ckv_lo, *ao_hi, *ao_lo;
    __nv_bfloat16 *Wqlr_hi, *Wqlr_lo, *Wqc_hi, *Wqc_lo, *Wqr_hi, *Wqr_lo;
    __nv_bfloat16 *Wkv_hi, *Wkv_lo, *Wkc_hi, *Wkc_lo, *Wv_hi, *Wv_lo, *Wo_hi, *Wo_lo;
    __nv_bfloat16 *Wkr_hi, *Wkr_lo, *qhi, *qlo, *khi, *klo, *vhi, *vlo;
    cudaGetSymbolAddress((void**)&h_hi,   g_h_hi);   cudaGetSymbolAddress((void**)&h_lo,   g_h_lo);
    cudaGetSymbolAddress((void**)&cq_hi,  g_cq_hi);  cudaGetSymbolAddress((void**)&cq_lo,  g_cq_lo);
    cudaGetSymbolAddress((void**)&ckv_hi, g_ckv_hi); cudaGetSymbolAddress((void**)&ckv_lo, g_ckv_lo);
    cudaGetSymbolAddress((void**)&ao_hi,  g_ao_hi);  cudaGetSymbolAddress((void**)&ao_lo,  g_ao_lo);
    cudaGetSymbolAddress((void**)&Wqlr_hi, g_Wqlr_hi); cudaGetSymbolAddress((void**)&Wqlr_lo, g_Wqlr_lo);
    cudaGetSymbolAddress((void**)&Wqc_hi,  g_Wqc_hi);  cudaGetSymbolAddress((void**)&Wqc_lo,  g_Wqc_lo);
    cudaGetSymbolAddress((void**)&Wqr_hi,  g_Wqr_hi);  cudaGetSymbolAddress((void**)&Wqr_lo,  g_Wqr_lo);
    cudaGetSymbolAddress((void**)&Wkv_hi,  g_Wkv_hi);  cudaGetSymbolAddress((void**)&Wkv_lo,  g_Wkv_lo);
    cudaGetSymbolAddress((void**)&Wkc_hi,  g_Wkc_hi);  cudaGetSymbolAddress((void**)&Wkc_lo,  g_Wkc_lo);
    cudaGetSymbolAddress((void**)&Wv_hi,   g_Wv_hi);   cudaGetSymbolAddress((void**)&Wv_lo,   g_Wv_lo);
    cudaGetSymbolAddress((void**)&Wo_hi,   g_Wo_hi);   cudaGetSymbolAddress((void**)&Wo_lo,   g_Wo_lo);
    cudaGetSymbolAddress((void**)&Wkr_hi,  g_Wkr_hi);  cudaGetSymbolAddress((void**)&Wkr_lo,  g_Wkr_lo);
    cudaGetSymbolAddress((void**)&qhi, g_qhi); cudaGetSymbolAddress((void**)&qlo, g_qlo);
    cudaGetSymbolAddress((void**)&khi, g_khi); cudaGetSymbolAddress((void**)&klo, g_klo);
    cudaGetSymbolAddress((void**)&vhi, g_vhi); cudaGetSymbolAddress((void**)&vlo, g_vlo);

    cudaFuncSetAttribute(mma_gemm6, cudaFuncAttributeMaxDynamicSharedMemorySize, G_SMEM);

    SJobs jobs;
    const float* srcs[8] = { hidden, Wq_lr, Wq_c, Wq_rope, Wkv, Wk_c, Wv, Wo };
    __nv_bfloat16* his[8] = { h_hi, Wqlr_hi, Wqc_hi, Wqr_hi, Wkv_hi, Wkc_hi, Wv_hi, Wo_hi };
    __nv_bfloat16* los[8] = { h_lo, Wqlr_lo, Wqc_lo, Wqr_lo, Wkv_lo, Wkc_lo, Wv_lo, Wo_lo };
    int ns[8] = { 2048*4096, 1536*4096, 4096*1536, 2048*1536,
                  512*4096, 4096*512, 4096*512, 4096*4096 };
    int blk = 0;
    for (int i = 0; i < 8; i++) {
        jobs.j[i].x = srcs[i]; jobs.j[i].hi = his[i]; jobs.j[i].lo = los[i];
        jobs.j[i].n8 = ns[i] / 8; jobs.j[i].blk0 = blk;
        blk += (jobs.j[i].n8 + 255) / 256;
    }
    multi_split_kernel<<<blk, 256>>>(jobs);
    pad_krope_kernel<<<(128 * 4096 + 255) / 256, 256>>>(Wk_rope, Wkr_hi, Wkr_lo, bk_rope, bkr);

    const int NONE = 0x7FFFFFFF;

    // G1: A = hidden (K=4096): c_q, c_kv, k_rope
    {
        GJobs g{};
        g.j[0] = { h_hi, h_lo, Wqlr_hi, Wqlr_lo, bq_lr, nullptr, cq_hi, cq_lo, 1536, 4096, 0, 0 };
        g.j[1] = { h_hi, h_lo, Wkv_hi,  Wkv_lo,  bkv,   nullptr, ckv_hi, ckv_lo, 512, 4096, 12, 0 };
        g.j[2] = { h_hi, h_lo, Wkr_hi,  Wkr_lo,  bkr,   kr, nullptr, nullptr, 128, 4096, 16, 0 };
        g.j[3] = g.j[2]; g.j[3].blk0 = NONE;
        mma_gemm6<<<dim3(17, 16), 128, G_SMEM>>>(g);
    }
    // G2+G3
    {
        GJobs g{};
        g.j[0] = { cq_hi, cq_lo, Wqc_hi, Wqc_lo, bq_c,    qc, nullptr, nullptr, 4096, 1536, 0,  0 };
        g.j[1] = { cq_hi, cq_lo, Wqr_hi, Wqr_lo, bq_rope, qr, nullptr, nullptr, 2048, 1536, 32, 0 };
        g.j[2] = { ckv_hi, ckv_lo, Wkc_hi, Wkc_lo, bk_c,  kc, nullptr, nullptr, 4096, 512, 48, 0 };
        g.j[3] = { ckv_hi, ckv_lo, Wv_hi,  Wv_lo,  bv, nullptr, vhi, vlo,       4096, 512, 80, 0 };
        mma_gemm6<<<dim3(112, 16), 128, G_SMEM>>>(g);
    }

    fuse_qk_kernel<<<16384, 256>>>(qc, qr, kc, kr, qhi, qlo, khi, klo);

    cudaFuncSetAttribute(attn_mma_kernel, cudaFuncAttributeMaxDynamicSharedMemorySize, ATT_SMEM);
    attn_mma_kernel<<<dim3(S_LEN / 64, NH), 128, ATT_SMEM>>>(
        qhi, qlo, khi, klo, vhi, vlo, mask, ao_hi, ao_lo);

    // G4: out = ao @ Wo^T
    {
        GJobs g{};
        g.j[0] = { ao_hi, ao_lo, Wo_hi, Wo_lo, bo, out, nullptr, nullptr, 4096, 4096, 0, 0 };
        g.j[1] = g.j[0]; g.j[1].blk0 = NONE;
        g.j[2] = g.j[0]; g.j[2].blk0 = NONE;
        g.j[3] = g.j[0]; g.j[3].blk0 = NONE;
        mma_gemm6<<<dim3(32, 16), 128, G_SMEM>>>(g);
    }
}